// round 2
// baseline (speedup 1.0000x reference)
#include <cuda_runtime.h>
#include <cuda_bf16.h>
#include <math.h>

// ---------------------------------------------------------------------------
// GDTEncoder: graph attention + PPR diffusion + FFN
// N=50000 nodes, DEG=16 edges/node (contiguous by dst), D_IN=D_OUT=256, H=8, HD=32
// ---------------------------------------------------------------------------

#define NN     50000
#define DEG    16
#define EDGES  (NN * DEG)
#define DIN    256
#define NH     8
#define HD     32
#define DOUT   256
#define DFF    1024
#define HOPS   5
#define ALPHA  0.15f
#define SLOPE  0.2f

// ---------------- scratch (static device globals; no allocation) -----------
__device__ float g_h[(size_t)NN * DIN];      // LN1 output
__device__ float g_feat0[(size_t)NN * DOUT]; // projected features (hop input 0)
__device__ float g_fa[(size_t)NN * DOUT];    // hop ping
__device__ float g_fb[(size_t)NN * DOUT];    // hop pong
__device__ float g_eh[(size_t)NN * NH];
__device__ float g_et[(size_t)NN * NH];
__device__ float g_a[(size_t)EDGES * NH];    // softmaxed edge weights
__device__ float g_rst[(size_t)NN * DOUT];   // feat after hops + h
__device__ float g_x[(size_t)NN * DOUT];     // LN2 output
__device__ float g_t[(size_t)NN * DFF];      // FFN hidden

// ---------------- LayerNorm over 256 channels, one block per row -----------
__global__ void ln256_kernel(const float* __restrict__ in,
                             const float* __restrict__ g,
                             const float* __restrict__ b,
                             float* __restrict__ out) {
    int n = blockIdx.x;
    int c = threadIdx.x;
    float v = in[(size_t)n * 256 + c];
    float s = v, sq = v * v;
    #pragma unroll
    for (int o = 16; o > 0; o >>= 1) {
        s  += __shfl_xor_sync(0xffffffffu, s, o);
        sq += __shfl_xor_sync(0xffffffffu, sq, o);
    }
    __shared__ float ws[8], wq[8];
    int w = c >> 5, l = c & 31;
    if (l == 0) { ws[w] = s; wq[w] = sq; }
    __syncthreads();
    s = 0.f; sq = 0.f;
    #pragma unroll
    for (int i = 0; i < 8; i++) { s += ws[i]; sq += wq[i]; }
    float mu  = s * (1.0f / 256.0f);
    float var = sq * (1.0f / 256.0f) - mu * mu;
    float rs  = rsqrtf(var + 1e-5f);
    out[(size_t)n * 256 + c] = (v - mu) * rs * g[c] + b[c];
}

// ---------------- SGEMM: C[M,N] = A[M,K] * B[N,K]^T, fp32 ------------------
// MODE 0: plain.  MODE 1: relu(C + bias).  MODE 2: C + bias + resid.
// Requires N % 128 == 0 and K % 16 == 0 (true for all calls here).
template <int MODE>
__global__ void __launch_bounds__(256)
sgemm_nt(const float* __restrict__ A, const float* __restrict__ B,
         const float* __restrict__ bias, const float* __restrict__ resid,
         float* __restrict__ C, int M, int N, int K) {
    constexpr int BM = 128, BN = 128, BK = 16;
    __shared__ float As[BK][BM];
    __shared__ float Bs[BK][BN];
    const int tid = threadIdx.x;
    const int n0 = blockIdx.x * BN;
    const int m0 = blockIdx.y * BM;
    const int tx = tid & 15;        // 0..15 -> N direction
    const int ty = tid >> 4;        // 0..15 -> M direction
    const int lr = tid >> 2;        // 0..63  load row
    const int lk = (tid & 3) * 4;   // 0,4,8,12 load k (float4)

    float acc[8][8];
    #pragma unroll
    for (int i = 0; i < 8; i++)
        #pragma unroll
        for (int j = 0; j < 8; j++) acc[i][j] = 0.f;

    for (int k0 = 0; k0 < K; k0 += BK) {
        #pragma unroll
        for (int i = 0; i < 2; i++) {
            int row = lr + i * 64;
            int gm  = m0 + row;
            float4 v = make_float4(0.f, 0.f, 0.f, 0.f);
            if (gm < M) v = *(const float4*)(A + (size_t)gm * K + k0 + lk);
            As[lk + 0][row] = v.x; As[lk + 1][row] = v.y;
            As[lk + 2][row] = v.z; As[lk + 3][row] = v.w;
        }
        #pragma unroll
        for (int i = 0; i < 2; i++) {
            int row = lr + i * 64;
            int gn  = n0 + row;
            float4 v = *(const float4*)(B + (size_t)gn * K + k0 + lk);
            Bs[lk + 0][row] = v.x; Bs[lk + 1][row] = v.y;
            Bs[lk + 2][row] = v.z; Bs[lk + 3][row] = v.w;
        }
        __syncthreads();
        #pragma unroll
        for (int k = 0; k < BK; k++) {
            float4 a0 = *(const float4*)&As[k][ty * 8];
            float4 a1 = *(const float4*)&As[k][ty * 8 + 4];
            float4 b0 = *(const float4*)&Bs[k][tx * 8];
            float4 b1 = *(const float4*)&Bs[k][tx * 8 + 4];
            float ra[8] = {a0.x, a0.y, a0.z, a0.w, a1.x, a1.y, a1.z, a1.w};
            float rb[8] = {b0.x, b0.y, b0.z, b0.w, b1.x, b1.y, b1.z, b1.w};
            #pragma unroll
            for (int i = 0; i < 8; i++)
                #pragma unroll
                for (int j = 0; j < 8; j++)
                    acc[i][j] += ra[i] * rb[j];
        }
        __syncthreads();
    }

    #pragma unroll
    for (int i = 0; i < 8; i++) {
        int gm = m0 + ty * 8 + i;
        if (gm >= M) continue;
        #pragma unroll
        for (int j = 0; j < 8; j++) {
            int gn = n0 + tx * 8 + j;
            float v = acc[i][j];
            if (MODE == 1) { v += bias[gn]; v = fmaxf(v, 0.f); }
            if (MODE == 2) { v += bias[gn] + resid[(size_t)gm * N + gn]; }
            C[(size_t)gm * N + gn] = v;
        }
    }
}

// ---------------- per-node head scores eh/et (one warp per node) -----------
__global__ void ehet_kernel(const float* __restrict__ attn_h,
                            const float* __restrict__ attn_t) {
    int warp = (blockIdx.x * blockDim.x + threadIdx.x) >> 5;
    int lane = threadIdx.x & 31;
    if (warp >= NN) return;
    const float* f = g_feat0 + (size_t)warp * DOUT;
    #pragma unroll
    for (int h = 0; h < NH; h++) {
        float v = f[h * HD + lane];
        float a = v * attn_h[h * HD + lane];
        float b = v * attn_t[h * HD + lane];
        #pragma unroll
        for (int o = 16; o > 0; o >>= 1) {
            a += __shfl_xor_sync(0xffffffffu, a, o);
            b += __shfl_xor_sync(0xffffffffu, b, o);
        }
        if (lane == 0) {
            g_eh[(size_t)warp * NH + h] = a;
            g_et[(size_t)warp * NH + h] = b;
        }
    }
}

// ---------------- edge scores + per-dst softmax (block of 128 per node) ----
__global__ void scores_kernel(const int* __restrict__ src) {
    int n = blockIdx.x;
    int t = threadIdx.x;       // 0..127 ; j = t/8 edge, h = t%8 head
    int j = t >> 3, h = t & 7;
    __shared__ int   ssrc[DEG];
    __shared__ float se[DEG][NH];
    __shared__ float sm[NH], ss[NH];
    if (t < DEG) ssrc[t] = src[(size_t)n * DEG + t];
    __syncthreads();
    int s = ssrc[j];
    float e = g_eh[(size_t)s * NH + h] + g_et[(size_t)n * NH + h];
    e = (e > 0.f) ? e : SLOPE * e;   // leaky relu
    se[j][h] = e;
    __syncthreads();
    if (t < NH) {
        float m = -1e30f;
        #pragma unroll
        for (int jj = 0; jj < DEG; jj++) m = fmaxf(m, se[jj][t]);
        float sum = 0.f;
        #pragma unroll
        for (int jj = 0; jj < DEG; jj++) sum += __expf(se[jj][t] - m);
        sm[t] = m; ss[t] = sum;
    }
    __syncthreads();
    g_a[(size_t)n * (DEG * NH) + t] = __expf(se[j][h] - sm[h]) / ss[h];
}

// ---------------- one PPR hop (block of 256 per node) ----------------------
// hop index selects ping-pong buffers; last hop fuses "+ h" residual -> g_rst
__global__ void hop_kernel(const int* __restrict__ src, int hop) {
    const float* fin;
    float* fout;
    if      (hop == 0) { fin = g_feat0; fout = g_fa; }
    else if (hop == 1) { fin = g_fa;    fout = g_fb; }
    else if (hop == 2) { fin = g_fb;    fout = g_fa; }
    else if (hop == 3) { fin = g_fa;    fout = g_fb; }
    else               { fin = g_fb;    fout = g_rst; }

    int n = blockIdx.x;
    int c = threadIdx.x;         // channel 0..255
    __shared__ float aw[DEG * NH];
    __shared__ int   ssrc[DEG];
    if (c < DEG * NH) aw[c] = g_a[(size_t)n * (DEG * NH) + c];
    if (c < DEG)      ssrc[c] = src[(size_t)n * DEG + c];
    __syncthreads();
    int h = c >> 5;
    float acc = 0.f;
    #pragma unroll
    for (int j = 0; j < DEG; j++)
        acc += aw[j * NH + h] * fin[(size_t)ssrc[j] * DOUT + c];
    float v = (1.0f - ALPHA) * acc + ALPHA * g_feat0[(size_t)n * DOUT + c];
    if (hop == HOPS - 1) v += g_h[(size_t)n * DOUT + c];   // residual with LN1 output
    fout[(size_t)n * DOUT + c] = v;
}

// ---------------------------------------------------------------------------
extern "C" void kernel_launch(void* const* d_in, const int* in_sizes, int n_in,
                              void* d_out, int out_size) {
    const float* ent_feat = (const float*)d_in[0];
    const float* W_ent    = (const float*)d_in[1];
    const float* attn_h   = (const float*)d_in[2];
    const float* attn_t   = (const float*)d_in[3];
    const float* ln1_g    = (const float*)d_in[4];
    const float* ln1_b    = (const float*)d_in[5];
    const float* ln2_g    = (const float*)d_in[6];
    const float* ln2_b    = (const float*)d_in[7];
    const float* W1       = (const float*)d_in[8];
    const float* b1       = (const float*)d_in[9];
    const float* W2       = (const float*)d_in[10];
    const float* b2       = (const float*)d_in[11];
    const int*   src      = (const int*)d_in[12];
    float*       out      = (float*)d_out;

    float* p_h     = nullptr;
    float* p_feat0 = nullptr;
    float* p_x     = nullptr;
    float* p_t     = nullptr;
    float* p_rst   = nullptr;
    cudaGetSymbolAddress((void**)&p_h,     g_h);
    cudaGetSymbolAddress((void**)&p_feat0, g_feat0);
    cudaGetSymbolAddress((void**)&p_x,     g_x);
    cudaGetSymbolAddress((void**)&p_t,     g_t);
    cudaGetSymbolAddress((void**)&p_rst,   g_rst);

    // 1. h = LN1(ent_feat)
    ln256_kernel<<<NN, 256>>>(ent_feat, ln1_g, ln1_b, p_h);

    // 2. feat0 = h @ W_ent^T
    {
        dim3 grid(DOUT / 128, (NN + 127) / 128);
        sgemm_nt<0><<<grid, 256>>>(p_h, W_ent, nullptr, nullptr, p_feat0,
                                   NN, DOUT, DIN);
    }

    // 3. per-node head scores
    ehet_kernel<<<(NN * 32 + 255) / 256, 256>>>(attn_h, attn_t);

    // 4. edge scores + softmax per destination node
    scores_kernel<<<NN, DEG * NH>>>(src);

    // 5-9. PPR hops (last one fuses residual into g_rst)
    for (int hop = 0; hop < HOPS; hop++)
        hop_kernel<<<NN, DOUT>>>(src, hop);

    // 10. x = LN2(rst)
    ln256_kernel<<<NN, 256>>>(p_rst, ln2_g, ln2_b, p_x);

    // 11. t = relu(x @ W1^T + b1)
    {
        dim3 grid(DFF / 128, (NN + 127) / 128);
        sgemm_nt<1><<<grid, 256>>>(p_x, W1, b1, nullptr, p_t, NN, DFF, DOUT);
    }

    // 12. out = t @ W2^T + b2 + rst
    {
        dim3 grid(DOUT / 128, (NN + 127) / 128);
        sgemm_nt<2><<<grid, 256>>>(p_t, W2, b2, p_rst, out, NN, DOUT, DFF);
    }
}

// round 3
// speedup vs baseline: 1.7107x; 1.7107x over previous
#include <cuda_runtime.h>
#include <cuda_bf16.h>
#include <math.h>
#include <stdint.h>

// ---------------------------------------------------------------------------
// GDTEncoder: graph attention + PPR diffusion + FFN
// N=50000 nodes, DEG=16 edges/node (contiguous by dst), D_IN=D_OUT=256, H=8, HD=32
// GEMMs via split-bf16 tensor-core mma (3-term: hi*hi + hi*lo + lo*hi)
// ---------------------------------------------------------------------------

#define NN     50000
#define DEG    16
#define EDGES  (NN * DEG)
#define DIN    256
#define NH     8
#define HD     32
#define DOUT   256
#define DFF    1024
#define HOPS   5
#define ALPHA  0.15f
#define SLOPE  0.2f

// ---------------- scratch (static device globals; no allocation) -----------
__device__ float g_h[(size_t)NN * DIN];      // LN1 output
__device__ float g_feat0[(size_t)NN * DOUT]; // projected features (hop input 0)
__device__ float g_fa[(size_t)NN * DOUT];    // hop ping
__device__ float g_fb[(size_t)NN * DOUT];    // hop pong
__device__ float g_eh[(size_t)NN * NH];
__device__ float g_et[(size_t)NN * NH];
__device__ float g_a[(size_t)EDGES * NH];    // softmaxed edge weights
__device__ float g_rst[(size_t)NN * DOUT];   // feat after hops + h
__device__ float g_x[(size_t)NN * DOUT];     // LN2 output
__device__ float g_t[(size_t)NN * DFF];      // FFN hidden

// ---------------- LayerNorm over 256 channels, one block per row -----------
__global__ void ln256_kernel(const float* __restrict__ in,
                             const float* __restrict__ g,
                             const float* __restrict__ b,
                             float* __restrict__ out) {
    int n = blockIdx.x;
    int c = threadIdx.x;
    float v = in[(size_t)n * 256 + c];
    float s = v, sq = v * v;
    #pragma unroll
    for (int o = 16; o > 0; o >>= 1) {
        s  += __shfl_xor_sync(0xffffffffu, s, o);
        sq += __shfl_xor_sync(0xffffffffu, sq, o);
    }
    __shared__ float ws[8], wq[8];
    int w = c >> 5, l = c & 31;
    if (l == 0) { ws[w] = s; wq[w] = sq; }
    __syncthreads();
    s = 0.f; sq = 0.f;
    #pragma unroll
    for (int i = 0; i < 8; i++) { s += ws[i]; sq += wq[i]; }
    float mu  = s * (1.0f / 256.0f);
    float var = sq * (1.0f / 256.0f) - mu * mu;
    float rs  = rsqrtf(var + 1e-5f);
    out[(size_t)n * 256 + c] = (v - mu) * rs * g[c] + b[c];
}

// ---------------- tensor-core GEMM helpers ---------------------------------
__device__ __forceinline__ void ldmat4(uint32_t& r0, uint32_t& r1,
                                       uint32_t& r2, uint32_t& r3,
                                       uint32_t addr) {
    asm volatile("ldmatrix.sync.aligned.m8n8.x4.shared.b16 {%0,%1,%2,%3}, [%4];"
                 : "=r"(r0), "=r"(r1), "=r"(r2), "=r"(r3) : "r"(addr));
}

__device__ __forceinline__ void mma_bf16(float c[4],
                                         uint32_t a0, uint32_t a1,
                                         uint32_t a2, uint32_t a3,
                                         uint32_t b0, uint32_t b1) {
    asm volatile(
        "mma.sync.aligned.m16n8k16.row.col.f32.bf16.bf16.f32 "
        "{%0,%1,%2,%3}, {%4,%5,%6,%7}, {%8,%9}, {%0,%1,%2,%3};"
        : "+f"(c[0]), "+f"(c[1]), "+f"(c[2]), "+f"(c[3])
        : "r"(a0), "r"(a1), "r"(a2), "r"(a3), "r"(b0), "r"(b1));
}

// split a float into bf16 hi + bf16 lo (residual)
__device__ __forceinline__ void split_bf16(float v, __nv_bfloat16& hi, __nv_bfloat16& lo) {
    hi = __float2bfloat16_rn(v);
    lo = __float2bfloat16_rn(v - __bfloat162float(hi));
}

// ---------------- GEMM: C[M,N] = A[M,K] * B[N,K]^T via split-bf16 mma ------
// MODE 0: plain.  MODE 1: relu(C + bias).  MODE 2: C + bias + resid.
// Requires N % 128 == 0 and K % 32 == 0 (true here).
template <int MODE>
__global__ void __launch_bounds__(256)
gemm_tc(const float* __restrict__ A, const float* __restrict__ B,
        const float* __restrict__ bias, const float* __restrict__ resid,
        float* __restrict__ C, int M, int N, int K) {
    constexpr int BM = 128, BN = 128, BK = 32;
    constexpr int LDS = 40;          // bf16 elems per smem row (80B -> conflict-free ldmatrix)
    __shared__ __align__(16) __nv_bfloat16 sAh[BM * LDS];
    __shared__ __align__(16) __nv_bfloat16 sAl[BM * LDS];
    __shared__ __align__(16) __nv_bfloat16 sBh[BN * LDS];
    __shared__ __align__(16) __nv_bfloat16 sBl[BN * LDS];

    const int tid  = threadIdx.x;
    const int m0   = blockIdx.y * BM;
    const int n0   = blockIdx.x * BN;
    const int wid  = tid >> 5;
    const int lane = tid & 31;
    const int wm   = (wid >> 2) * 64;   // warp m-offset (0 or 64)
    const int wn   = (wid & 3) * 32;    // warp n-offset (0..96)

    // loader mapping: thread -> (row, 4 consecutive float4 k-chunks)
    const int lrow = tid >> 1;          // 0..127
    const int lkc  = (tid & 1) * 4;     // chunk 0..3 or 4..7

    // ldmatrix lane addressing
    const int lg = lane >> 3;           // lane group 0..3
    const int lr = lane & 7;

    const uint32_t baseAh = (uint32_t)__cvta_generic_to_shared(sAh);
    const uint32_t baseAl = (uint32_t)__cvta_generic_to_shared(sAl);
    const uint32_t baseBh = (uint32_t)__cvta_generic_to_shared(sBh);
    const uint32_t baseBl = (uint32_t)__cvta_generic_to_shared(sBl);

    float acc[4][4][4];
    #pragma unroll
    for (int i = 0; i < 4; i++)
        #pragma unroll
        for (int j = 0; j < 4; j++)
            #pragma unroll
            for (int q = 0; q < 4; q++) acc[i][j][q] = 0.f;

    const bool arow_ok = (m0 + lrow) < M;
    const float* Arow = A + (size_t)(m0 + lrow) * K;
    const float* Brow = B + (size_t)(n0 + lrow) * K;

    for (int k0 = 0; k0 < K; k0 += BK) {
        // ---- load + convert fp32 -> bf16 hi/lo into smem ----
        #pragma unroll
        for (int i = 0; i < 4; i++) {
            int kc = lkc + i;                     // float4 chunk 0..7
            float4 va = make_float4(0.f, 0.f, 0.f, 0.f);
            if (arow_ok) va = *(const float4*)(Arow + k0 + kc * 4);
            float4 vb = *(const float4*)(Brow + k0 + kc * 4);
            __nv_bfloat16 h0, h1, h2, h3, l0, l1, l2, l3;
            split_bf16(va.x, h0, l0); split_bf16(va.y, h1, l1);
            split_bf16(va.z, h2, l2); split_bf16(va.w, h3, l3);
            int off = lrow * LDS + kc * 4;
            __nv_bfloat162* ph = (__nv_bfloat162*)&sAh[off];
            __nv_bfloat162* pl = (__nv_bfloat162*)&sAl[off];
            ph[0] = __nv_bfloat162(h0, h1); ph[1] = __nv_bfloat162(h2, h3);
            pl[0] = __nv_bfloat162(l0, l1); pl[1] = __nv_bfloat162(l2, l3);
            split_bf16(vb.x, h0, l0); split_bf16(vb.y, h1, l1);
            split_bf16(vb.z, h2, l2); split_bf16(vb.w, h3, l3);
            ph = (__nv_bfloat162*)&sBh[off];
            pl = (__nv_bfloat162*)&sBl[off];
            ph[0] = __nv_bfloat162(h0, h1); ph[1] = __nv_bfloat162(h2, h3);
            pl[0] = __nv_bfloat162(l0, l1); pl[1] = __nv_bfloat162(l2, l3);
        }
        __syncthreads();

        // ---- two k16 steps per BK=32 tile ----
        #pragma unroll
        for (int ks = 0; ks < 2; ks++) {
            const int kb = ks * 16;

            // B fragments: 4 n-tiles via 2 ldmatrix.x4 (hi and lo)
            uint32_t bh[4][2], bl[4][2];
            #pragma unroll
            for (int p = 0; p < 2; p++) {
                int row = wn + p * 16 + lr + (lg & 2) * 4;   // +8 for groups 2,3
                int kc  = kb + (lg & 1) * 8;
                uint32_t off = (uint32_t)(row * LDS + kc) * 2;
                ldmat4(bh[2*p][0], bh[2*p][1], bh[2*p+1][0], bh[2*p+1][1], baseBh + off);
                ldmat4(bl[2*p][0], bl[2*p][1], bl[2*p+1][0], bl[2*p+1][1], baseBl + off);
            }

            #pragma unroll
            for (int mi = 0; mi < 4; mi++) {
                int row = wm + mi * 16 + lr + (lg & 1) * 8;  // +8 for groups 1,3
                int kc  = kb + (lg & 2) * 4;                 // +8 for groups 2,3
                uint32_t off = (uint32_t)(row * LDS + kc) * 2;
                uint32_t ah0, ah1, ah2, ah3, al0, al1, al2, al3;
                ldmat4(ah0, ah1, ah2, ah3, baseAh + off);
                ldmat4(al0, al1, al2, al3, baseAl + off);
                #pragma unroll
                for (int nj = 0; nj < 4; nj++) {
                    mma_bf16(acc[mi][nj], ah0, ah1, ah2, ah3, bh[nj][0], bh[nj][1]);
                    mma_bf16(acc[mi][nj], ah0, ah1, ah2, ah3, bl[nj][0], bl[nj][1]);
                    mma_bf16(acc[mi][nj], al0, al1, al2, al3, bh[nj][0], bh[nj][1]);
                }
            }
        }
        __syncthreads();
    }

    // ---- epilogue ----
    const int gr  = lane >> 2;        // row within 8
    const int gc2 = (lane & 3) * 2;   // col pair
    #pragma unroll
    for (int mi = 0; mi < 4; mi++) {
        #pragma unroll
        for (int half = 0; half < 2; half++) {
            int gm = m0 + wm + mi * 16 + gr + half * 8;
            if (gm >= M) continue;
            #pragma unroll
            for (int nj = 0; nj < 4; nj++) {
                int gn = n0 + wn + nj * 8 + gc2;
                float v0 = acc[mi][nj][half * 2 + 0];
                float v1 = acc[mi][nj][half * 2 + 1];
                if (MODE == 1) {
                    v0 = fmaxf(v0 + bias[gn], 0.f);
                    v1 = fmaxf(v1 + bias[gn + 1], 0.f);
                } else if (MODE == 2) {
                    const float* rr = resid + (size_t)gm * N + gn;
                    v0 += bias[gn]     + rr[0];
                    v1 += bias[gn + 1] + rr[1];
                }
                *(float2*)(C + (size_t)gm * N + gn) = make_float2(v0, v1);
            }
        }
    }
}

// ---------------- per-node head scores eh/et (one warp per node) -----------
__global__ void ehet_kernel(const float* __restrict__ attn_h,
                            const float* __restrict__ attn_t) {
    int warp = (blockIdx.x * blockDim.x + threadIdx.x) >> 5;
    int lane = threadIdx.x & 31;
    if (warp >= NN) return;
    const float* f = g_feat0 + (size_t)warp * DOUT;
    #pragma unroll
    for (int h = 0; h < NH; h++) {
        float v = f[h * HD + lane];
        float a = v * attn_h[h * HD + lane];
        float b = v * attn_t[h * HD + lane];
        #pragma unroll
        for (int o = 16; o > 0; o >>= 1) {
            a += __shfl_xor_sync(0xffffffffu, a, o);
            b += __shfl_xor_sync(0xffffffffu, b, o);
        }
        if (lane == 0) {
            g_eh[(size_t)warp * NH + h] = a;
            g_et[(size_t)warp * NH + h] = b;
        }
    }
}

// ---------------- edge scores + per-dst softmax (block of 128 per node) ----
__global__ void scores_kernel(const int* __restrict__ src) {
    int n = blockIdx.x;
    int t = threadIdx.x;       // 0..127 ; j = t/8 edge, h = t%8 head
    int j = t >> 3, h = t & 7;
    __shared__ int   ssrc[DEG];
    __shared__ float se[DEG][NH];
    __shared__ float sm[NH], ss[NH];
    if (t < DEG) ssrc[t] = src[(size_t)n * DEG + t];
    __syncthreads();
    int s = ssrc[j];
    float e = g_eh[(size_t)s * NH + h] + g_et[(size_t)n * NH + h];
    e = (e > 0.f) ? e : SLOPE * e;   // leaky relu
    se[j][h] = e;
    __syncthreads();
    if (t < NH) {
        float m = -1e30f;
        #pragma unroll
        for (int jj = 0; jj < DEG; jj++) m = fmaxf(m, se[jj][t]);
        float sum = 0.f;
        #pragma unroll
        for (int jj = 0; jj < DEG; jj++) sum += __expf(se[jj][t] - m);
        sm[t] = m; ss[t] = sum;
    }
    __syncthreads();
    g_a[(size_t)n * (DEG * NH) + t] = __expf(se[j][h] - sm[h]) / ss[h];
}

// ---------------- one PPR hop (block of 256 per node) ----------------------
// hop index selects ping-pong buffers; last hop fuses "+ h" residual -> g_rst
__global__ void hop_kernel(const int* __restrict__ src, int hop) {
    const float* fin;
    float* fout;
    if      (hop == 0) { fin = g_feat0; fout = g_fa; }
    else if (hop == 1) { fin = g_fa;    fout = g_fb; }
    else if (hop == 2) { fin = g_fb;    fout = g_fa; }
    else if (hop == 3) { fin = g_fa;    fout = g_fb; }
    else               { fin = g_fb;    fout = g_rst; }

    int n = blockIdx.x;
    int c = threadIdx.x;         // channel 0..255
    __shared__ float aw[DEG * NH];
    __shared__ int   ssrc[DEG];
    if (c < DEG * NH) aw[c] = g_a[(size_t)n * (DEG * NH) + c];
    if (c < DEG)      ssrc[c] = src[(size_t)n * DEG + c];
    __syncthreads();
    int h = c >> 5;
    float acc = 0.f;
    #pragma unroll
    for (int j = 0; j < DEG; j++)
        acc += aw[j * NH + h] * fin[(size_t)ssrc[j] * DOUT + c];
    float v = (1.0f - ALPHA) * acc + ALPHA * g_feat0[(size_t)n * DOUT + c];
    if (hop == HOPS - 1) v += g_h[(size_t)n * DOUT + c];   // residual with LN1 output
    fout[(size_t)n * DOUT + c] = v;
}

// ---------------------------------------------------------------------------
extern "C" void kernel_launch(void* const* d_in, const int* in_sizes, int n_in,
                              void* d_out, int out_size) {
    const float* ent_feat = (const float*)d_in[0];
    const float* W_ent    = (const float*)d_in[1];
    const float* attn_h   = (const float*)d_in[2];
    const float* attn_t   = (const float*)d_in[3];
    const float* ln1_g    = (const float*)d_in[4];
    const float* ln1_b    = (const float*)d_in[5];
    const float* ln2_g    = (const float*)d_in[6];
    const float* ln2_b    = (const float*)d_in[7];
    const float* W1       = (const float*)d_in[8];
    const float* b1       = (const float*)d_in[9];
    const float* W2       = (const float*)d_in[10];
    const float* b2       = (const float*)d_in[11];
    const int*   src      = (const int*)d_in[12];
    float*       out      = (float*)d_out;

    float* p_h     = nullptr;
    float* p_feat0 = nullptr;
    float* p_x     = nullptr;
    float* p_t     = nullptr;
    float* p_rst   = nullptr;
    cudaGetSymbolAddress((void**)&p_h,     g_h);
    cudaGetSymbolAddress((void**)&p_feat0, g_feat0);
    cudaGetSymbolAddress((void**)&p_x,     g_x);
    cudaGetSymbolAddress((void**)&p_t,     g_t);
    cudaGetSymbolAddress((void**)&p_rst,   g_rst);

    // 1. h = LN1(ent_feat)
    ln256_kernel<<<NN, 256>>>(ent_feat, ln1_g, ln1_b, p_h);

    // 2. feat0 = h @ W_ent^T    (tensor cores, split-bf16)
    {
        dim3 grid(DOUT / 128, (NN + 127) / 128);
        gemm_tc<0><<<grid, 256>>>(p_h, W_ent, nullptr, nullptr, p_feat0,
                                  NN, DOUT, DIN);
    }

    // 3. per-node head scores
    ehet_kernel<<<(NN * 32 + 255) / 256, 256>>>(attn_h, attn_t);

    // 4. edge scores + softmax per destination node
    scores_kernel<<<NN, DEG * NH>>>(src);

    // 5-9. PPR hops (last one fuses residual into g_rst)
    for (int hop = 0; hop < HOPS; hop++)
        hop_kernel<<<NN, DOUT>>>(src, hop);

    // 10. x = LN2(rst)
    ln256_kernel<<<NN, 256>>>(p_rst, ln2_g, ln2_b, p_x);

    // 11. t = relu(x @ W1^T + b1)
    {
        dim3 grid(DFF / 128, (NN + 127) / 128);
        gemm_tc<1><<<grid, 256>>>(p_x, W1, b1, nullptr, p_t, NN, DFF, DOUT);
    }

    // 12. out = t @ W2^T + b2 + rst
    {
        dim3 grid(DOUT / 128, (NN + 127) / 128);
        gemm_tc<2><<<grid, 256>>>(p_t, W2, b2, p_rst, out, NN, DOUT, DFF);
    }
}

// round 4
// speedup vs baseline: 1.7400x; 1.0171x over previous
#include <cuda_runtime.h>
#include <cuda_bf16.h>
#include <math.h>
#include <stdint.h>

// ---------------------------------------------------------------------------
// GDTEncoder: graph attention + PPR diffusion + FFN
// N=50000, DEG=16 (dst-contiguous), D_IN=D_OUT=256, H=8, HD=32, DFF=1024
// GEMMs: split-bf16 (3-term) tensor-core mma, pre-converted operands,
//        cp.async double-buffered pipeline.
// ---------------------------------------------------------------------------

#define NN     50000
#define DEG    16
#define EDGES  (NN * DEG)
#define DIN    256
#define NH     8
#define HD     32
#define DOUT   256
#define DFF    1024
#define HOPS   5
#define ALPHA  0.15f
#define SLOPE  0.2f

// ---------------- scratch (static device globals; no allocation) -----------
__device__ float g_h[(size_t)NN * DIN];      // LN1 output (fp32, for residual)
__device__ float g_feat0[(size_t)NN * DOUT]; // projected features (hop input 0)
__device__ float g_fa[(size_t)NN * DOUT];    // hop ping
__device__ float g_fb[(size_t)NN * DOUT];    // hop pong
__device__ float g_eh[(size_t)NN * NH];
__device__ float g_et[(size_t)NN * NH];
__device__ float g_a[(size_t)EDGES * NH];    // softmaxed edge weights
__device__ float g_rst[(size_t)NN * DOUT];   // feat after hops + h

// bf16 hi/lo operand buffers
__device__ __nv_bfloat16 g_hh[(size_t)NN * DIN],  g_hl[(size_t)NN * DIN];
__device__ __nv_bfloat16 g_xh[(size_t)NN * DOUT], g_xl[(size_t)NN * DOUT];
__device__ __nv_bfloat16 g_th[(size_t)NN * DFF],  g_tl[(size_t)NN * DFF];
__device__ __nv_bfloat16 g_wenth[DOUT * DIN],  g_wentl[DOUT * DIN];
__device__ __nv_bfloat16 g_w1h[DFF * DOUT],    g_w1l[DFF * DOUT];
__device__ __nv_bfloat16 g_w2h[DOUT * DFF],    g_w2l[DOUT * DFF];

// ---------------- helpers --------------------------------------------------
__device__ __forceinline__ void split_bf16(float v, __nv_bfloat16& hi, __nv_bfloat16& lo) {
    hi = __float2bfloat16_rn(v);
    lo = __float2bfloat16_rn(v - __bfloat162float(hi));
}

__device__ __forceinline__ void ldmat4(uint32_t& r0, uint32_t& r1,
                                       uint32_t& r2, uint32_t& r3,
                                       uint32_t addr) {
    asm volatile("ldmatrix.sync.aligned.m8n8.x4.shared.b16 {%0,%1,%2,%3}, [%4];"
                 : "=r"(r0), "=r"(r1), "=r"(r2), "=r"(r3) : "r"(addr));
}

__device__ __forceinline__ void mma_bf16(float c[4],
                                         uint32_t a0, uint32_t a1,
                                         uint32_t a2, uint32_t a3,
                                         uint32_t b0, uint32_t b1) {
    asm volatile(
        "mma.sync.aligned.m16n8k16.row.col.f32.bf16.bf16.f32 "
        "{%0,%1,%2,%3}, {%4,%5,%6,%7}, {%8,%9}, {%0,%1,%2,%3};"
        : "+f"(c[0]), "+f"(c[1]), "+f"(c[2]), "+f"(c[3])
        : "r"(a0), "r"(a1), "r"(a2), "r"(a3), "r"(b0), "r"(b1));
}

__device__ __forceinline__ void cp16(uint32_t dst, const void* src, int sz) {
    asm volatile("cp.async.cg.shared.global [%0], [%1], 16, %2;\n"
                 :: "r"(dst), "l"(src), "r"(sz));
}
__device__ __forceinline__ void cp_commit() {
    asm volatile("cp.async.commit_group;\n" ::);
}
__device__ __forceinline__ void cp_wait1() {
    asm volatile("cp.async.wait_group 1;\n" ::);
}

// ---------------- LayerNorm over 256 channels ------------------------------
// Writes bf16 hi/lo always; fp32 copy optionally.
template <bool WRITE_F32>
__global__ void ln256_kernel(const float* __restrict__ in,
                             const float* __restrict__ g,
                             const float* __restrict__ b,
                             float* __restrict__ out_f32,
                             __nv_bfloat16* __restrict__ out_h,
                             __nv_bfloat16* __restrict__ out_l) {
    int n = blockIdx.x;
    int c = threadIdx.x;
    float v = in[(size_t)n * 256 + c];
    float s = v, sq = v * v;
    #pragma unroll
    for (int o = 16; o > 0; o >>= 1) {
        s  += __shfl_xor_sync(0xffffffffu, s, o);
        sq += __shfl_xor_sync(0xffffffffu, sq, o);
    }
    __shared__ float ws[8], wq[8];
    int w = c >> 5, l = c & 31;
    if (l == 0) { ws[w] = s; wq[w] = sq; }
    __syncthreads();
    s = 0.f; sq = 0.f;
    #pragma unroll
    for (int i = 0; i < 8; i++) { s += ws[i]; sq += wq[i]; }
    float mu  = s * (1.0f / 256.0f);
    float var = sq * (1.0f / 256.0f) - mu * mu;
    float rs  = rsqrtf(var + 1e-5f);
    float y = (v - mu) * rs * g[c] + b[c];
    if (WRITE_F32) out_f32[(size_t)n * 256 + c] = y;
    __nv_bfloat16 hi, lo;
    split_bf16(y, hi, lo);
    out_h[(size_t)n * 256 + c] = hi;
    out_l[(size_t)n * 256 + c] = lo;
}

// ---------------- weight fp32 -> bf16 hi/lo --------------------------------
__global__ void wconv_kernel(const float* __restrict__ w, int n,
                             __nv_bfloat16* __restrict__ wh,
                             __nv_bfloat16* __restrict__ wl) {
    int i = blockIdx.x * blockDim.x + threadIdx.x;
    if (i >= n) return;
    __nv_bfloat16 hi, lo;
    split_bf16(w[i], hi, lo);
    wh[i] = hi; wl[i] = lo;
}

// ---------------- GEMM: C[M,N] = A[M,K] * B[N,K]^T, split-bf16, pipelined --
// MODE 0: fp32 C.  MODE 1: relu(C+bias) -> bf16 hi/lo (Ch, Cl).
// MODE 2: fp32 C = acc + bias + resid.
// N % 128 == 0, K % 32 == 0.
template <int MODE>
__global__ void __launch_bounds__(256)
gemm_tc(const __nv_bfloat16* __restrict__ Ah, const __nv_bfloat16* __restrict__ Al,
        const __nv_bfloat16* __restrict__ Bh, const __nv_bfloat16* __restrict__ Bl,
        const float* __restrict__ bias, const float* __restrict__ resid,
        float* __restrict__ C,
        __nv_bfloat16* __restrict__ Ch, __nv_bfloat16* __restrict__ Cl,
        int M, int N, int K) {
    constexpr int BM = 128, BN = 128, BK = 32;
    constexpr int LDS = 40;                 // bf16/row -> 80B rows, 16B aligned
    constexpr int MAT = BM * LDS * 2;       // 10240 B per matrix
    constexpr int STAGE = 4 * MAT;          // 40960 B per stage

    extern __shared__ __align__(16) char dynsmem[];
    const uint32_t smem0 = (uint32_t)__cvta_generic_to_shared(dynsmem);

    const int tid  = threadIdx.x;
    const int m0   = blockIdx.y * BM;
    const int n0   = blockIdx.x * BN;
    const int wid  = tid >> 5;
    const int lane = tid & 31;
    const int wm   = (wid >> 2) * 64;
    const int wn   = (wid & 3) * 32;
    const int lg   = lane >> 3;
    const int lr   = lane & 7;

    // loader mapping: row = tid>>1 (0..127), chunk pair c0 = (tid&1)*2
    const int lrow = tid >> 1;
    const int lc0  = (tid & 1) * 2;
    const bool arow_ok = (m0 + lrow) < M;
    const int  a_sz = arow_ok ? 16 : 0;
    const __nv_bfloat16* pAh = Ah + (size_t)(m0 + lrow) * K + lc0 * 8;
    const __nv_bfloat16* pAl = Al + (size_t)(m0 + lrow) * K + lc0 * 8;
    const __nv_bfloat16* pBh = Bh + (size_t)(n0 + lrow) * K + lc0 * 8;
    const __nv_bfloat16* pBl = Bl + (size_t)(n0 + lrow) * K + lc0 * 8;
    const uint32_t soff = (uint32_t)(lrow * 80 + lc0 * 16);

    const int KT = K / BK;

    auto load_stage = [&](int kt, int s) {
        uint32_t sb = smem0 + s * STAGE + soff;
        int ko = kt * BK;
        cp16(sb + 0 * MAT,      pAh + ko,     a_sz);
        cp16(sb + 0 * MAT + 16, pAh + ko + 8, a_sz);
        cp16(sb + 1 * MAT,      pAl + ko,     a_sz);
        cp16(sb + 1 * MAT + 16, pAl + ko + 8, a_sz);
        cp16(sb + 2 * MAT,      pBh + ko,     16);
        cp16(sb + 2 * MAT + 16, pBh + ko + 8, 16);
        cp16(sb + 3 * MAT,      pBl + ko,     16);
        cp16(sb + 3 * MAT + 16, pBl + ko + 8, 16);
    };

    float acc[4][4][4];
    #pragma unroll
    for (int i = 0; i < 4; i++)
        #pragma unroll
        for (int j = 0; j < 4; j++)
            #pragma unroll
            for (int q = 0; q < 4; q++) acc[i][j][q] = 0.f;

    load_stage(0, 0);
    cp_commit();

    for (int kt = 0; kt < KT; kt++) {
        if (kt + 1 < KT) load_stage(kt + 1, (kt + 1) & 1);
        cp_commit();
        cp_wait1();
        __syncthreads();

        const uint32_t baseAh = smem0 + (kt & 1) * STAGE + 0 * MAT;
        const uint32_t baseAl = baseAh + MAT;
        const uint32_t baseBh = baseAh + 2 * MAT;
        const uint32_t baseBl = baseAh + 3 * MAT;

        #pragma unroll
        for (int ks = 0; ks < 2; ks++) {
            const int kb = ks * 16;
            uint32_t bh[4][2], bl[4][2];
            #pragma unroll
            for (int p = 0; p < 2; p++) {
                int row = wn + p * 16 + lr + (lg & 2) * 4;
                int kc  = kb + (lg & 1) * 8;
                uint32_t off = (uint32_t)(row * LDS + kc) * 2;
                ldmat4(bh[2*p][0], bh[2*p][1], bh[2*p+1][0], bh[2*p+1][1], baseBh + off);
                ldmat4(bl[2*p][0], bl[2*p][1], bl[2*p+1][0], bl[2*p+1][1], baseBl + off);
            }
            #pragma unroll
            for (int mi = 0; mi < 4; mi++) {
                int row = wm + mi * 16 + lr + (lg & 1) * 8;
                int kc  = kb + (lg & 2) * 4;
                uint32_t off = (uint32_t)(row * LDS + kc) * 2;
                uint32_t ah0, ah1, ah2, ah3, al0, al1, al2, al3;
                ldmat4(ah0, ah1, ah2, ah3, baseAh + off);
                ldmat4(al0, al1, al2, al3, baseAl + off);
                #pragma unroll
                for (int nj = 0; nj < 4; nj++) {
                    mma_bf16(acc[mi][nj], ah0, ah1, ah2, ah3, bh[nj][0], bh[nj][1]);
                    mma_bf16(acc[mi][nj], ah0, ah1, ah2, ah3, bl[nj][0], bl[nj][1]);
                    mma_bf16(acc[mi][nj], al0, al1, al2, al3, bh[nj][0], bh[nj][1]);
                }
            }
        }
        __syncthreads();
    }

    // ---- epilogue ----
    const int gr  = lane >> 2;
    const int gc2 = (lane & 3) * 2;
    #pragma unroll
    for (int mi = 0; mi < 4; mi++) {
        #pragma unroll
        for (int half = 0; half < 2; half++) {
            int gm = m0 + wm + mi * 16 + gr + half * 8;
            if (gm >= M) continue;
            #pragma unroll
            for (int nj = 0; nj < 4; nj++) {
                int gn = n0 + wn + nj * 8 + gc2;
                float v0 = acc[mi][nj][half * 2 + 0];
                float v1 = acc[mi][nj][half * 2 + 1];
                if (MODE == 1) {
                    v0 = fmaxf(v0 + bias[gn], 0.f);
                    v1 = fmaxf(v1 + bias[gn + 1], 0.f);
                    __nv_bfloat16 h0, l0, h1, l1;
                    split_bf16(v0, h0, l0);
                    split_bf16(v1, h1, l1);
                    *(__nv_bfloat162*)(Ch + (size_t)gm * N + gn) = __nv_bfloat162(h0, h1);
                    *(__nv_bfloat162*)(Cl + (size_t)gm * N + gn) = __nv_bfloat162(l0, l1);
                } else {
                    if (MODE == 2) {
                        const float* rr = resid + (size_t)gm * N + gn;
                        v0 += bias[gn]     + rr[0];
                        v1 += bias[gn + 1] + rr[1];
                    }
                    *(float2*)(C + (size_t)gm * N + gn) = make_float2(v0, v1);
                }
            }
        }
    }
}

// ---------------- per-node head scores eh/et (one warp per node) -----------
__global__ void ehet_kernel(const float* __restrict__ attn_h,
                            const float* __restrict__ attn_t) {
    int warp = (blockIdx.x * blockDim.x + threadIdx.x) >> 5;
    int lane = threadIdx.x & 31;
    if (warp >= NN) return;
    const float* f = g_feat0 + (size_t)warp * DOUT;
    #pragma unroll
    for (int h = 0; h < NH; h++) {
        float v = f[h * HD + lane];
        float a = v * attn_h[h * HD + lane];
        float b = v * attn_t[h * HD + lane];
        #pragma unroll
        for (int o = 16; o > 0; o >>= 1) {
            a += __shfl_xor_sync(0xffffffffu, a, o);
            b += __shfl_xor_sync(0xffffffffu, b, o);
        }
        if (lane == 0) {
            g_eh[(size_t)warp * NH + h] = a;
            g_et[(size_t)warp * NH + h] = b;
        }
    }
}

// ---------------- edge scores + per-dst softmax ----------------------------
__global__ void scores_kernel(const int* __restrict__ src) {
    int n = blockIdx.x;
    int t = threadIdx.x;
    int j = t >> 3, h = t & 7;
    __shared__ int   ssrc[DEG];
    __shared__ float se[DEG][NH];
    __shared__ float sm[NH], ss[NH];
    if (t < DEG) ssrc[t] = src[(size_t)n * DEG + t];
    __syncthreads();
    int s = ssrc[j];
    float e = g_eh[(size_t)s * NH + h] + g_et[(size_t)n * NH + h];
    e = (e > 0.f) ? e : SLOPE * e;
    se[j][h] = e;
    __syncthreads();
    if (t < NH) {
        float m = -1e30f;
        #pragma unroll
        for (int jj = 0; jj < DEG; jj++) m = fmaxf(m, se[jj][t]);
        float sum = 0.f;
        #pragma unroll
        for (int jj = 0; jj < DEG; jj++) sum += __expf(se[jj][t] - m);
        sm[t] = m; ss[t] = sum;
    }
    __syncthreads();
    g_a[(size_t)n * (DEG * NH) + t] = __expf(se[j][h] - sm[h]) / ss[h];
}

// ---------------- one PPR hop ----------------------------------------------
__global__ void hop_kernel(const int* __restrict__ src, int hop) {
    const float* fin;
    float* fout;
    if      (hop == 0) { fin = g_feat0; fout = g_fa; }
    else if (hop == 1) { fin = g_fa;    fout = g_fb; }
    else if (hop == 2) { fin = g_fb;    fout = g_fa; }
    else if (hop == 3) { fin = g_fa;    fout = g_fb; }
    else               { fin = g_fb;    fout = g_rst; }

    int n = blockIdx.x;
    int c = threadIdx.x;
    __shared__ float aw[DEG * NH];
    __shared__ int   ssrc[DEG];
    if (c < DEG * NH) aw[c] = g_a[(size_t)n * (DEG * NH) + c];
    if (c < DEG)      ssrc[c] = src[(size_t)n * DEG + c];
    __syncthreads();
    int h = c >> 5;
    float acc = 0.f;
    #pragma unroll
    for (int j = 0; j < DEG; j++)
        acc += aw[j * NH + h] * fin[(size_t)ssrc[j] * DOUT + c];
    float v = (1.0f - ALPHA) * acc + ALPHA * g_feat0[(size_t)n * DOUT + c];
    if (hop == HOPS - 1) v += g_h[(size_t)n * DOUT + c];
    fout[(size_t)n * DOUT + c] = v;
}

// ---------------------------------------------------------------------------
extern "C" void kernel_launch(void* const* d_in, const int* in_sizes, int n_in,
                              void* d_out, int out_size) {
    const float* ent_feat = (const float*)d_in[0];
    const float* W_ent    = (const float*)d_in[1];
    const float* attn_h   = (const float*)d_in[2];
    const float* attn_t   = (const float*)d_in[3];
    const float* ln1_g    = (const float*)d_in[4];
    const float* ln1_b    = (const float*)d_in[5];
    const float* ln2_g    = (const float*)d_in[6];
    const float* ln2_b    = (const float*)d_in[7];
    const float* W1       = (const float*)d_in[8];
    const float* b1       = (const float*)d_in[9];
    const float* W2       = (const float*)d_in[10];
    const float* b2       = (const float*)d_in[11];
    const int*   src      = (const int*)d_in[12];
    float*       out      = (float*)d_out;

    const int SMEM_BYTES = 2 * 4 * 128 * 40 * 2;   // 81920
    cudaFuncSetAttribute(gemm_tc<0>, cudaFuncAttributeMaxDynamicSharedMemorySize, SMEM_BYTES);
    cudaFuncSetAttribute(gemm_tc<1>, cudaFuncAttributeMaxDynamicSharedMemorySize, SMEM_BYTES);
    cudaFuncSetAttribute(gemm_tc<2>, cudaFuncAttributeMaxDynamicSharedMemorySize, SMEM_BYTES);

    float *p_h, *p_feat0, *p_rst;
    __nv_bfloat16 *p_hh, *p_hl, *p_xh, *p_xl, *p_th, *p_tl;
    __nv_bfloat16 *p_wenth, *p_wentl, *p_w1h, *p_w1l, *p_w2h, *p_w2l;
    cudaGetSymbolAddress((void**)&p_h,     g_h);
    cudaGetSymbolAddress((void**)&p_feat0, g_feat0);
    cudaGetSymbolAddress((void**)&p_rst,   g_rst);
    cudaGetSymbolAddress((void**)&p_hh,    g_hh);
    cudaGetSymbolAddress((void**)&p_hl,    g_hl);
    cudaGetSymbolAddress((void**)&p_xh,    g_xh);
    cudaGetSymbolAddress((void**)&p_xl,    g_xl);
    cudaGetSymbolAddress((void**)&p_th,    g_th);
    cudaGetSymbolAddress((void**)&p_tl,    g_tl);
    cudaGetSymbolAddress((void**)&p_wenth, g_wenth);
    cudaGetSymbolAddress((void**)&p_wentl, g_wentl);
    cudaGetSymbolAddress((void**)&p_w1h,   g_w1h);
    cudaGetSymbolAddress((void**)&p_w1l,   g_w1l);
    cudaGetSymbolAddress((void**)&p_w2h,   g_w2h);
    cudaGetSymbolAddress((void**)&p_w2l,   g_w2l);

    // 0. weights -> bf16 hi/lo
    wconv_kernel<<<(DOUT * DIN + 255) / 256, 256>>>(W_ent, DOUT * DIN, p_wenth, p_wentl);
    wconv_kernel<<<(DFF * DOUT + 255) / 256, 256>>>(W1, DFF * DOUT, p_w1h, p_w1l);
    wconv_kernel<<<(DOUT * DFF + 255) / 256, 256>>>(W2, DOUT * DFF, p_w2h, p_w2l);

    // 1. h = LN1(ent_feat)  (fp32 + bf16 hi/lo)
    ln256_kernel<true><<<NN, 256>>>(ent_feat, ln1_g, ln1_b, p_h, p_hh, p_hl);

    // 2. feat0 = h @ W_ent^T
    {
        dim3 grid(DOUT / 128, (NN + 127) / 128);
        gemm_tc<0><<<grid, 256, SMEM_BYTES>>>(p_hh, p_hl, p_wenth, p_wentl,
                                              nullptr, nullptr, p_feat0,
                                              nullptr, nullptr, NN, DOUT, DIN);
    }

    // 3. per-node head scores
    ehet_kernel<<<(NN * 32 + 255) / 256, 256>>>(attn_h, attn_t);

    // 4. edge scores + softmax
    scores_kernel<<<NN, DEG * NH>>>(src);

    // 5-9. PPR hops
    for (int hop = 0; hop < HOPS; hop++)
        hop_kernel<<<NN, DOUT>>>(src, hop);

    // 10. x = LN2(rst) -> bf16 hi/lo only
    ln256_kernel<false><<<NN, 256>>>(p_rst, ln2_g, ln2_b, nullptr, p_xh, p_xl);

    // 11. t = relu(x @ W1^T + b1) -> bf16 hi/lo directly
    {
        dim3 grid(DFF / 128, (NN + 127) / 128);
        gemm_tc<1><<<grid, 256, SMEM_BYTES>>>(p_xh, p_xl, p_w1h, p_w1l,
                                              b1, nullptr, nullptr,
                                              p_th, p_tl, NN, DFF, DOUT);
    }

    // 12. out = t @ W2^T + b2 + rst
    {
        dim3 grid(DOUT / 128, (NN + 127) / 128);
        gemm_tc<2><<<grid, 256, SMEM_BYTES>>>(p_th, p_tl, p_w2h, p_w2l,
                                              b2, p_rst, out,
                                              nullptr, nullptr, NN, DOUT, DFF);
    }
}

// round 6
// speedup vs baseline: 2.4199x; 1.3907x over previous
#include <cuda_runtime.h>
#include <cuda_bf16.h>
#include <cuda_fp16.h>
#include <math.h>
#include <stdint.h>

// ---------------------------------------------------------------------------
// GDTEncoder: graph attention + PPR diffusion + FFN
// N=50000, DEG=16 (dst-contiguous), D_IN=D_OUT=256, H=8, HD=32, DFF=1024
// G1 (proj): split-bf16 3-term mma.sync.  G2/G3 (FFN): single-pass fp16 mma.
// ---------------------------------------------------------------------------

#define NN     50000
#define DEG    16
#define EDGES  (NN * DEG)
#define DIN    256
#define NH     8
#define HD     32
#define DOUT   256
#define DFF    1024
#define HOPS   5
#define ALPHA  0.15f
#define SLOPE  0.2f

// ---------------- scratch (static device globals; no allocation) -----------
__device__ __align__(256) float g_h[(size_t)NN * DIN];      // LN1 out (fp32)
__device__ __align__(256) float g_feat0[(size_t)NN * DOUT];
__device__ __align__(256) float g_fa[(size_t)NN * DOUT];
__device__ __align__(256) float g_fb[(size_t)NN * DOUT];
__device__ __align__(256) float g_eh[(size_t)NN * NH];
__device__ __align__(256) float g_et[(size_t)NN * NH];
__device__ __align__(256) float g_a[(size_t)EDGES * NH];
__device__ __align__(256) float g_rst[(size_t)NN * DOUT];

// bf16 hi/lo for G1 operands
__device__ __align__(256) __nv_bfloat16 g_hh[(size_t)NN * DIN], g_hl[(size_t)NN * DIN];
__device__ __align__(256) __nv_bfloat16 g_wenth[DOUT * DIN], g_wentl[DOUT * DIN];
// fp16 for G2/G3 operands
__device__ __align__(256) __half g_x16[(size_t)NN * DOUT];
__device__ __align__(256) __half g_t16[(size_t)NN * DFF];
__device__ __align__(256) __half g_w116[DFF * DOUT];
__device__ __align__(256) __half g_w216[DOUT * DFF];

// ---------------- helpers --------------------------------------------------
__device__ __forceinline__ void split_bf16(float v, __nv_bfloat16& hi, __nv_bfloat16& lo) {
    hi = __float2bfloat16_rn(v);
    lo = __float2bfloat16_rn(v - __bfloat162float(hi));
}

__device__ __forceinline__ void ldmat4(uint32_t& r0, uint32_t& r1,
                                       uint32_t& r2, uint32_t& r3,
                                       uint32_t addr) {
    asm volatile("ldmatrix.sync.aligned.m8n8.x4.shared.b16 {%0,%1,%2,%3}, [%4];"
                 : "=r"(r0), "=r"(r1), "=r"(r2), "=r"(r3) : "r"(addr));
}

__device__ __forceinline__ void mma_bf(float c[4],
                                       uint32_t a0, uint32_t a1, uint32_t a2, uint32_t a3,
                                       uint32_t b0, uint32_t b1) {
    asm volatile(
        "mma.sync.aligned.m16n8k16.row.col.f32.bf16.bf16.f32 "
        "{%0,%1,%2,%3}, {%4,%5,%6,%7}, {%8,%9}, {%0,%1,%2,%3};"
        : "+f"(c[0]), "+f"(c[1]), "+f"(c[2]), "+f"(c[3])
        : "r"(a0), "r"(a1), "r"(a2), "r"(a3), "r"(b0), "r"(b1));
}

__device__ __forceinline__ void mma_fp(float c[4],
                                       uint32_t a0, uint32_t a1, uint32_t a2, uint32_t a3,
                                       uint32_t b0, uint32_t b1) {
    asm volatile(
        "mma.sync.aligned.m16n8k16.row.col.f32.f16.f16.f32 "
        "{%0,%1,%2,%3}, {%4,%5,%6,%7}, {%8,%9}, {%0,%1,%2,%3};"
        : "+f"(c[0]), "+f"(c[1]), "+f"(c[2]), "+f"(c[3])
        : "r"(a0), "r"(a1), "r"(a2), "r"(a3), "r"(b0), "r"(b1));
}

__device__ __forceinline__ void cp16(uint32_t dst, const void* src, int sz) {
    asm volatile("cp.async.cg.shared.global [%0], [%1], 16, %2;\n"
                 :: "r"(dst), "l"(src), "r"(sz));
}
__device__ __forceinline__ void cp_commit() {
    asm volatile("cp.async.commit_group;\n" ::);
}
__device__ __forceinline__ void cp_wait1() {
    asm volatile("cp.async.wait_group 1;\n" ::);
}
__device__ __forceinline__ void cp_wait0() {
    asm volatile("cp.async.wait_group 0;\n" ::);
}

// ---------------- GEMM: C[M,N] = A[M,K] * B[N,K]^T -------------------------
// TERMS=3: split-bf16 3-term (Ah,Al,Bh,Bl).  TERMS=1: single fp16 (Ah,Bh).
// MODE 0: fp32 C.   MODE 1: relu(acc+bias) -> fp16 Ch.   MODE 2: acc+bias+resid -> fp32 C.
// N % 128 == 0, K % 32 == 0.  Operand storage is uint16_t (bf16 or fp16 bits).
template <int MODE, int TERMS, int ISH>
__global__ void __launch_bounds__(256)
gemm_mma(const uint16_t* __restrict__ Ah, const uint16_t* __restrict__ Al,
         const uint16_t* __restrict__ Bh, const uint16_t* __restrict__ Bl,
         const float* __restrict__ bias, const float* __restrict__ resid,
         float* __restrict__ C, __half* __restrict__ Ch,
         int M, int N, int K) {
    constexpr int BM = 128, BN = 128, BK = 32;
    constexpr int LDS = 40;                 // elems/row -> 80B, conflict-free ldmatrix
    constexpr int MAT = BM * LDS * 2;       // 10240 B per matrix
    constexpr int NMAT = (TERMS == 3) ? 4 : 2;
    constexpr int STAGE = NMAT * MAT;
    constexpr int OFF_B = (TERMS == 3) ? 2 * MAT : MAT;

    extern __shared__ __align__(16) char dynsmem[];
    const uint32_t smem0 = (uint32_t)__cvta_generic_to_shared(dynsmem);

    const int tid  = threadIdx.x;
    const int m0   = blockIdx.y * BM;
    const int n0   = blockIdx.x * BN;
    const int wid  = tid >> 5;
    const int lane = tid & 31;
    const int wm   = (wid >> 2) * 64;
    const int wn   = (wid & 3) * 32;
    const int lg   = lane >> 3;
    const int lr   = lane & 7;

    const int lrow = tid >> 1;
    const int lc0  = (tid & 1) * 2;
    const bool arow_ok = (m0 + lrow) < M;
    const int  a_sz = arow_ok ? 16 : 0;
    const uint16_t* pAh = Ah + (size_t)(m0 + lrow) * K + lc0 * 8;
    const uint16_t* pAl = (TERMS == 3) ? Al + (size_t)(m0 + lrow) * K + lc0 * 8 : nullptr;
    const uint16_t* pBh = Bh + (size_t)(n0 + lrow) * K + lc0 * 8;
    const uint16_t* pBl = (TERMS == 3) ? Bl + (size_t)(n0 + lrow) * K + lc0 * 8 : nullptr;
    const uint32_t soff = (uint32_t)(lrow * 80 + lc0 * 16);

    const int KT = K / BK;

    auto load_stage = [&](int kt, int s) {
        uint32_t sb = smem0 + s * STAGE + soff;
        int ko = kt * BK;
        cp16(sb,      pAh + ko,     a_sz);
        cp16(sb + 16, pAh + ko + 8, a_sz);
        if (TERMS == 3) {
            cp16(sb + MAT,      pAl + ko,     a_sz);
            cp16(sb + MAT + 16, pAl + ko + 8, a_sz);
        }
        cp16(sb + OFF_B,      pBh + ko,     16);
        cp16(sb + OFF_B + 16, pBh + ko + 8, 16);
        if (TERMS == 3) {
            cp16(sb + OFF_B + MAT,      pBl + ko,     16);
            cp16(sb + OFF_B + MAT + 16, pBl + ko + 8, 16);
        }
    };

    float acc[4][4][4];
    #pragma unroll
    for (int i = 0; i < 4; i++)
        #pragma unroll
        for (int j = 0; j < 4; j++)
            #pragma unroll
            for (int q = 0; q < 4; q++) acc[i][j][q] = 0.f;

    load_stage(0, 0);
    cp_commit();

    for (int kt = 0; kt < KT; kt++) {
        if (kt + 1 < KT) {
            load_stage(kt + 1, (kt + 1) & 1);
            cp_commit();
            cp_wait1();
        } else {
            cp_wait0();
        }
        __syncthreads();

        const uint32_t baseAh = smem0 + (kt & 1) * STAGE;
        const uint32_t baseAl = baseAh + MAT;
        const uint32_t baseBh = baseAh + OFF_B;
        const uint32_t baseBl = baseBh + MAT;

        #pragma unroll
        for (int ks = 0; ks < 2; ks++) {
            const int kb = ks * 16;
            uint32_t bh[4][2], bl[4][2];
            #pragma unroll
            for (int p = 0; p < 2; p++) {
                int row = wn + p * 16 + lr + (lg & 2) * 4;
                int kc  = kb + (lg & 1) * 8;
                uint32_t off = (uint32_t)(row * LDS + kc) * 2;
                ldmat4(bh[2*p][0], bh[2*p][1], bh[2*p+1][0], bh[2*p+1][1], baseBh + off);
                if (TERMS == 3)
                    ldmat4(bl[2*p][0], bl[2*p][1], bl[2*p+1][0], bl[2*p+1][1], baseBl + off);
            }
            #pragma unroll
            for (int mi = 0; mi < 4; mi++) {
                int row = wm + mi * 16 + lr + (lg & 1) * 8;
                int kc  = kb + (lg & 2) * 4;
                uint32_t off = (uint32_t)(row * LDS + kc) * 2;
                uint32_t ah0, ah1, ah2, ah3;
                ldmat4(ah0, ah1, ah2, ah3, baseAh + off);
                uint32_t al0 = 0, al1 = 0, al2 = 0, al3 = 0;
                if (TERMS == 3) ldmat4(al0, al1, al2, al3, baseAl + off);
                #pragma unroll
                for (int nj = 0; nj < 4; nj++) {
                    if (ISH) {
                        mma_fp(acc[mi][nj], ah0, ah1, ah2, ah3, bh[nj][0], bh[nj][1]);
                    } else {
                        mma_bf(acc[mi][nj], ah0, ah1, ah2, ah3, bh[nj][0], bh[nj][1]);
                        if (TERMS == 3) {
                            mma_bf(acc[mi][nj], ah0, ah1, ah2, ah3, bl[nj][0], bl[nj][1]);
                            mma_bf(acc[mi][nj], al0, al1, al2, al3, bh[nj][0], bh[nj][1]);
                        }
                    }
                }
            }
        }
        __syncthreads();
    }

    // ---- epilogue ----
    const int gr  = lane >> 2;
    const int gc2 = (lane & 3) * 2;
    #pragma unroll
    for (int mi = 0; mi < 4; mi++) {
        #pragma unroll
        for (int half = 0; half < 2; half++) {
            int gm = m0 + wm + mi * 16 + gr + half * 8;
            if (gm >= M) continue;
            #pragma unroll
            for (int nj = 0; nj < 4; nj++) {
                int gn = n0 + wn + nj * 8 + gc2;
                float v0 = acc[mi][nj][half * 2 + 0];
                float v1 = acc[mi][nj][half * 2 + 1];
                if (MODE == 1) {
                    v0 = fmaxf(v0 + bias[gn], 0.f);
                    v1 = fmaxf(v1 + bias[gn + 1], 0.f);
                    *(__half2*)(Ch + (size_t)gm * N + gn) =
                        __halves2half2(__float2half_rn(v0), __float2half_rn(v1));
                } else {
                    if (MODE == 2) {
                        const float* rr = resid + (size_t)gm * N + gn;
                        v0 += bias[gn]     + rr[0];
                        v1 += bias[gn + 1] + rr[1];
                    }
                    *(float2*)(C + (size_t)gm * N + gn) = make_float2(v0, v1);
                }
            }
        }
    }
}

// ---------------- LayerNorm, warp per row, float4 --------------------------
// OUTK 0: fp32 + bf16 hi/lo (LN1).   OUTK 1: fp16 only (LN2).
template <int OUTK>
__global__ void ln256w_kernel(const float* __restrict__ in,
                              const float* __restrict__ g,
                              const float* __restrict__ b,
                              float* __restrict__ out_f32,
                              __nv_bfloat16* __restrict__ out_h,
                              __nv_bfloat16* __restrict__ out_l,
                              __half* __restrict__ out_16) {
    int row  = blockIdx.x * 8 + (threadIdx.x >> 5);
    int lane = threadIdx.x & 31;
    if (row >= NN) return;
    const float* rp = in + (size_t)row * 256;
    float4 v0 = *(const float4*)(rp + lane * 8);
    float4 v1 = *(const float4*)(rp + lane * 8 + 4);
    float s  = v0.x + v0.y + v0.z + v0.w + v1.x + v1.y + v1.z + v1.w;
    float sq = v0.x*v0.x + v0.y*v0.y + v0.z*v0.z + v0.w*v0.w
             + v1.x*v1.x + v1.y*v1.y + v1.z*v1.z + v1.w*v1.w;
    #pragma unroll
    for (int o = 16; o > 0; o >>= 1) {
        s  += __shfl_xor_sync(0xffffffffu, s, o);
        sq += __shfl_xor_sync(0xffffffffu, sq, o);
    }
    float mu  = s * (1.0f / 256.0f);
    float var = sq * (1.0f / 256.0f) - mu * mu;
    float rs  = rsqrtf(var + 1e-5f);
    float4 g0 = *(const float4*)(g + lane * 8);
    float4 g1 = *(const float4*)(g + lane * 8 + 4);
    float4 b0 = *(const float4*)(b + lane * 8);
    float4 b1 = *(const float4*)(b + lane * 8 + 4);
    float y[8];
    y[0] = (v0.x - mu) * rs * g0.x + b0.x;
    y[1] = (v0.y - mu) * rs * g0.y + b0.y;
    y[2] = (v0.z - mu) * rs * g0.z + b0.z;
    y[3] = (v0.w - mu) * rs * g0.w + b0.w;
    y[4] = (v1.x - mu) * rs * g1.x + b1.x;
    y[5] = (v1.y - mu) * rs * g1.y + b1.y;
    y[6] = (v1.z - mu) * rs * g1.z + b1.z;
    y[7] = (v1.w - mu) * rs * g1.w + b1.w;
    size_t o8 = (size_t)row * 256 + lane * 8;
    if (OUTK == 0) {
        *(float4*)(out_f32 + o8)     = make_float4(y[0], y[1], y[2], y[3]);
        *(float4*)(out_f32 + o8 + 4) = make_float4(y[4], y[5], y[6], y[7]);
        #pragma unroll
        for (int i = 0; i < 8; i += 2) {
            __nv_bfloat16 h0, l0, h1, l1;
            split_bf16(y[i],   h0, l0);
            split_bf16(y[i+1], h1, l1);
            *(__nv_bfloat162*)(out_h + o8 + i) = __nv_bfloat162(h0, h1);
            *(__nv_bfloat162*)(out_l + o8 + i) = __nv_bfloat162(l0, l1);
        }
    } else {
        #pragma unroll
        for (int i = 0; i < 8; i += 2)
            *(__half2*)(out_16 + o8 + i) =
                __halves2half2(__float2half_rn(y[i]), __float2half_rn(y[i+1]));
    }
}

// ---------------- weight conversions ---------------------------------------
__global__ void wconv_bf_kernel(const float* __restrict__ w, int n,
                                __nv_bfloat16* __restrict__ wh,
                                __nv_bfloat16* __restrict__ wl) {
    int i = blockIdx.x * blockDim.x + threadIdx.x;
    if (i >= n) return;
    __nv_bfloat16 hi, lo;
    split_bf16(w[i], hi, lo);
    wh[i] = hi; wl[i] = lo;
}

__global__ void wconv_h_kernel(const float* __restrict__ w, int n,
                               __half* __restrict__ wh) {
    int i = blockIdx.x * blockDim.x + threadIdx.x;
    if (i >= n) return;
    wh[i] = __float2half_rn(w[i]);
}

// ---------------- per-node head scores eh/et -------------------------------
__global__ void ehet_kernel(const float* __restrict__ attn_h,
                            const float* __restrict__ attn_t) {
    int warp = (blockIdx.x * blockDim.x + threadIdx.x) >> 5;
    int lane = threadIdx.x & 31;
    if (warp >= NN) return;
    const float* f = g_feat0 + (size_t)warp * DOUT;
    #pragma unroll
    for (int h = 0; h < NH; h++) {
        float v = f[h * HD + lane];
        float a = v * attn_h[h * HD + lane];
        float b = v * attn_t[h * HD + lane];
        #pragma unroll
        for (int o = 16; o > 0; o >>= 1) {
            a += __shfl_xor_sync(0xffffffffu, a, o);
            b += __shfl_xor_sync(0xffffffffu, b, o);
        }
        if (lane == 0) {
            g_eh[(size_t)warp * NH + h] = a;
            g_et[(size_t)warp * NH + h] = b;
        }
    }
}

// ---------------- edge scores + per-dst softmax ----------------------------
__global__ void scores_kernel(const int* __restrict__ src) {
    int n = blockIdx.x;
    int t = threadIdx.x;
    int j = t >> 3, h = t & 7;
    __shared__ int   ssrc[DEG];
    __shared__ float se[DEG][NH];
    __shared__ float sm[NH], ss[NH];
    if (t < DEG) ssrc[t] = src[(size_t)n * DEG + t];
    __syncthreads();
    int s = ssrc[j];
    float e = g_eh[(size_t)s * NH + h] + g_et[(size_t)n * NH + h];
    e = (e > 0.f) ? e : SLOPE * e;
    se[j][h] = e;
    __syncthreads();
    if (t < NH) {
        float m = -1e30f;
        #pragma unroll
        for (int jj = 0; jj < DEG; jj++) m = fmaxf(m, se[jj][t]);
        float sum = 0.f;
        #pragma unroll
        for (int jj = 0; jj < DEG; jj++) sum += __expf(se[jj][t] - m);
        sm[t] = m; ss[t] = sum;
    }
    __syncthreads();
    g_a[(size_t)n * (DEG * NH) + t] = __expf(se[j][h] - sm[h]) / ss[h];
}

// ---------------- one PPR hop ----------------------------------------------
__global__ void hop_kernel(const int* __restrict__ src, int hop) {
    const float* fin;
    float* fout;
    if      (hop == 0) { fin = g_feat0; fout = g_fa; }
    else if (hop == 1) { fin = g_fa;    fout = g_fb; }
    else if (hop == 2) { fin = g_fb;    fout = g_fa; }
    else if (hop == 3) { fin = g_fa;    fout = g_fb; }
    else               { fin = g_fb;    fout = g_rst; }

    int n = blockIdx.x;
    int c = threadIdx.x;
    __shared__ float aw[DEG * NH];
    __shared__ int   ssrc[DEG];
    if (c < DEG * NH) aw[c] = g_a[(size_t)n * (DEG * NH) + c];
    if (c < DEG)      ssrc[c] = src[(size_t)n * DEG + c];
    __syncthreads();
    int h = c >> 5;
    float acc = 0.f;
    #pragma unroll
    for (int j = 0; j < DEG; j++)
        acc += aw[j * NH + h] * fin[(size_t)ssrc[j] * DOUT + c];
    float v = (1.0f - ALPHA) * acc + ALPHA * g_feat0[(size_t)n * DOUT + c];
    if (hop == HOPS - 1) v += g_h[(size_t)n * DOUT + c];
    fout[(size_t)n * DOUT + c] = v;
}

// ---------------------------------------------------------------------------
extern "C" void kernel_launch(void* const* d_in, const int* in_sizes, int n_in,
                              void* d_out, int out_size) {
    const float* ent_feat = (const float*)d_in[0];
    const float* W_ent    = (const float*)d_in[1];
    const float* attn_h   = (const float*)d_in[2];
    const float* attn_t   = (const float*)d_in[3];
    const float* ln1_g    = (const float*)d_in[4];
    const float* ln1_b    = (const float*)d_in[5];
    const float* ln2_g    = (const float*)d_in[6];
    const float* ln2_b    = (const float*)d_in[7];
    const float* W1       = (const float*)d_in[8];
    const float* b1       = (const float*)d_in[9];
    const float* W2       = (const float*)d_in[10];
    const float* b2       = (const float*)d_in[11];
    const int*   src      = (const int*)d_in[12];
    float*       out      = (float*)d_out;

    const int SMEM3 = 2 * 4 * 10240;   // 81920 (3-term)
    const int SMEM1 = 2 * 2 * 10240;   // 40960 (1-term)
    cudaFuncSetAttribute(gemm_mma<0,3,0>, cudaFuncAttributeMaxDynamicSharedMemorySize, SMEM3);
    cudaFuncSetAttribute(gemm_mma<1,1,1>, cudaFuncAttributeMaxDynamicSharedMemorySize, SMEM1);
    cudaFuncSetAttribute(gemm_mma<2,1,1>, cudaFuncAttributeMaxDynamicSharedMemorySize, SMEM1);

    float *p_h, *p_feat0, *p_rst;
    __nv_bfloat16 *p_hh, *p_hl, *p_wenth, *p_wentl;
    __half *p_x16, *p_t16, *p_w116, *p_w216;
    cudaGetSymbolAddress((void**)&p_h,     g_h);
    cudaGetSymbolAddress((void**)&p_feat0, g_feat0);
    cudaGetSymbolAddress((void**)&p_rst,   g_rst);
    cudaGetSymbolAddress((void**)&p_hh,    g_hh);
    cudaGetSymbolAddress((void**)&p_hl,    g_hl);
    cudaGetSymbolAddress((void**)&p_wenth, g_wenth);
    cudaGetSymbolAddress((void**)&p_wentl, g_wentl);
    cudaGetSymbolAddress((void**)&p_x16,   g_x16);
    cudaGetSymbolAddress((void**)&p_t16,   g_t16);
    cudaGetSymbolAddress((void**)&p_w116,  g_w116);
    cudaGetSymbolAddress((void**)&p_w216,  g_w216);

    // 0. weight conversions (4 launches so launch #6 below is the G1 GEMM,
    //    which the ncu capture (-s 5 -c 1) will then profile)
    wconv_bf_kernel<<<(DOUT * DIN + 255) / 256, 256>>>(W_ent, DOUT * DIN, p_wenth, p_wentl);   // 1
    {
        int n1 = DFF * DOUT, half1 = n1 / 2;
        wconv_h_kernel<<<(half1 + 255) / 256, 256>>>(W1, half1, p_w116);                        // 2
        wconv_h_kernel<<<(half1 + 255) / 256, 256>>>(W1 + half1, half1, p_w116 + half1);        // 3
    }
    wconv_h_kernel<<<(DOUT * DFF + 255) / 256, 256>>>(W2, DOUT * DFF, p_w216);                  // 4

    // 1. h = LN1(ent_feat)  (fp32 + bf16 hi/lo)                                                // 5
    ln256w_kernel<0><<<(NN + 7) / 8, 256>>>(ent_feat, ln1_g, ln1_b, p_h, p_hh, p_hl, nullptr);

    // 2. feat0 = h @ W_ent^T    (split-bf16 3-term)                                            // 6
    {
        dim3 grid(DOUT / 128, (NN + 127) / 128);
        gemm_mma<0,3,0><<<grid, 256, SMEM3>>>((const uint16_t*)p_hh, (const uint16_t*)p_hl,
                                              (const uint16_t*)p_wenth, (const uint16_t*)p_wentl,
                                              nullptr, nullptr, p_feat0, nullptr,
                                              NN, DOUT, DIN);
    }

    // 3. per-node head scores
    ehet_kernel<<<(NN * 32 + 255) / 256, 256>>>(attn_h, attn_t);

    // 4. edge scores + softmax
    scores_kernel<<<NN, DEG * NH>>>(src);

    // 5-9. PPR hops
    for (int hop = 0; hop < HOPS; hop++)
        hop_kernel<<<NN, DOUT>>>(src, hop);

    // 10. x = LN2(rst) -> fp16
    ln256w_kernel<1><<<(NN + 7) / 8, 256>>>(p_rst, ln2_g, ln2_b, nullptr, nullptr, nullptr, p_x16);

    // 11. t = relu(x @ W1^T + b1) -> fp16   (single-pass fp16)
    {
        dim3 grid(DFF / 128, (NN + 127) / 128);
        gemm_mma<1,1,1><<<grid, 256, SMEM1>>>((const uint16_t*)p_x16, nullptr,
                                              (const uint16_t*)p_w116, nullptr,
                                              b1, nullptr, nullptr, p_t16,
                                              NN, DFF, DOUT);
    }

    // 12. out = t @ W2^T + b2 + rst   (single-pass fp16)
    {
        dim3 grid(DOUT / 128, (NN + 127) / 128);
        gemm_mma<2,1,1><<<grid, 256, SMEM1>>>((const uint16_t*)p_t16, nullptr,
                                              (const uint16_t*)p_w216, nullptr,
                                              b2, p_rst, out, nullptr,
                                              NN, DOUT, DFF);
    }
}

// round 7
// speedup vs baseline: 3.2889x; 1.3591x over previous
#include <cuda_runtime.h>
#include <cuda_fp16.h>
#include <math.h>
#include <stdint.h>

// ---------------------------------------------------------------------------
// GDTEncoder: graph attention + PPR diffusion + FFN
// N=50000, DEG=16 (dst-contiguous), D_IN=D_OUT=256, H=8, HD=32, DFF=1024
// All GEMMs single-pass fp16 mma.sync (fp32 accum); hop state fp16.
// ---------------------------------------------------------------------------

#define NN     50000
#define DEG    16
#define EDGES  (NN * DEG)
#define DIN    256
#define NH     8
#define HD     32
#define DOUT   256
#define DFF    1024
#define HOPS   5
#define ALPHA  0.15f
#define SLOPE  0.2f

// ---------------- scratch (static device globals; no allocation) -----------
__device__ __align__(256) float g_h[(size_t)NN * DIN];      // LN1 out (fp32 residual)
__device__ __align__(256) float g_eh[(size_t)NN * NH];
__device__ __align__(256) float g_et[(size_t)NN * NH];
__device__ __align__(256) float g_a[(size_t)EDGES * NH];    // softmaxed edge weights
__device__ __align__(256) float g_rst[(size_t)NN * DOUT];   // feat after hops + h (fp32)

// fp16 state
__device__ __align__(256) __half g_h16[(size_t)NN * DIN];    // LN1 out fp16 (G1 A)
__device__ __align__(256) __half g_f016[(size_t)NN * DOUT];  // feat0 fp16
__device__ __align__(256) __half g_fa16[(size_t)NN * DOUT];  // hop ping
__device__ __align__(256) __half g_fb16[(size_t)NN * DOUT];  // hop pong
__device__ __align__(256) __half g_x16[(size_t)NN * DOUT];   // LN2 out fp16
__device__ __align__(256) __half g_t16[(size_t)NN * DFF];    // FFN hidden fp16
__device__ __align__(256) __half g_went16[DOUT * DIN];
__device__ __align__(256) __half g_w116[DFF * DOUT];
__device__ __align__(256) __half g_w216[DOUT * DFF];

// ---------------- mma / cp.async helpers -----------------------------------
__device__ __forceinline__ void ldmat4(uint32_t& r0, uint32_t& r1,
                                       uint32_t& r2, uint32_t& r3,
                                       uint32_t addr) {
    asm volatile("ldmatrix.sync.aligned.m8n8.x4.shared.b16 {%0,%1,%2,%3}, [%4];"
                 : "=r"(r0), "=r"(r1), "=r"(r2), "=r"(r3) : "r"(addr));
}

__device__ __forceinline__ void mma_fp(float c[4],
                                       uint32_t a0, uint32_t a1, uint32_t a2, uint32_t a3,
                                       uint32_t b0, uint32_t b1) {
    asm volatile(
        "mma.sync.aligned.m16n8k16.row.col.f32.f16.f16.f32 "
        "{%0,%1,%2,%3}, {%4,%5,%6,%7}, {%8,%9}, {%0,%1,%2,%3};"
        : "+f"(c[0]), "+f"(c[1]), "+f"(c[2]), "+f"(c[3])
        : "r"(a0), "r"(a1), "r"(a2), "r"(a3), "r"(b0), "r"(b1));
}

__device__ __forceinline__ void cp16(uint32_t dst, const void* src, int sz) {
    asm volatile("cp.async.cg.shared.global [%0], [%1], 16, %2;\n"
                 :: "r"(dst), "l"(src), "r"(sz));
}
__device__ __forceinline__ void cp_commit() {
    asm volatile("cp.async.commit_group;\n" ::);
}
__device__ __forceinline__ void cp_wait1() {
    asm volatile("cp.async.wait_group 1;\n" ::);
}
__device__ __forceinline__ void cp_wait0() {
    asm volatile("cp.async.wait_group 0;\n" ::);
}

// ---------------- GEMM: C[M,N] = A[M,K] * B[N,K]^T, fp16 mma ---------------
// MODE 0: plain -> fp16 Ch.   MODE 1: relu(acc+bias) -> fp16 Ch.
// MODE 2: acc+bias+resid -> fp32 C.
// N % 128 == 0, K % 32 == 0.
template <int MODE>
__global__ void __launch_bounds__(256)
gemm_mma(const __half* __restrict__ A, const __half* __restrict__ B,
         const float* __restrict__ bias, const float* __restrict__ resid,
         float* __restrict__ C, __half* __restrict__ Ch,
         int M, int N, int K) {
    constexpr int BM = 128, BN = 128, BK = 32;
    constexpr int LDS = 40;                 // elems/row -> 80B, conflict-free ldmatrix
    constexpr int MAT = BM * LDS * 2;       // 10240 B per matrix
    constexpr int STAGE = 2 * MAT;

    extern __shared__ __align__(16) char dynsmem[];
    const uint32_t smem0 = (uint32_t)__cvta_generic_to_shared(dynsmem);

    const int tid  = threadIdx.x;
    const int m0   = blockIdx.y * BM;
    const int n0   = blockIdx.x * BN;
    const int wid  = tid >> 5;
    const int lane = tid & 31;
    const int wm   = (wid >> 2) * 64;
    const int wn   = (wid & 3) * 32;
    const int lg   = lane >> 3;
    const int lr   = lane & 7;

    const int lrow = tid >> 1;
    const int lc0  = (tid & 1) * 2;
    const bool arow_ok = (m0 + lrow) < M;
    const int  a_sz = arow_ok ? 16 : 0;
    const __half* pA = A + (size_t)(m0 + lrow) * K + lc0 * 8;
    const __half* pB = B + (size_t)(n0 + lrow) * K + lc0 * 8;
    const uint32_t soff = (uint32_t)(lrow * 80 + lc0 * 16);

    const int KT = K / BK;

    auto load_stage = [&](int kt, int s) {
        uint32_t sb = smem0 + s * STAGE + soff;
        int ko = kt * BK;
        cp16(sb,            pA + ko,     a_sz);
        cp16(sb + 16,       pA + ko + 8, a_sz);
        cp16(sb + MAT,      pB + ko,     16);
        cp16(sb + MAT + 16, pB + ko + 8, 16);
    };

    float acc[4][4][4];
    #pragma unroll
    for (int i = 0; i < 4; i++)
        #pragma unroll
        for (int j = 0; j < 4; j++)
            #pragma unroll
            for (int q = 0; q < 4; q++) acc[i][j][q] = 0.f;

    load_stage(0, 0);
    cp_commit();

    for (int kt = 0; kt < KT; kt++) {
        if (kt + 1 < KT) {
            load_stage(kt + 1, (kt + 1) & 1);
            cp_commit();
            cp_wait1();
        } else {
            cp_wait0();
        }
        __syncthreads();

        const uint32_t baseA = smem0 + (kt & 1) * STAGE;
        const uint32_t baseB = baseA + MAT;

        #pragma unroll
        for (int ks = 0; ks < 2; ks++) {
            const int kb = ks * 16;
            uint32_t bh[4][2];
            #pragma unroll
            for (int p = 0; p < 2; p++) {
                int row = wn + p * 16 + lr + (lg & 2) * 4;
                int kc  = kb + (lg & 1) * 8;
                uint32_t off = (uint32_t)(row * LDS + kc) * 2;
                ldmat4(bh[2*p][0], bh[2*p][1], bh[2*p+1][0], bh[2*p+1][1], baseB + off);
            }
            #pragma unroll
            for (int mi = 0; mi < 4; mi++) {
                int row = wm + mi * 16 + lr + (lg & 1) * 8;
                int kc  = kb + (lg & 2) * 4;
                uint32_t off = (uint32_t)(row * LDS + kc) * 2;
                uint32_t a0, a1, a2, a3;
                ldmat4(a0, a1, a2, a3, baseA + off);
                #pragma unroll
                for (int nj = 0; nj < 4; nj++)
                    mma_fp(acc[mi][nj], a0, a1, a2, a3, bh[nj][0], bh[nj][1]);
            }
        }
        __syncthreads();
    }

    // ---- epilogue ----
    const int gr  = lane >> 2;
    const int gc2 = (lane & 3) * 2;
    #pragma unroll
    for (int mi = 0; mi < 4; mi++) {
        #pragma unroll
        for (int half = 0; half < 2; half++) {
            int gm = m0 + wm + mi * 16 + gr + half * 8;
            if (gm >= M) continue;
            #pragma unroll
            for (int nj = 0; nj < 4; nj++) {
                int gn = n0 + wn + nj * 8 + gc2;
                float v0 = acc[mi][nj][half * 2 + 0];
                float v1 = acc[mi][nj][half * 2 + 1];
                if (MODE == 0) {
                    *(__half2*)(Ch + (size_t)gm * N + gn) =
                        __halves2half2(__float2half_rn(v0), __float2half_rn(v1));
                } else if (MODE == 1) {
                    v0 = fmaxf(v0 + bias[gn], 0.f);
                    v1 = fmaxf(v1 + bias[gn + 1], 0.f);
                    *(__half2*)(Ch + (size_t)gm * N + gn) =
                        __halves2half2(__float2half_rn(v0), __float2half_rn(v1));
                } else {
                    const float* rr = resid + (size_t)gm * N + gn;
                    v0 += bias[gn]     + rr[0];
                    v1 += bias[gn + 1] + rr[1];
                    *(float2*)(C + (size_t)gm * N + gn) = make_float2(v0, v1);
                }
            }
        }
    }
}

// ---------------- LayerNorm, warp per row ----------------------------------
// WRITE_F32: also emit fp32 copy (LN1 residual).
template <bool WRITE_F32>
__global__ void ln256w_kernel(const float* __restrict__ in,
                              const float* __restrict__ g,
                              const float* __restrict__ b,
                              float* __restrict__ out_f32,
                              __half* __restrict__ out_16) {
    int row  = blockIdx.x * 8 + (threadIdx.x >> 5);
    int lane = threadIdx.x & 31;
    if (row >= NN) return;
    const float* rp = in + (size_t)row * 256;
    float4 v0 = *(const float4*)(rp + lane * 8);
    float4 v1 = *(const float4*)(rp + lane * 8 + 4);
    float s  = v0.x + v0.y + v0.z + v0.w + v1.x + v1.y + v1.z + v1.w;
    float sq = v0.x*v0.x + v0.y*v0.y + v0.z*v0.z + v0.w*v0.w
             + v1.x*v1.x + v1.y*v1.y + v1.z*v1.z + v1.w*v1.w;
    #pragma unroll
    for (int o = 16; o > 0; o >>= 1) {
        s  += __shfl_xor_sync(0xffffffffu, s, o);
        sq += __shfl_xor_sync(0xffffffffu, sq, o);
    }
    float mu  = s * (1.0f / 256.0f);
    float var = sq * (1.0f / 256.0f) - mu * mu;
    float rs  = rsqrtf(var + 1e-5f);
    float4 g0 = *(const float4*)(g + lane * 8);
    float4 g1 = *(const float4*)(g + lane * 8 + 4);
    float4 b0 = *(const float4*)(b + lane * 8);
    float4 b1 = *(const float4*)(b + lane * 8 + 4);
    float y[8];
    y[0] = (v0.x - mu) * rs * g0.x + b0.x;
    y[1] = (v0.y - mu) * rs * g0.y + b0.y;
    y[2] = (v0.z - mu) * rs * g0.z + b0.z;
    y[3] = (v0.w - mu) * rs * g0.w + b0.w;
    y[4] = (v1.x - mu) * rs * g1.x + b1.x;
    y[5] = (v1.y - mu) * rs * g1.y + b1.y;
    y[6] = (v1.z - mu) * rs * g1.z + b1.z;
    y[7] = (v1.w - mu) * rs * g1.w + b1.w;
    size_t o8 = (size_t)row * 256 + lane * 8;
    if (WRITE_F32) {
        *(float4*)(out_f32 + o8)     = make_float4(y[0], y[1], y[2], y[3]);
        *(float4*)(out_f32 + o8 + 4) = make_float4(y[4], y[5], y[6], y[7]);
    }
    #pragma unroll
    for (int i = 0; i < 8; i += 2)
        *(__half2*)(out_16 + o8 + i) =
            __halves2half2(__float2half_rn(y[i]), __float2half_rn(y[i+1]));
}

// ---------------- weight fp32 -> fp16 --------------------------------------
__global__ void wconv_h_kernel(const float* __restrict__ w, int n,
                               __half* __restrict__ wh) {
    int i = (blockIdx.x * blockDim.x + threadIdx.x) * 4;
    if (i >= n) return;
    float4 v = *(const float4*)(w + i);
    *(__half2*)(wh + i)     = __halves2half2(__float2half_rn(v.x), __float2half_rn(v.y));
    *(__half2*)(wh + i + 2) = __halves2half2(__float2half_rn(v.z), __float2half_rn(v.w));
}

// ---------------- per-node head scores eh/et (warp per node, fp16 feat) ----
__global__ void ehet_kernel(const float* __restrict__ attn_h,
                            const float* __restrict__ attn_t) {
    int warp = (blockIdx.x * blockDim.x + threadIdx.x) >> 5;
    int lane = threadIdx.x & 31;
    if (warp >= NN) return;
    const __half* f = g_f016 + (size_t)warp * DOUT;
    #pragma unroll
    for (int h = 0; h < NH; h++) {
        float v = __half2float(f[h * HD + lane]);
        float a = v * attn_h[h * HD + lane];
        float b = v * attn_t[h * HD + lane];
        #pragma unroll
        for (int o = 16; o > 0; o >>= 1) {
            a += __shfl_xor_sync(0xffffffffu, a, o);
            b += __shfl_xor_sync(0xffffffffu, b, o);
        }
        if (lane == 0) {
            g_eh[(size_t)warp * NH + h] = a;
            g_et[(size_t)warp * NH + h] = b;
        }
    }
}

// ---------------- edge scores + per-dst softmax ----------------------------
__global__ void scores_kernel(const int* __restrict__ src) {
    int n = blockIdx.x;
    int t = threadIdx.x;
    int j = t >> 3, h = t & 7;
    __shared__ int   ssrc[DEG];
    __shared__ float se[DEG][NH];
    __shared__ float sm[NH], ss[NH];
    if (t < DEG) ssrc[t] = src[(size_t)n * DEG + t];
    __syncthreads();
    int s = ssrc[j];
    float e = g_eh[(size_t)s * NH + h] + g_et[(size_t)n * NH + h];
    e = (e > 0.f) ? e : SLOPE * e;
    se[j][h] = e;
    __syncthreads();
    if (t < NH) {
        float m = -1e30f;
        #pragma unroll
        for (int jj = 0; jj < DEG; jj++) m = fmaxf(m, se[jj][t]);
        float sum = 0.f;
        #pragma unroll
        for (int jj = 0; jj < DEG; jj++) sum += __expf(se[jj][t] - m);
        sm[t] = m; ss[t] = sum;
    }
    __syncthreads();
    g_a[(size_t)n * (DEG * NH) + t] = __expf(se[j][h] - sm[h]) / ss[h];
}

// ---------------- one PPR hop, fp16 state (block 128 thr = 128 half2) ------
// last hop fuses "+ h" residual and writes fp32 g_rst
__global__ void hop16_kernel(const int* __restrict__ src, int hop) {
    const __half2* fin;
    __half2* fout16 = nullptr;
    if      (hop == 0) { fin = (const __half2*)g_f016; fout16 = (__half2*)g_fa16; }
    else if (hop == 1) { fin = (const __half2*)g_fa16; fout16 = (__half2*)g_fb16; }
    else if (hop == 2) { fin = (const __half2*)g_fb16; fout16 = (__half2*)g_fa16; }
    else if (hop == 3) { fin = (const __half2*)g_fa16; fout16 = (__half2*)g_fb16; }
    else               { fin = (const __half2*)g_fb16; }

    int n = blockIdx.x;
    int t = threadIdx.x;                 // channel pair 0..127
    __shared__ float aw[DEG * NH];
    __shared__ int   ssrc[DEG];
    aw[t] = g_a[(size_t)n * (DEG * NH) + t];
    if (t < DEG) ssrc[t] = src[(size_t)n * DEG + t];
    __syncthreads();

    int h = t >> 4;                      // head for channels 2t, 2t+1
    float ax = 0.f, ay = 0.f;
    #pragma unroll
    for (int j = 0; j < DEG; j++) {
        float2 f = __half22float2(fin[(size_t)ssrc[j] * 128 + t]);
        float w = aw[j * NH + h];
        ax += w * f.x;
        ay += w * f.y;
    }
    float2 f0 = __half22float2(((const __half2*)g_f016)[(size_t)n * 128 + t]);
    float vx = (1.0f - ALPHA) * ax + ALPHA * f0.x;
    float vy = (1.0f - ALPHA) * ay + ALPHA * f0.y;
    if (hop == HOPS - 1) {
        float2 hh = *(const float2*)(g_h + (size_t)n * 256 + t * 2);
        *(float2*)(g_rst + (size_t)n * 256 + t * 2) = make_float2(vx + hh.x, vy + hh.y);
    } else {
        fout16[(size_t)n * 128 + t] = __halves2half2(__float2half_rn(vx), __float2half_rn(vy));
    }
}

// ---------------------------------------------------------------------------
extern "C" void kernel_launch(void* const* d_in, const int* in_sizes, int n_in,
                              void* d_out, int out_size) {
    const float* ent_feat = (const float*)d_in[0];
    const float* W_ent    = (const float*)d_in[1];
    const float* attn_h   = (const float*)d_in[2];
    const float* attn_t   = (const float*)d_in[3];
    const float* ln1_g    = (const float*)d_in[4];
    const float* ln1_b    = (const float*)d_in[5];
    const float* ln2_g    = (const float*)d_in[6];
    const float* ln2_b    = (const float*)d_in[7];
    const float* W1       = (const float*)d_in[8];
    const float* b1       = (const float*)d_in[9];
    const float* W2       = (const float*)d_in[10];
    const float* b2       = (const float*)d_in[11];
    const int*   src      = (const int*)d_in[12];
    float*       out      = (float*)d_out;

    const int SMEM = 2 * 2 * 10240;   // 40960, double-buffered A+B
    cudaFuncSetAttribute(gemm_mma<0>, cudaFuncAttributeMaxDynamicSharedMemorySize, SMEM);
    cudaFuncSetAttribute(gemm_mma<1>, cudaFuncAttributeMaxDynamicSharedMemorySize, SMEM);
    cudaFuncSetAttribute(gemm_mma<2>, cudaFuncAttributeMaxDynamicSharedMemorySize, SMEM);

    float *p_h, *p_rst;
    __half *p_h16, *p_f016, *p_x16, *p_t16, *p_went16, *p_w116, *p_w216;
    cudaGetSymbolAddress((void**)&p_h,      g_h);
    cudaGetSymbolAddress((void**)&p_rst,    g_rst);
    cudaGetSymbolAddress((void**)&p_h16,    g_h16);
    cudaGetSymbolAddress((void**)&p_f016,   g_f016);
    cudaGetSymbolAddress((void**)&p_x16,    g_x16);
    cudaGetSymbolAddress((void**)&p_t16,    g_t16);
    cudaGetSymbolAddress((void**)&p_went16, g_went16);
    cudaGetSymbolAddress((void**)&p_w116,   g_w116);
    cudaGetSymbolAddress((void**)&p_w216,   g_w216);

    // 0. weight conversions (4 launches -> G1 GEMM is launch #6 for ncu -s 5)
    wconv_h_kernel<<<(DOUT * DIN / 4 + 255) / 256, 256>>>(W_ent, DOUT * DIN, p_went16);  // 1
    {
        int n1 = DFF * DOUT, half1 = n1 / 2;
        wconv_h_kernel<<<(half1 / 4 + 255) / 256, 256>>>(W1, half1, p_w116);             // 2
        wconv_h_kernel<<<(half1 / 4 + 255) / 256, 256>>>(W1 + half1, half1, p_w116 + half1); // 3
    }
    wconv_h_kernel<<<(DOUT * DFF / 4 + 255) / 256, 256>>>(W2, DOUT * DFF, p_w216);       // 4

    // 1. h = LN1(ent_feat)  (fp32 + fp16)                                               // 5
    ln256w_kernel<true><<<(NN + 7) / 8, 256>>>(ent_feat, ln1_g, ln1_b, p_h, p_h16);

    // 2. feat0 = h @ W_ent^T -> fp16                                                    // 6
    {
        dim3 grid(DOUT / 128, (NN + 127) / 128);
        gemm_mma<0><<<grid, 256, SMEM>>>(p_h16, p_went16, nullptr, nullptr,
                                         nullptr, p_f016, NN, DOUT, DIN);
    }

    // 3. per-node head scores
    ehet_kernel<<<(NN * 32 + 255) / 256, 256>>>(attn_h, attn_t);

    // 4. edge scores + softmax
    scores_kernel<<<NN, DEG * NH>>>(src);

    // 5-9. PPR hops (fp16 state; last hop writes fp32 rst with +h residual)
    for (int hop = 0; hop < HOPS; hop++)
        hop16_kernel<<<NN, 128>>>(src, hop);

    // 10. x = LN2(rst) -> fp16
    ln256w_kernel<false><<<(NN + 7) / 8, 256>>>(p_rst, ln2_g, ln2_b, nullptr, p_x16);

    // 11. t = relu(x @ W1^T + b1) -> fp16
    {
        dim3 grid(DFF / 128, (NN + 127) / 128);
        gemm_mma<1><<<grid, 256, SMEM>>>(p_x16, p_w116, b1, nullptr,
                                         nullptr, p_t16, NN, DFF, DOUT);
    }

    // 12. out = t @ W2^T + b2 + rst  (fp32)
    {
        dim3 grid(DOUT / 128, (NN + 127) / 128);
        gemm_mma<2><<<grid, 256, SMEM>>>(p_t16, p_w216, b2, p_rst,
                                         out, nullptr, NN, DOUT, DFF);
    }
}

// round 8
// speedup vs baseline: 3.6347x; 1.1052x over previous
#include <cuda_runtime.h>
#include <cuda_fp16.h>
#include <math.h>
#include <stdint.h>

// ---------------------------------------------------------------------------
// GDTEncoder: graph attention + PPR diffusion + FFN
// N=50000, DEG=16 (dst-contiguous), D_IN=D_OUT=256, H=8, HD=32, DFF=1024
// fp16 mma.sync GEMMs (4-stage cp.async), ehet fused into G1 epilogue,
// LN2 fused into final hop, fp16 hop state.
// ---------------------------------------------------------------------------

#define NN     50000
#define DEG    16
#define EDGES  (NN * DEG)
#define DIN    256
#define NH     8
#define HD     32
#define DOUT   256
#define DFF    1024
#define HOPS   5
#define ALPHA  0.15f
#define SLOPE  0.2f

// ---------------- scratch (static device globals; no allocation) -----------
__device__ __align__(256) float g_h[(size_t)NN * DIN];      // LN1 out (fp32 residual)
__device__ __align__(256) float g_eh[(size_t)NN * NH];
__device__ __align__(256) float g_et[(size_t)NN * NH];
__device__ __align__(256) float g_a[(size_t)EDGES * NH];    // softmaxed edge weights
__device__ __align__(256) float g_rst[(size_t)NN * DOUT];   // feat after hops + h (fp32)

__device__ __align__(256) __half g_h16[(size_t)NN * DIN];    // LN1 out fp16 (G1 A)
__device__ __align__(256) __half g_f016[(size_t)NN * DOUT];  // feat0 fp16
__device__ __align__(256) __half g_fa16[(size_t)NN * DOUT];  // hop ping
__device__ __align__(256) __half g_fb16[(size_t)NN * DOUT];  // hop pong
__device__ __align__(256) __half g_x16[(size_t)NN * DOUT];   // LN2 out fp16
__device__ __align__(256) __half g_t16[(size_t)NN * DFF];    // FFN hidden fp16
__device__ __align__(256) __half g_went16[DOUT * DIN];
__device__ __align__(256) __half g_w116[DFF * DOUT];
__device__ __align__(256) __half g_w216[DOUT * DFF];

// ---------------- mma / cp.async helpers -----------------------------------
__device__ __forceinline__ void ldmat4(uint32_t& r0, uint32_t& r1,
                                       uint32_t& r2, uint32_t& r3,
                                       uint32_t addr) {
    asm volatile("ldmatrix.sync.aligned.m8n8.x4.shared.b16 {%0,%1,%2,%3}, [%4];"
                 : "=r"(r0), "=r"(r1), "=r"(r2), "=r"(r3) : "r"(addr));
}

__device__ __forceinline__ void mma_fp(float c[4],
                                       uint32_t a0, uint32_t a1, uint32_t a2, uint32_t a3,
                                       uint32_t b0, uint32_t b1) {
    asm volatile(
        "mma.sync.aligned.m16n8k16.row.col.f32.f16.f16.f32 "
        "{%0,%1,%2,%3}, {%4,%5,%6,%7}, {%8,%9}, {%0,%1,%2,%3};"
        : "+f"(c[0]), "+f"(c[1]), "+f"(c[2]), "+f"(c[3])
        : "r"(a0), "r"(a1), "r"(a2), "r"(a3), "r"(b0), "r"(b1));
}

__device__ __forceinline__ void cp16(uint32_t dst, const void* src, int sz) {
    asm volatile("cp.async.cg.shared.global [%0], [%1], 16, %2;\n"
                 :: "r"(dst), "l"(src), "r"(sz));
}
__device__ __forceinline__ void cp_commit() {
    asm volatile("cp.async.commit_group;\n" ::);
}
template <int N>
__device__ __forceinline__ void cp_waitg() {
    asm volatile("cp.async.wait_group %0;\n" :: "n"(N));
}

// ---------------- GEMM: C[M,N] = A[M,K] * B[N,K]^T, fp16 mma ---------------
// MODE 0: plain -> fp16 Ch, PLUS fused per-head eh/et dot products (G1).
// MODE 1: relu(acc+bias) -> fp16 Ch.   MODE 2: acc+bias+resid -> fp32 C.
// N % 128 == 0, K % 32 == 0.  4-stage cp.async ring, 1 syncthreads/tile.
template <int MODE>
__global__ void __launch_bounds__(256)
gemm_mma(const __half* __restrict__ A, const __half* __restrict__ B,
         const float* __restrict__ bias, const float* __restrict__ resid,
         float* __restrict__ C, __half* __restrict__ Ch,
         const float* __restrict__ attn_h, const float* __restrict__ attn_t,
         int M, int N, int K) {
    constexpr int BM = 128, BN = 128, BK = 32;
    constexpr int LDS = 40;                 // elems/row -> 80B, conflict-free ldmatrix
    constexpr int MAT = BM * LDS * 2;       // 10240 B per matrix
    constexpr int STAGE = 2 * MAT;          // 20480 B (A + B)
    constexpr int STAGES = 4;

    extern __shared__ __align__(16) char dynsmem[];
    const uint32_t smem0 = (uint32_t)__cvta_generic_to_shared(dynsmem);

    const int tid  = threadIdx.x;
    const int m0   = blockIdx.y * BM;
    const int n0   = blockIdx.x * BN;
    const int wid  = tid >> 5;
    const int lane = tid & 31;
    const int wm   = (wid >> 2) * 64;
    const int wn   = (wid & 3) * 32;
    const int lg   = lane >> 3;
    const int lr   = lane & 7;

    const int lrow = tid >> 1;
    const int lc0  = (tid & 1) * 2;
    const bool arow_ok = (m0 + lrow) < M;
    const int  a_sz = arow_ok ? 16 : 0;
    const __half* pA = A + (size_t)(m0 + lrow) * K + lc0 * 8;
    const __half* pB = B + (size_t)(n0 + lrow) * K + lc0 * 8;
    const uint32_t soff = (uint32_t)(lrow * 80 + lc0 * 16);

    const int KT = K / BK;

    auto load_stage = [&](int kt, int s) {
        uint32_t sb = smem0 + s * STAGE + soff;
        int ko = kt * BK;
        cp16(sb,            pA + ko,     a_sz);
        cp16(sb + 16,       pA + ko + 8, a_sz);
        cp16(sb + MAT,      pB + ko,     16);
        cp16(sb + MAT + 16, pB + ko + 8, 16);
    };

    float acc[4][4][4];
    #pragma unroll
    for (int i = 0; i < 4; i++)
        #pragma unroll
        for (int j = 0; j < 4; j++)
            #pragma unroll
            for (int q = 0; q < 4; q++) acc[i][j][q] = 0.f;

    // prologue: fill STAGES-1 slots
    #pragma unroll
    for (int s = 0; s < STAGES - 1; s++) {
        if (s < KT) load_stage(s, s);
        cp_commit();
    }

    for (int kt = 0; kt < KT; kt++) {
        cp_waitg<STAGES - 2>();     // oldest (kt) stage landed
        __syncthreads();            // also protects slot reuse below

        int nk = kt + STAGES - 1;
        if (nk < KT) load_stage(nk, nk & (STAGES - 1));
        cp_commit();

        const uint32_t baseA = smem0 + (kt & (STAGES - 1)) * STAGE;
        const uint32_t baseB = baseA + MAT;

        #pragma unroll
        for (int ks = 0; ks < 2; ks++) {
            const int kb = ks * 16;
            uint32_t bh[4][2];
            #pragma unroll
            for (int p = 0; p < 2; p++) {
                int row = wn + p * 16 + lr + (lg & 2) * 4;
                int kc  = kb + (lg & 1) * 8;
                uint32_t off = (uint32_t)(row * LDS + kc) * 2;
                ldmat4(bh[2*p][0], bh[2*p][1], bh[2*p+1][0], bh[2*p+1][1], baseB + off);
            }
            #pragma unroll
            for (int mi = 0; mi < 4; mi++) {
                int row = wm + mi * 16 + lr + (lg & 1) * 8;
                int kc  = kb + (lg & 2) * 4;
                uint32_t off = (uint32_t)(row * LDS + kc) * 2;
                uint32_t a0, a1, a2, a3;
                ldmat4(a0, a1, a2, a3, baseA + off);
                #pragma unroll
                for (int nj = 0; nj < 4; nj++)
                    mma_fp(acc[mi][nj], a0, a1, a2, a3, bh[nj][0], bh[nj][1]);
            }
        }
    }

    // ---- epilogue ----
    const int gr  = lane >> 2;
    const int gc2 = (lane & 3) * 2;

    // G1: per-head attn vectors for this warp's 32-column (one-head) chunk
    float avh[8], avt[8];
    int hh = 0;
    if (MODE == 0) {
        hh = (n0 + wn) >> 5;              // head index (wn is 32-aligned)
        #pragma unroll
        for (int nj = 0; nj < 4; nj++)
            #pragma unroll
            for (int q = 0; q < 2; q++) {
                int col = nj * 8 + gc2 + q;
                avh[nj * 2 + q] = attn_h[hh * HD + col];
                avt[nj * 2 + q] = attn_t[hh * HD + col];
            }
    }

    #pragma unroll
    for (int mi = 0; mi < 4; mi++) {
        #pragma unroll
        for (int half = 0; half < 2; half++) {
            int gm = m0 + wm + mi * 16 + gr + half * 8;
            if (gm >= M) continue;        // xor-1/2 partners share gr -> same gm
            if (MODE == 0) {
                float seh = 0.f, set = 0.f;
                #pragma unroll
                for (int nj = 0; nj < 4; nj++) {
                    float v0 = acc[mi][nj][half * 2 + 0];
                    float v1 = acc[mi][nj][half * 2 + 1];
                    int gn = n0 + wn + nj * 8 + gc2;
                    *(__half2*)(Ch + (size_t)gm * N + gn) =
                        __halves2half2(__float2half_rn(v0), __float2half_rn(v1));
                    seh += v0 * avh[nj * 2] + v1 * avh[nj * 2 + 1];
                    set += v0 * avt[nj * 2] + v1 * avt[nj * 2 + 1];
                }
                seh += __shfl_xor_sync(0xffffffffu, seh, 1);
                set += __shfl_xor_sync(0xffffffffu, set, 1);
                seh += __shfl_xor_sync(0xffffffffu, seh, 2);
                set += __shfl_xor_sync(0xffffffffu, set, 2);
                if ((lane & 3) == 0) {
                    g_eh[(size_t)gm * NH + hh] = seh;
                    g_et[(size_t)gm * NH + hh] = set;
                }
            } else {
                #pragma unroll
                for (int nj = 0; nj < 4; nj++) {
                    int gn = n0 + wn + nj * 8 + gc2;
                    float v0 = acc[mi][nj][half * 2 + 0];
                    float v1 = acc[mi][nj][half * 2 + 1];
                    if (MODE == 1) {
                        v0 = fmaxf(v0 + bias[gn], 0.f);
                        v1 = fmaxf(v1 + bias[gn + 1], 0.f);
                        *(__half2*)(Ch + (size_t)gm * N + gn) =
                            __halves2half2(__float2half_rn(v0), __float2half_rn(v1));
                    } else {
                        const float* rr = resid + (size_t)gm * N + gn;
                        v0 += bias[gn]     + rr[0];
                        v1 += bias[gn + 1] + rr[1];
                        *(float2*)(C + (size_t)gm * N + gn) = make_float2(v0, v1);
                    }
                }
            }
        }
    }
}

// ---------------- LayerNorm, warp per row (LN1) -----------------------------
__global__ void ln256w_kernel(const float* __restrict__ in,
                              const float* __restrict__ g,
                              const float* __restrict__ b,
                              float* __restrict__ out_f32,
                              __half* __restrict__ out_16) {
    int row  = blockIdx.x * 8 + (threadIdx.x >> 5);
    int lane = threadIdx.x & 31;
    if (row >= NN) return;
    const float* rp = in + (size_t)row * 256;
    float4 v0 = *(const float4*)(rp + lane * 8);
    float4 v1 = *(const float4*)(rp + lane * 8 + 4);
    float s  = v0.x + v0.y + v0.z + v0.w + v1.x + v1.y + v1.z + v1.w;
    float sq = v0.x*v0.x + v0.y*v0.y + v0.z*v0.z + v0.w*v0.w
             + v1.x*v1.x + v1.y*v1.y + v1.z*v1.z + v1.w*v1.w;
    #pragma unroll
    for (int o = 16; o > 0; o >>= 1) {
        s  += __shfl_xor_sync(0xffffffffu, s, o);
        sq += __shfl_xor_sync(0xffffffffu, sq, o);
    }
    float mu  = s * (1.0f / 256.0f);
    float var = sq * (1.0f / 256.0f) - mu * mu;
    float rs  = rsqrtf(var + 1e-5f);
    float4 g0 = *(const float4*)(g + lane * 8);
    float4 g1 = *(const float4*)(g + lane * 8 + 4);
    float4 b0 = *(const float4*)(b + lane * 8);
    float4 b1 = *(const float4*)(b + lane * 8 + 4);
    float y[8];
    y[0] = (v0.x - mu) * rs * g0.x + b0.x;
    y[1] = (v0.y - mu) * rs * g0.y + b0.y;
    y[2] = (v0.z - mu) * rs * g0.z + b0.z;
    y[3] = (v0.w - mu) * rs * g0.w + b0.w;
    y[4] = (v1.x - mu) * rs * g1.x + b1.x;
    y[5] = (v1.y - mu) * rs * g1.y + b1.y;
    y[6] = (v1.z - mu) * rs * g1.z + b1.z;
    y[7] = (v1.w - mu) * rs * g1.w + b1.w;
    size_t o8 = (size_t)row * 256 + lane * 8;
    *(float4*)(out_f32 + o8)     = make_float4(y[0], y[1], y[2], y[3]);
    *(float4*)(out_f32 + o8 + 4) = make_float4(y[4], y[5], y[6], y[7]);
    #pragma unroll
    for (int i = 0; i < 8; i += 2)
        *(__half2*)(out_16 + o8 + i) =
            __halves2half2(__float2half_rn(y[i]), __float2half_rn(y[i+1]));
}

// ---------------- all weights fp32 -> fp16 (one launch) --------------------
__global__ void wconv_all_kernel(const float* __restrict__ went,
                                 const float* __restrict__ w1,
                                 const float* __restrict__ w2) {
    int i = (blockIdx.x * blockDim.x + threadIdx.x) * 4;
    const int N0 = DOUT * DIN;            // 65536
    const int N1 = N0 + DFF * DOUT;       // 327680
    const int N2 = N1 + DOUT * DFF;       // 589824
    if (i >= N2) return;
    const float* srcp;
    __half* dstp;
    int off;
    if (i < N0)      { srcp = went; dstp = g_went16; off = i; }
    else if (i < N1) { srcp = w1;   dstp = g_w116;   off = i - N0; }
    else             { srcp = w2;   dstp = g_w216;   off = i - N1; }
    float4 v = *(const float4*)(srcp + off);
    *(__half2*)(dstp + off)     = __halves2half2(__float2half_rn(v.x), __float2half_rn(v.y));
    *(__half2*)(dstp + off + 2) = __halves2half2(__float2half_rn(v.z), __float2half_rn(v.w));
}

// ---------------- edge scores + per-dst softmax ----------------------------
__global__ void scores_kernel(const int* __restrict__ src) {
    int n = blockIdx.x;
    int t = threadIdx.x;
    int j = t >> 3, h = t & 7;
    __shared__ int   ssrc[DEG];
    __shared__ float se[DEG][NH];
    __shared__ float sm[NH], ss[NH];
    if (t < DEG) ssrc[t] = src[(size_t)n * DEG + t];
    __syncthreads();
    int s = ssrc[j];
    float e = g_eh[(size_t)s * NH + h] + g_et[(size_t)n * NH + h];
    e = (e > 0.f) ? e : SLOPE * e;
    se[j][h] = e;
    __syncthreads();
    if (t < NH) {
        float m = -1e30f;
        #pragma unroll
        for (int jj = 0; jj < DEG; jj++) m = fmaxf(m, se[jj][t]);
        float sum = 0.f;
        #pragma unroll
        for (int jj = 0; jj < DEG; jj++) sum += __expf(se[jj][t] - m);
        sm[t] = m; ss[t] = sum;
    }
    __syncthreads();
    g_a[(size_t)n * (DEG * NH) + t] = __expf(se[j][h] - sm[h]) / ss[h];
}

// ---------------- hops 0..3, fp16 state (block 128 thr = 128 half2) --------
__global__ void hop16_kernel(const int* __restrict__ src, int hop) {
    const __half2* fin;
    __half2* fout16;
    if      (hop == 0) { fin = (const __half2*)g_f016; fout16 = (__half2*)g_fa16; }
    else if (hop == 1) { fin = (const __half2*)g_fa16; fout16 = (__half2*)g_fb16; }
    else if (hop == 2) { fin = (const __half2*)g_fb16; fout16 = (__half2*)g_fa16; }
    else               { fin = (const __half2*)g_fa16; fout16 = (__half2*)g_fb16; }

    int n = blockIdx.x;
    int t = threadIdx.x;
    __shared__ float aw[DEG * NH];
    __shared__ int   ssrc[DEG];
    aw[t] = g_a[(size_t)n * (DEG * NH) + t];
    if (t < DEG) ssrc[t] = src[(size_t)n * DEG + t];
    __syncthreads();

    int h = t >> 4;
    float ax = 0.f, ay = 0.f;
    #pragma unroll
    for (int j = 0; j < DEG; j++) {
        float2 f = __half22float2(fin[(size_t)ssrc[j] * 128 + t]);
        float w = aw[j * NH + h];
        ax += w * f.x;
        ay += w * f.y;
    }
    float2 f0 = __half22float2(((const __half2*)g_f016)[(size_t)n * 128 + t]);
    float vx = (1.0f - ALPHA) * ax + ALPHA * f0.x;
    float vy = (1.0f - ALPHA) * ay + ALPHA * f0.y;
    fout16[(size_t)n * 128 + t] = __halves2half2(__float2half_rn(vx), __float2half_rn(vy));
}

// ---------------- final hop + residual + fused LN2 -------------------------
// reads g_fb16 (hop4 input), writes fp32 g_rst and fp16 g_x16 = LN2(rst)
__global__ void hoplast_kernel(const int* __restrict__ src,
                               const float* __restrict__ ln2_g,
                               const float* __restrict__ ln2_b) {
    int n = blockIdx.x;
    int t = threadIdx.x;                 // channel pair 0..127
    int wid = t >> 5, lane = t & 31;
    __shared__ float aw[DEG * NH];
    __shared__ int   ssrc[DEG];
    __shared__ float wsum[4], wsq[4];
    aw[t] = g_a[(size_t)n * (DEG * NH) + t];
    if (t < DEG) ssrc[t] = src[(size_t)n * DEG + t];
    __syncthreads();

    int h = t >> 4;
    const __half2* fin = (const __half2*)g_fb16;
    float ax = 0.f, ay = 0.f;
    #pragma unroll
    for (int j = 0; j < DEG; j++) {
        float2 f = __half22float2(fin[(size_t)ssrc[j] * 128 + t]);
        float w = aw[j * NH + h];
        ax += w * f.x;
        ay += w * f.y;
    }
    float2 f0 = __half22float2(((const __half2*)g_f016)[(size_t)n * 128 + t]);
    float2 hh = *(const float2*)(g_h + (size_t)n * 256 + t * 2);
    float vx = (1.0f - ALPHA) * ax + ALPHA * f0.x + hh.x;
    float vy = (1.0f - ALPHA) * ay + ALPHA * f0.y + hh.y;
    *(float2*)(g_rst + (size_t)n * 256 + t * 2) = make_float2(vx, vy);

    // LN2 over the row
    float s  = vx + vy;
    float sq = vx * vx + vy * vy;
    #pragma unroll
    for (int o = 16; o > 0; o >>= 1) {
        s  += __shfl_xor_sync(0xffffffffu, s, o);
        sq += __shfl_xor_sync(0xffffffffu, sq, o);
    }
    if (lane == 0) { wsum[wid] = s; wsq[wid] = sq; }
    __syncthreads();
    s = wsum[0] + wsum[1] + wsum[2] + wsum[3];
    sq = wsq[0] + wsq[1] + wsq[2] + wsq[3];
    float mu  = s * (1.0f / 256.0f);
    float var = sq * (1.0f / 256.0f) - mu * mu;
    float rs  = rsqrtf(var + 1e-5f);
    float2 gg = *(const float2*)(ln2_g + t * 2);
    float2 bb = *(const float2*)(ln2_b + t * 2);
    float yx = (vx - mu) * rs * gg.x + bb.x;
    float yy = (vy - mu) * rs * gg.y + bb.y;
    ((__half2*)g_x16)[(size_t)n * 128 + t] =
        __halves2half2(__float2half_rn(yx), __float2half_rn(yy));
}

// ---------------------------------------------------------------------------
extern "C" void kernel_launch(void* const* d_in, const int* in_sizes, int n_in,
                              void* d_out, int out_size) {
    const float* ent_feat = (const float*)d_in[0];
    const float* W_ent    = (const float*)d_in[1];
    const float* attn_h   = (const float*)d_in[2];
    const float* attn_t   = (const float*)d_in[3];
    const float* ln1_g    = (const float*)d_in[4];
    const float* ln1_b    = (const float*)d_in[5];
    const float* ln2_g    = (const float*)d_in[6];
    const float* ln2_b    = (const float*)d_in[7];
    const float* W1       = (const float*)d_in[8];
    const float* b1       = (const float*)d_in[9];
    const float* W2       = (const float*)d_in[10];
    const float* b2       = (const float*)d_in[11];
    const int*   src      = (const int*)d_in[12];
    float*       out      = (float*)d_out;

    const int SMEM = 4 * 20480;   // 81920, 4-stage ring
    cudaFuncSetAttribute(gemm_mma<0>, cudaFuncAttributeMaxDynamicSharedMemorySize, SMEM);
    cudaFuncSetAttribute(gemm_mma<1>, cudaFuncAttributeMaxDynamicSharedMemorySize, SMEM);
    cudaFuncSetAttribute(gemm_mma<2>, cudaFuncAttributeMaxDynamicSharedMemorySize, SMEM);

    float *p_h, *p_rst;
    __half *p_h16, *p_f016, *p_x16, *p_t16, *p_went16, *p_w116, *p_w216;
    cudaGetSymbolAddress((void**)&p_h,      g_h);
    cudaGetSymbolAddress((void**)&p_rst,    g_rst);
    cudaGetSymbolAddress((void**)&p_h16,    g_h16);
    cudaGetSymbolAddress((void**)&p_f016,   g_f016);
    cudaGetSymbolAddress((void**)&p_x16,    g_x16);
    cudaGetSymbolAddress((void**)&p_t16,    g_t16);
    cudaGetSymbolAddress((void**)&p_went16, g_went16);
    cudaGetSymbolAddress((void**)&p_w116,   g_w116);
    cudaGetSymbolAddress((void**)&p_w216,   g_w216);

    // 1. all weights -> fp16 (single launch)
    wconv_all_kernel<<<(589824 / 4 + 255) / 256, 256>>>(W_ent, W1, W2);

    // 2. h = LN1(ent_feat)  (fp32 + fp16)
    ln256w_kernel<<<(NN + 7) / 8, 256>>>(ent_feat, ln1_g, ln1_b, p_h, p_h16);

    // 3. feat0 = h @ W_ent^T -> fp16, with fused eh/et head dots
    {
        dim3 grid(DOUT / 128, (NN + 127) / 128);
        gemm_mma<0><<<grid, 256, SMEM>>>(p_h16, p_went16, nullptr, nullptr,
                                         nullptr, p_f016, attn_h, attn_t,
                                         NN, DOUT, DIN);
    }

    // 4. edge scores + softmax
    scores_kernel<<<NN, DEG * NH>>>(src);

    // 5-8. hops 0..3 (fp16 state)   [launch #6 = hop1 for ncu]
    for (int hop = 0; hop < HOPS - 1; hop++)
        hop16_kernel<<<NN, 128>>>(src, hop);

    // 9. final hop + residual + fused LN2 -> rst fp32, x fp16
    hoplast_kernel<<<NN, 128>>>(src, ln2_g, ln2_b);

    // 10. t = relu(x @ W1^T + b1) -> fp16
    {
        dim3 grid(DFF / 128, (NN + 127) / 128);
        gemm_mma<1><<<grid, 256, SMEM>>>(p_x16, p_w116, b1, nullptr,
                                         nullptr, p_t16, nullptr, nullptr,
                                         NN, DFF, DOUT);
    }

    // 11. out = t @ W2^T + b2 + rst  (fp32)
    {
        dim3 grid(DOUT / 128, (NN + 127) / 128);
        gemm_mma<2><<<grid, 256, SMEM>>>(p_t16, p_w216, b2, p_rst,
                                         out, nullptr, nullptr, nullptr,
                                         NN, DOUT, DFF);
    }
}

// round 9
// speedup vs baseline: 3.8165x; 1.0500x over previous
#include <cuda_runtime.h>
#include <cuda_fp16.h>
#include <math.h>
#include <stdint.h>

// ---------------------------------------------------------------------------
// GDTEncoder: graph attention + PPR diffusion + FFN
// N=50000, DEG=16 (dst-contiguous), D_IN=D_OUT=256, H=8, HD=32, DFF=1024
// fp16 mma.sync GEMMs (3-stage cp.async, 2 CTA/SM), ehet fused into G1,
// scores fused into hop0, LN2 fused into final hop, fp16 hop state.
// ---------------------------------------------------------------------------

#define NN     50000
#define DEG    16
#define EDGES  (NN * DEG)
#define DIN    256
#define NH     8
#define HD     32
#define DOUT   256
#define DFF    1024
#define HOPS   5
#define ALPHA  0.15f
#define SLOPE  0.2f

// ---------------- scratch (static device globals; no allocation) -----------
__device__ __align__(256) float g_h[(size_t)NN * DIN];      // LN1 out (fp32 residual)
__device__ __align__(256) float g_eh[(size_t)NN * NH];
__device__ __align__(256) float g_et[(size_t)NN * NH];
__device__ __align__(256) float g_a[(size_t)EDGES * NH];    // softmaxed edge weights
__device__ __align__(256) float g_rst[(size_t)NN * DOUT];   // feat after hops + h (fp32)

__device__ __align__(256) __half g_h16[(size_t)NN * DIN];    // LN1 out fp16 (G1 A)
__device__ __align__(256) __half g_f016[(size_t)NN * DOUT];  // feat0 fp16
__device__ __align__(256) __half g_fa16[(size_t)NN * DOUT];  // hop ping
__device__ __align__(256) __half g_fb16[(size_t)NN * DOUT];  // hop pong
__device__ __align__(256) __half g_x16[(size_t)NN * DOUT];   // LN2 out fp16
__device__ __align__(256) __half g_t16[(size_t)NN * DFF];    // FFN hidden fp16
__device__ __align__(256) __half g_went16[DOUT * DIN];
__device__ __align__(256) __half g_w116[DFF * DOUT];
__device__ __align__(256) __half g_w216[DOUT * DFF];

// ---------------- mma / cp.async helpers -----------------------------------
__device__ __forceinline__ void ldmat4(uint32_t& r0, uint32_t& r1,
                                       uint32_t& r2, uint32_t& r3,
                                       uint32_t addr) {
    asm volatile("ldmatrix.sync.aligned.m8n8.x4.shared.b16 {%0,%1,%2,%3}, [%4];"
                 : "=r"(r0), "=r"(r1), "=r"(r2), "=r"(r3) : "r"(addr));
}

__device__ __forceinline__ void mma_fp(float c[4],
                                       uint32_t a0, uint32_t a1, uint32_t a2, uint32_t a3,
                                       uint32_t b0, uint32_t b1) {
    asm volatile(
        "mma.sync.aligned.m16n8k16.row.col.f32.f16.f16.f32 "
        "{%0,%1,%2,%3}, {%4,%5,%6,%7}, {%8,%9}, {%0,%1,%2,%3};"
        : "+f"(c[0]), "+f"(c[1]), "+f"(c[2]), "+f"(c[3])
        : "r"(a0), "r"(a1), "r"(a2), "r"(a3), "r"(b0), "r"(b1));
}

__device__ __forceinline__ void cp16(uint32_t dst, const void* src, int sz) {
    asm volatile("cp.async.cg.shared.global [%0], [%1], 16, %2;\n"
                 :: "r"(dst), "l"(src), "r"(sz));
}
__device__ __forceinline__ void cp_commit() {
    asm volatile("cp.async.commit_group;\n" ::);
}
template <int N>
__device__ __forceinline__ void cp_waitg() {
    asm volatile("cp.async.wait_group %0;\n" :: "n"(N));
}

// ---------------- GEMM: C[M,N] = A[M,K] * B[N,K]^T, fp16 mma ---------------
// MODE 0: plain -> fp16 Ch + fused eh/et.  MODE 1: relu(acc+bias) -> fp16 Ch.
// MODE 2: acc+bias+resid -> fp32 C.
// 3-stage cp.async ring, 2 CTAs/SM, 1 syncthreads/tile.
template <int MODE>
__global__ void __launch_bounds__(256, 2)
gemm_mma(const __half* __restrict__ A, const __half* __restrict__ B,
         const float* __restrict__ bias, const float* __restrict__ resid,
         float* __restrict__ C, __half* __restrict__ Ch,
         const float* __restrict__ attn_h, const float* __restrict__ attn_t,
         int M, int N, int K) {
    constexpr int BM = 128, BN = 128, BK = 32;
    constexpr int LDS = 40;                 // elems/row -> 80B, conflict-free ldmatrix
    constexpr int MAT = BM * LDS * 2;       // 10240 B per matrix
    constexpr int STAGE = 2 * MAT;          // 20480 B (A + B)
    constexpr int STAGES = 3;

    extern __shared__ __align__(16) char dynsmem[];
    const uint32_t smem0 = (uint32_t)__cvta_generic_to_shared(dynsmem);

    const int tid  = threadIdx.x;
    const int m0   = blockIdx.y * BM;
    const int n0   = blockIdx.x * BN;
    const int wid  = tid >> 5;
    const int lane = tid & 31;
    const int wm   = (wid >> 2) * 64;
    const int wn   = (wid & 3) * 32;
    const int lg   = lane >> 3;
    const int lr   = lane & 7;

    const int lrow = tid >> 1;
    const int lc0  = (tid & 1) * 2;
    const bool arow_ok = (m0 + lrow) < M;
    const int  a_sz = arow_ok ? 16 : 0;
    const __half* pA = A + (size_t)(m0 + lrow) * K + lc0 * 8;
    const __half* pB = B + (size_t)(n0 + lrow) * K + lc0 * 8;
    const uint32_t soff = (uint32_t)(lrow * 80 + lc0 * 16);

    const int KT = K / BK;                  // >= 8 for all calls

    auto load_stage = [&](int kt, int s) {
        uint32_t sb = smem0 + s * STAGE + soff;
        int ko = kt * BK;
        cp16(sb,            pA + ko,     a_sz);
        cp16(sb + 16,       pA + ko + 8, a_sz);
        cp16(sb + MAT,      pB + ko,     16);
        cp16(sb + MAT + 16, pB + ko + 8, 16);
    };

    float acc[4][4][4];
    #pragma unroll
    for (int i = 0; i < 4; i++)
        #pragma unroll
        for (int j = 0; j < 4; j++)
            #pragma unroll
            for (int q = 0; q < 4; q++) acc[i][j][q] = 0.f;

    // prologue: fill STAGES-1 slots
    #pragma unroll
    for (int s = 0; s < STAGES - 1; s++) {
        load_stage(s, s);
        cp_commit();
    }

    int cslot = 0;
    int lslot = STAGES - 1;
    for (int kt = 0; kt < KT; kt++) {
        cp_waitg<STAGES - 2>();     // oldest stage landed
        __syncthreads();            // also protects slot reuse

        int nk = kt + STAGES - 1;
        if (nk < KT) load_stage(nk, lslot);
        cp_commit();

        const uint32_t baseA = smem0 + cslot * STAGE;
        const uint32_t baseB = baseA + MAT;

        #pragma unroll
        for (int ks = 0; ks < 2; ks++) {
            const int kb = ks * 16;
            uint32_t bh[4][2];
            #pragma unroll
            for (int p = 0; p < 2; p++) {
                int row = wn + p * 16 + lr + (lg & 2) * 4;
                int kc  = kb + (lg & 1) * 8;
                uint32_t off = (uint32_t)(row * LDS + kc) * 2;
                ldmat4(bh[2*p][0], bh[2*p][1], bh[2*p+1][0], bh[2*p+1][1], baseB + off);
            }
            #pragma unroll
            for (int mi = 0; mi < 4; mi++) {
                int row = wm + mi * 16 + lr + (lg & 1) * 8;
                int kc  = kb + (lg & 2) * 4;
                uint32_t off = (uint32_t)(row * LDS + kc) * 2;
                uint32_t a0, a1, a2, a3;
                ldmat4(a0, a1, a2, a3, baseA + off);
                #pragma unroll
                for (int nj = 0; nj < 4; nj++)
                    mma_fp(acc[mi][nj], a0, a1, a2, a3, bh[nj][0], bh[nj][1]);
            }
        }
        cslot = (cslot + 1 == STAGES) ? 0 : cslot + 1;
        lslot = (lslot + 1 == STAGES) ? 0 : lslot + 1;
    }

    // ---- epilogue ----
    const int gr  = lane >> 2;
    const int gc2 = (lane & 3) * 2;

    float avh[8], avt[8];
    int hh = 0;
    if (MODE == 0) {
        hh = (n0 + wn) >> 5;              // head index (wn is 32-aligned)
        #pragma unroll
        for (int nj = 0; nj < 4; nj++)
            #pragma unroll
            for (int q = 0; q < 2; q++) {
                int col = nj * 8 + gc2 + q;
                avh[nj * 2 + q] = attn_h[hh * HD + col];
                avt[nj * 2 + q] = attn_t[hh * HD + col];
            }
    }

    #pragma unroll
    for (int mi = 0; mi < 4; mi++) {
        #pragma unroll
        for (int half = 0; half < 2; half++) {
            int gm = m0 + wm + mi * 16 + gr + half * 8;
            if (gm >= M) continue;
            if (MODE == 0) {
                float seh = 0.f, set = 0.f;
                #pragma unroll
                for (int nj = 0; nj < 4; nj++) {
                    float v0 = acc[mi][nj][half * 2 + 0];
                    float v1 = acc[mi][nj][half * 2 + 1];
                    int gn = n0 + wn + nj * 8 + gc2;
                    *(__half2*)(Ch + (size_t)gm * N + gn) =
                        __halves2half2(__float2half_rn(v0), __float2half_rn(v1));
                    seh += v0 * avh[nj * 2] + v1 * avh[nj * 2 + 1];
                    set += v0 * avt[nj * 2] + v1 * avt[nj * 2 + 1];
                }
                seh += __shfl_xor_sync(0xffffffffu, seh, 1);
                set += __shfl_xor_sync(0xffffffffu, set, 1);
                seh += __shfl_xor_sync(0xffffffffu, seh, 2);
                set += __shfl_xor_sync(0xffffffffu, set, 2);
                if ((lane & 3) == 0) {
                    g_eh[(size_t)gm * NH + hh] = seh;
                    g_et[(size_t)gm * NH + hh] = set;
                }
            } else {
                #pragma unroll
                for (int nj = 0; nj < 4; nj++) {
                    int gn = n0 + wn + nj * 8 + gc2;
                    float v0 = acc[mi][nj][half * 2 + 0];
                    float v1 = acc[mi][nj][half * 2 + 1];
                    if (MODE == 1) {
                        v0 = fmaxf(v0 + bias[gn], 0.f);
                        v1 = fmaxf(v1 + bias[gn + 1], 0.f);
                        *(__half2*)(Ch + (size_t)gm * N + gn) =
                            __halves2half2(__float2half_rn(v0), __float2half_rn(v1));
                    } else {
                        const float* rr = resid + (size_t)gm * N + gn;
                        v0 += bias[gn]     + rr[0];
                        v1 += bias[gn + 1] + rr[1];
                        *(float2*)(C + (size_t)gm * N + gn) = make_float2(v0, v1);
                    }
                }
            }
        }
    }
}

// ---------------- LayerNorm, warp per row (LN1) -----------------------------
__global__ void ln256w_kernel(const float* __restrict__ in,
                              const float* __restrict__ g,
                              const float* __restrict__ b,
                              float* __restrict__ out_f32,
                              __half* __restrict__ out_16) {
    int row  = blockIdx.x * 8 + (threadIdx.x >> 5);
    int lane = threadIdx.x & 31;
    if (row >= NN) return;
    const float* rp = in + (size_t)row * 256;
    float4 v0 = *(const float4*)(rp + lane * 8);
    float4 v1 = *(const float4*)(rp + lane * 8 + 4);
    float s  = v0.x + v0.y + v0.z + v0.w + v1.x + v1.y + v1.z + v1.w;
    float sq = v0.x*v0.x + v0.y*v0.y + v0.z*v0.z + v0.w*v0.w
             + v1.x*v1.x + v1.y*v1.y + v1.z*v1.z + v1.w*v1.w;
    #pragma unroll
    for (int o = 16; o > 0; o >>= 1) {
        s  += __shfl_xor_sync(0xffffffffu, s, o);
        sq += __shfl_xor_sync(0xffffffffu, sq, o);
    }
    float mu  = s * (1.0f / 256.0f);
    float var = sq * (1.0f / 256.0f) - mu * mu;
    float rs  = rsqrtf(var + 1e-5f);
    float4 g0 = *(const float4*)(g + lane * 8);
    float4 g1 = *(const float4*)(g + lane * 8 + 4);
    float4 b0 = *(const float4*)(b + lane * 8);
    float4 b1 = *(const float4*)(b + lane * 8 + 4);
    float y[8];
    y[0] = (v0.x - mu) * rs * g0.x + b0.x;
    y[1] = (v0.y - mu) * rs * g0.y + b0.y;
    y[2] = (v0.z - mu) * rs * g0.z + b0.z;
    y[3] = (v0.w - mu) * rs * g0.w + b0.w;
    y[4] = (v1.x - mu) * rs * g1.x + b1.x;
    y[5] = (v1.y - mu) * rs * g1.y + b1.y;
    y[6] = (v1.z - mu) * rs * g1.z + b1.z;
    y[7] = (v1.w - mu) * rs * g1.w + b1.w;
    size_t o8 = (size_t)row * 256 + lane * 8;
    *(float4*)(out_f32 + o8)     = make_float4(y[0], y[1], y[2], y[3]);
    *(float4*)(out_f32 + o8 + 4) = make_float4(y[4], y[5], y[6], y[7]);
    #pragma unroll
    for (int i = 0; i < 8; i += 2)
        *(__half2*)(out_16 + o8 + i) =
            __halves2half2(__float2half_rn(y[i]), __float2half_rn(y[i+1]));
}

// ---------------- all weights fp32 -> fp16 (one launch) --------------------
__global__ void wconv_all_kernel(const float* __restrict__ went,
                                 const float* __restrict__ w1,
                                 const float* __restrict__ w2) {
    int i = (blockIdx.x * blockDim.x + threadIdx.x) * 4;
    const int N0 = DOUT * DIN;
    const int N1 = N0 + DFF * DOUT;
    const int N2 = N1 + DOUT * DFF;
    if (i >= N2) return;
    const float* srcp;
    __half* dstp;
    int off;
    if (i < N0)      { srcp = went; dstp = g_went16; off = i; }
    else if (i < N1) { srcp = w1;   dstp = g_w116;   off = i - N0; }
    else             { srcp = w2;   dstp = g_w216;   off = i - N1; }
    float4 v = *(const float4*)(srcp + off);
    *(__half2*)(dstp + off)     = __halves2half2(__float2half_rn(v.x), __float2half_rn(v.y));
    *(__half2*)(dstp + off + 2) = __halves2half2(__float2half_rn(v.z), __float2half_rn(v.w));
}

// ---------------- fused edge softmax + hop 0 -------------------------------
// computes per-dst softmax weights (stores g_a for later hops) then hop-0 gather
__global__ void hop0s_kernel(const int* __restrict__ src) {
    int n = blockIdx.x;
    int t = threadIdx.x;                 // 0..127
    int j = t >> 3, h = t & 7;
    __shared__ int   ssrc[DEG];
    __shared__ float se[DEG][NH];
    __shared__ float sm[NH], ss[NH];
    __shared__ float aw[DEG * NH];
    if (t < DEG) ssrc[t] = src[(size_t)n * DEG + t];
    __syncthreads();
    int s = ssrc[j];
    float e = g_eh[(size_t)s * NH + h] + g_et[(size_t)n * NH + h];
    e = (e > 0.f) ? e : SLOPE * e;
    se[j][h] = e;
    __syncthreads();
    if (t < NH) {
        float m = -1e30f;
        #pragma unroll
        for (int jj = 0; jj < DEG; jj++) m = fmaxf(m, se[jj][t]);
        float sum = 0.f;
        #pragma unroll
        for (int jj = 0; jj < DEG; jj++) sum += __expf(se[jj][t] - m);
        sm[t] = m; ss[t] = sum;
    }
    __syncthreads();
    float a = __expf(se[j][h] - sm[h]) / ss[h];
    aw[t] = a;                            // t == j*NH + h
    g_a[(size_t)n * (DEG * NH) + t] = a;
    __syncthreads();

    // hop 0: feat0 -> fa
    int hh = t >> 4;
    const __half2* fin = (const __half2*)g_f016;
    float ax = 0.f, ay = 0.f;
    #pragma unroll
    for (int jj = 0; jj < DEG; jj++) {
        float2 f = __half22float2(fin[(size_t)ssrc[jj] * 128 + t]);
        float w = aw[jj * NH + hh];
        ax += w * f.x;
        ay += w * f.y;
    }
    float2 f0 = __half22float2(fin[(size_t)n * 128 + t]);
    float vx = (1.0f - ALPHA) * ax + ALPHA * f0.x;
    float vy = (1.0f - ALPHA) * ay + ALPHA * f0.y;
    ((__half2*)g_fa16)[(size_t)n * 128 + t] =
        __halves2half2(__float2half_rn(vx), __float2half_rn(vy));
}

// ---------------- hops 1..3, fp16 state ------------------------------------
__global__ void hop16_kernel(const int* __restrict__ src, int hop) {
    const __half2* fin;
    __half2* fout16;
    if      (hop == 1) { fin = (const __half2*)g_fa16; fout16 = (__half2*)g_fb16; }
    else if (hop == 2) { fin = (const __half2*)g_fb16; fout16 = (__half2*)g_fa16; }
    else               { fin = (const __half2*)g_fa16; fout16 = (__half2*)g_fb16; }

    int n = blockIdx.x;
    int t = threadIdx.x;
    __shared__ float aw[DEG * NH];
    __shared__ int   ssrc[DEG];
    aw[t] = g_a[(size_t)n * (DEG * NH) + t];
    if (t < DEG) ssrc[t] = src[(size_t)n * DEG + t];
    __syncthreads();

    int h = t >> 4;
    float ax = 0.f, ay = 0.f;
    #pragma unroll
    for (int j = 0; j < DEG; j++) {
        float2 f = __half22float2(fin[(size_t)ssrc[j] * 128 + t]);
        float w = aw[j * NH + h];
        ax += w * f.x;
        ay += w * f.y;
    }
    float2 f0 = __half22float2(((const __half2*)g_f016)[(size_t)n * 128 + t]);
    float vx = (1.0f - ALPHA) * ax + ALPHA * f0.x;
    float vy = (1.0f - ALPHA) * ay + ALPHA * f0.y;
    fout16[(size_t)n * 128 + t] = __halves2half2(__float2half_rn(vx), __float2half_rn(vy));
}

// ---------------- final hop + residual + fused LN2 -------------------------
__global__ void hoplast_kernel(const int* __restrict__ src,
                               const float* __restrict__ ln2_g,
                               const float* __restrict__ ln2_b) {
    int n = blockIdx.x;
    int t = threadIdx.x;
    int wid = t >> 5, lane = t & 31;
    __shared__ float aw[DEG * NH];
    __shared__ int   ssrc[DEG];
    __shared__ float wsum[4], wsq[4];
    aw[t] = g_a[(size_t)n * (DEG * NH) + t];
    if (t < DEG) ssrc[t] = src[(size_t)n * DEG + t];
    __syncthreads();

    int h = t >> 4;
    const __half2* fin = (const __half2*)g_fb16;
    float ax = 0.f, ay = 0.f;
    #pragma unroll
    for (int j = 0; j < DEG; j++) {
        float2 f = __half22float2(fin[(size_t)ssrc[j] * 128 + t]);
        float w = aw[j * NH + h];
        ax += w * f.x;
        ay += w * f.y;
    }
    float2 f0 = __half22float2(((const __half2*)g_f016)[(size_t)n * 128 + t]);
    float2 hh = *(const float2*)(g_h + (size_t)n * 256 + t * 2);
    float vx = (1.0f - ALPHA) * ax + ALPHA * f0.x + hh.x;
    float vy = (1.0f - ALPHA) * ay + ALPHA * f0.y + hh.y;
    *(float2*)(g_rst + (size_t)n * 256 + t * 2) = make_float2(vx, vy);

    float s  = vx + vy;
    float sq = vx * vx + vy * vy;
    #pragma unroll
    for (int o = 16; o > 0; o >>= 1) {
        s  += __shfl_xor_sync(0xffffffffu, s, o);
        sq += __shfl_xor_sync(0xffffffffu, sq, o);
    }
    if (lane == 0) { wsum[wid] = s; wsq[wid] = sq; }
    __syncthreads();
    s = wsum[0] + wsum[1] + wsum[2] + wsum[3];
    sq = wsq[0] + wsq[1] + wsq[2] + wsq[3];
    float mu  = s * (1.0f / 256.0f);
    float var = sq * (1.0f / 256.0f) - mu * mu;
    float rs  = rsqrtf(var + 1e-5f);
    float2 gg = *(const float2*)(ln2_g + t * 2);
    float2 bb = *(const float2*)(ln2_b + t * 2);
    float yx = (vx - mu) * rs * gg.x + bb.x;
    float yy = (vy - mu) * rs * gg.y + bb.y;
    ((__half2*)g_x16)[(size_t)n * 128 + t] =
        __halves2half2(__float2half_rn(yx), __float2half_rn(yy));
}

// ---------------------------------------------------------------------------
extern "C" void kernel_launch(void* const* d_in, const int* in_sizes, int n_in,
                              void* d_out, int out_size) {
    const float* ent_feat = (const float*)d_in[0];
    const float* W_ent    = (const float*)d_in[1];
    const float* attn_h   = (const float*)d_in[2];
    const float* attn_t   = (const float*)d_in[3];
    const float* ln1_g    = (const float*)d_in[4];
    const float* ln1_b    = (const float*)d_in[5];
    const float* ln2_g    = (const float*)d_in[6];
    const float* ln2_b    = (const float*)d_in[7];
    const float* W1       = (const float*)d_in[8];
    const float* b1       = (const float*)d_in[9];
    const float* W2       = (const float*)d_in[10];
    const float* b2       = (const float*)d_in[11];
    const int*   src      = (const int*)d_in[12];
    float*       out      = (float*)d_out;

    const int SMEM = 3 * 20480;   // 61440, 3-stage ring -> 2 CTAs/SM
    cudaFuncSetAttribute(gemm_mma<0>, cudaFuncAttributeMaxDynamicSharedMemorySize, SMEM);
    cudaFuncSetAttribute(gemm_mma<1>, cudaFuncAttributeMaxDynamicSharedMemorySize, SMEM);
    cudaFuncSetAttribute(gemm_mma<2>, cudaFuncAttributeMaxDynamicSharedMemorySize, SMEM);

    float *p_h, *p_rst;
    __half *p_h16, *p_f016, *p_x16, *p_t16, *p_went16, *p_w116, *p_w216;
    cudaGetSymbolAddress((void**)&p_h,      g_h);
    cudaGetSymbolAddress((void**)&p_rst,    g_rst);
    cudaGetSymbolAddress((void**)&p_h16,    g_h16);
    cudaGetSymbolAddress((void**)&p_f016,   g_f016);
    cudaGetSymbolAddress((void**)&p_x16,    g_x16);
    cudaGetSymbolAddress((void**)&p_t16,    g_t16);
    cudaGetSymbolAddress((void**)&p_went16, g_went16);
    cudaGetSymbolAddress((void**)&p_w116,   g_w116);
    cudaGetSymbolAddress((void**)&p_w216,   g_w216);

    // 1. all weights -> fp16
    wconv_all_kernel<<<(589824 / 4 + 255) / 256, 256>>>(W_ent, W1, W2);

    // 2. h = LN1(ent_feat)  (fp32 + fp16)
    ln256w_kernel<<<(NN + 7) / 8, 256>>>(ent_feat, ln1_g, ln1_b, p_h, p_h16);

    // 3. feat0 = h @ W_ent^T -> fp16, fused eh/et
    {
        dim3 grid(DOUT / 128, (NN + 127) / 128);
        gemm_mma<0><<<grid, 256, SMEM>>>(p_h16, p_went16, nullptr, nullptr,
                                         nullptr, p_f016, attn_h, attn_t,
                                         NN, DOUT, DIN);
    }

    // 4. fused softmax + hop0
    hop0s_kernel<<<NN, 128>>>(src);

    // 5-7. hops 1..3   [launch #6 = hop2 for ncu -s 5]
    for (int hop = 1; hop < HOPS - 1; hop++)
        hop16_kernel<<<NN, 128>>>(src, hop);

    // 8. final hop + residual + fused LN2
    hoplast_kernel<<<NN, 128>>>(src, ln2_g, ln2_b);

    // 9. t = relu(x @ W1^T + b1) -> fp16
    {
        dim3 grid(DFF / 128, (NN + 127) / 128);
        gemm_mma<1><<<grid, 256, SMEM>>>(p_x16, p_w116, b1, nullptr,
                                         nullptr, p_t16, nullptr, nullptr,
                                         NN, DFF, DOUT);
    }

    // 10. out = t @ W2^T + b2 + rst  (fp32)
    {
        dim3 grid(DOUT / 128, (NN + 127) / 128);
        gemm_mma<2><<<grid, 256, SMEM>>>(p_t16, p_w216, b2, p_rst,
                                         out, nullptr, nullptr, nullptr,
                                         NN, DOUT, DFF);
    }
}

// round 10
// speedup vs baseline: 4.4047x; 1.1541x over previous
#include <cuda_runtime.h>
#include <cuda_fp16.h>
#include <math.h>
#include <stdint.h>

// ---------------------------------------------------------------------------
// GDTEncoder: graph attention + PPR diffusion + FFN
// N=50000, DEG=16 (dst-contiguous), D_IN=D_OUT=256, H=8, HD=32, DFF=1024
// fp16 mma.sync GEMMs (3-stage cp.async), ehet fused into G1,
// scores fused into hop0, vectorized LDG.128 gathers for hops 1..4,
// LN2 fused (warp-local) into final hop.
// ---------------------------------------------------------------------------

#define NN     50000
#define DEG    16
#define EDGES  (NN * DEG)
#define DIN    256
#define NH     8
#define HD     32
#define DOUT   256
#define DFF    1024
#define HOPS   5
#define ALPHA  0.15f
#define SLOPE  0.2f

// ---------------- scratch (static device globals; no allocation) -----------
__device__ __align__(256) float g_h[(size_t)NN * DIN];      // LN1 out (fp32 residual)
__device__ __align__(256) float g_eh[(size_t)NN * NH];
__device__ __align__(256) float g_et[(size_t)NN * NH];
__device__ __align__(256) float g_a[(size_t)EDGES * NH];    // softmaxed edge weights
__device__ __align__(256) float g_rst[(size_t)NN * DOUT];   // feat after hops + h (fp32)

__device__ __align__(256) __half g_h16[(size_t)NN * DIN];    // LN1 out fp16 (G1 A)
__device__ __align__(256) __half g_f016[(size_t)NN * DOUT];  // feat0 fp16
__device__ __align__(256) __half g_fa16[(size_t)NN * DOUT];  // hop ping
__device__ __align__(256) __half g_fb16[(size_t)NN * DOUT];  // hop pong
__device__ __align__(256) __half g_x16[(size_t)NN * DOUT];   // LN2 out fp16
__device__ __align__(256) __half g_t16[(size_t)NN * DFF];    // FFN hidden fp16
__device__ __align__(256) __half g_went16[DOUT * DIN];
__device__ __align__(256) __half g_w116[DFF * DOUT];
__device__ __align__(256) __half g_w216[DOUT * DFF];

// ---------------- mma / cp.async helpers -----------------------------------
__device__ __forceinline__ void ldmat4(uint32_t& r0, uint32_t& r1,
                                       uint32_t& r2, uint32_t& r3,
                                       uint32_t addr) {
    asm volatile("ldmatrix.sync.aligned.m8n8.x4.shared.b16 {%0,%1,%2,%3}, [%4];"
                 : "=r"(r0), "=r"(r1), "=r"(r2), "=r"(r3) : "r"(addr));
}

__device__ __forceinline__ void mma_fp(float c[4],
                                       uint32_t a0, uint32_t a1, uint32_t a2, uint32_t a3,
                                       uint32_t b0, uint32_t b1) {
    asm volatile(
        "mma.sync.aligned.m16n8k16.row.col.f32.f16.f16.f32 "
        "{%0,%1,%2,%3}, {%4,%5,%6,%7}, {%8,%9}, {%0,%1,%2,%3};"
        : "+f"(c[0]), "+f"(c[1]), "+f"(c[2]), "+f"(c[3])
        : "r"(a0), "r"(a1), "r"(a2), "r"(a3), "r"(b0), "r"(b1));
}

__device__ __forceinline__ void cp16(uint32_t dst, const void* src, int sz) {
    asm volatile("cp.async.cg.shared.global [%0], [%1], 16, %2;\n"
                 :: "r"(dst), "l"(src), "r"(sz));
}
__device__ __forceinline__ void cp_commit() {
    asm volatile("cp.async.commit_group;\n" ::);
}
template <int N>
__device__ __forceinline__ void cp_waitg() {
    asm volatile("cp.async.wait_group %0;\n" :: "n"(N));
}

// ---------------- GEMM: C[M,N] = A[M,K] * B[N,K]^T, fp16 mma ---------------
// MODE 0: plain -> fp16 Ch + fused eh/et.  MODE 1: relu(acc+bias) -> fp16 Ch.
// MODE 2: acc+bias+resid -> fp32 C.
template <int MODE>
__global__ void __launch_bounds__(256, 2)
gemm_mma(const __half* __restrict__ A, const __half* __restrict__ B,
         const float* __restrict__ bias, const float* __restrict__ resid,
         float* __restrict__ C, __half* __restrict__ Ch,
         const float* __restrict__ attn_h, const float* __restrict__ attn_t,
         int M, int N, int K) {
    constexpr int BM = 128, BN = 128, BK = 32;
    constexpr int LDS = 40;
    constexpr int MAT = BM * LDS * 2;       // 10240 B
    constexpr int STAGE = 2 * MAT;          // 20480 B
    constexpr int STAGES = 3;

    extern __shared__ __align__(16) char dynsmem[];
    const uint32_t smem0 = (uint32_t)__cvta_generic_to_shared(dynsmem);

    const int tid  = threadIdx.x;
    const int m0   = blockIdx.y * BM;
    const int n0   = blockIdx.x * BN;
    const int wid  = tid >> 5;
    const int lane = tid & 31;
    const int wm   = (wid >> 2) * 64;
    const int wn   = (wid & 3) * 32;
    const int lg   = lane >> 3;
    const int lr   = lane & 7;

    const int lrow = tid >> 1;
    const int lc0  = (tid & 1) * 2;
    const bool arow_ok = (m0 + lrow) < M;
    const int  a_sz = arow_ok ? 16 : 0;
    const __half* pA = A + (size_t)(m0 + lrow) * K + lc0 * 8;
    const __half* pB = B + (size_t)(n0 + lrow) * K + lc0 * 8;
    const uint32_t soff = (uint32_t)(lrow * 80 + lc0 * 16);

    const int KT = K / BK;

    auto load_stage = [&](int kt, int s) {
        uint32_t sb = smem0 + s * STAGE + soff;
        int ko = kt * BK;
        cp16(sb,            pA + ko,     a_sz);
        cp16(sb + 16,       pA + ko + 8, a_sz);
        cp16(sb + MAT,      pB + ko,     16);
        cp16(sb + MAT + 16, pB + ko + 8, 16);
    };

    float acc[4][4][4];
    #pragma unroll
    for (int i = 0; i < 4; i++)
        #pragma unroll
        for (int j = 0; j < 4; j++)
            #pragma unroll
            for (int q = 0; q < 4; q++) acc[i][j][q] = 0.f;

    #pragma unroll
    for (int s = 0; s < STAGES - 1; s++) {
        load_stage(s, s);
        cp_commit();
    }

    int cslot = 0;
    int lslot = STAGES - 1;
    for (int kt = 0; kt < KT; kt++) {
        cp_waitg<STAGES - 2>();
        __syncthreads();

        int nk = kt + STAGES - 1;
        if (nk < KT) load_stage(nk, lslot);
        cp_commit();

        const uint32_t baseA = smem0 + cslot * STAGE;
        const uint32_t baseB = baseA + MAT;

        #pragma unroll
        for (int ks = 0; ks < 2; ks++) {
            const int kb = ks * 16;
            uint32_t bh[4][2];
            #pragma unroll
            for (int p = 0; p < 2; p++) {
                int row = wn + p * 16 + lr + (lg & 2) * 4;
                int kc  = kb + (lg & 1) * 8;
                uint32_t off = (uint32_t)(row * LDS + kc) * 2;
                ldmat4(bh[2*p][0], bh[2*p][1], bh[2*p+1][0], bh[2*p+1][1], baseB + off);
            }
            #pragma unroll
            for (int mi = 0; mi < 4; mi++) {
                int row = wm + mi * 16 + lr + (lg & 1) * 8;
                int kc  = kb + (lg & 2) * 4;
                uint32_t off = (uint32_t)(row * LDS + kc) * 2;
                uint32_t a0, a1, a2, a3;
                ldmat4(a0, a1, a2, a3, baseA + off);
                #pragma unroll
                for (int nj = 0; nj < 4; nj++)
                    mma_fp(acc[mi][nj], a0, a1, a2, a3, bh[nj][0], bh[nj][1]);
            }
        }
        cslot = (cslot + 1 == STAGES) ? 0 : cslot + 1;
        lslot = (lslot + 1 == STAGES) ? 0 : lslot + 1;
    }

    const int gr  = lane >> 2;
    const int gc2 = (lane & 3) * 2;

    float avh[8], avt[8];
    int hh = 0;
    if (MODE == 0) {
        hh = (n0 + wn) >> 5;
        #pragma unroll
        for (int nj = 0; nj < 4; nj++)
            #pragma unroll
            for (int q = 0; q < 2; q++) {
                int col = nj * 8 + gc2 + q;
                avh[nj * 2 + q] = attn_h[hh * HD + col];
                avt[nj * 2 + q] = attn_t[hh * HD + col];
            }
    }

    #pragma unroll
    for (int mi = 0; mi < 4; mi++) {
        #pragma unroll
        for (int half = 0; half < 2; half++) {
            int gm = m0 + wm + mi * 16 + gr + half * 8;
            if (gm >= M) continue;
            if (MODE == 0) {
                float seh = 0.f, set = 0.f;
                #pragma unroll
                for (int nj = 0; nj < 4; nj++) {
                    float v0 = acc[mi][nj][half * 2 + 0];
                    float v1 = acc[mi][nj][half * 2 + 1];
                    int gn = n0 + wn + nj * 8 + gc2;
                    *(__half2*)(Ch + (size_t)gm * N + gn) =
                        __halves2half2(__float2half_rn(v0), __float2half_rn(v1));
                    seh += v0 * avh[nj * 2] + v1 * avh[nj * 2 + 1];
                    set += v0 * avt[nj * 2] + v1 * avt[nj * 2 + 1];
                }
                seh += __shfl_xor_sync(0xffffffffu, seh, 1);
                set += __shfl_xor_sync(0xffffffffu, set, 1);
                seh += __shfl_xor_sync(0xffffffffu, seh, 2);
                set += __shfl_xor_sync(0xffffffffu, set, 2);
                if ((lane & 3) == 0) {
                    g_eh[(size_t)gm * NH + hh] = seh;
                    g_et[(size_t)gm * NH + hh] = set;
                }
            } else {
                #pragma unroll
                for (int nj = 0; nj < 4; nj++) {
                    int gn = n0 + wn + nj * 8 + gc2;
                    float v0 = acc[mi][nj][half * 2 + 0];
                    float v1 = acc[mi][nj][half * 2 + 1];
                    if (MODE == 1) {
                        v0 = fmaxf(v0 + bias[gn], 0.f);
                        v1 = fmaxf(v1 + bias[gn + 1], 0.f);
                        *(__half2*)(Ch + (size_t)gm * N + gn) =
                            __halves2half2(__float2half_rn(v0), __float2half_rn(v1));
                    } else {
                        const float* rr = resid + (size_t)gm * N + gn;
                        v0 += bias[gn]     + rr[0];
                        v1 += bias[gn + 1] + rr[1];
                        *(float2*)(C + (size_t)gm * N + gn) = make_float2(v0, v1);
                    }
                }
            }
        }
    }
}

// ---------------- LayerNorm, warp per row (LN1) -----------------------------
__global__ void ln256w_kernel(const float* __restrict__ in,
                              const float* __restrict__ g,
                              const float* __restrict__ b,
                              float* __restrict__ out_f32,
                              __half* __restrict__ out_16) {
    int row  = blockIdx.x * 8 + (threadIdx.x >> 5);
    int lane = threadIdx.x & 31;
    if (row >= NN) return;
    const float* rp = in + (size_t)row * 256;
    float4 v0 = *(const float4*)(rp + lane * 8);
    float4 v1 = *(const float4*)(rp + lane * 8 + 4);
    float s  = v0.x + v0.y + v0.z + v0.w + v1.x + v1.y + v1.z + v1.w;
    float sq = v0.x*v0.x + v0.y*v0.y + v0.z*v0.z + v0.w*v0.w
             + v1.x*v1.x + v1.y*v1.y + v1.z*v1.z + v1.w*v1.w;
    #pragma unroll
    for (int o = 16; o > 0; o >>= 1) {
        s  += __shfl_xor_sync(0xffffffffu, s, o);
        sq += __shfl_xor_sync(0xffffffffu, sq, o);
    }
    float mu  = s * (1.0f / 256.0f);
    float var = sq * (1.0f / 256.0f) - mu * mu;
    float rs  = rsqrtf(var + 1e-5f);
    float4 g0 = *(const float4*)(g + lane * 8);
    float4 g1 = *(const float4*)(g + lane * 8 + 4);
    float4 b0 = *(const float4*)(b + lane * 8);
    float4 b1 = *(const float4*)(b + lane * 8 + 4);
    float y[8];
    y[0] = (v0.x - mu) * rs * g0.x + b0.x;
    y[1] = (v0.y - mu) * rs * g0.y + b0.y;
    y[2] = (v0.z - mu) * rs * g0.z + b0.z;
    y[3] = (v0.w - mu) * rs * g0.w + b0.w;
    y[4] = (v1.x - mu) * rs * g1.x + b1.x;
    y[5] = (v1.y - mu) * rs * g1.y + b1.y;
    y[6] = (v1.z - mu) * rs * g1.z + b1.z;
    y[7] = (v1.w - mu) * rs * g1.w + b1.w;
    size_t o8 = (size_t)row * 256 + lane * 8;
    *(float4*)(out_f32 + o8)     = make_float4(y[0], y[1], y[2], y[3]);
    *(float4*)(out_f32 + o8 + 4) = make_float4(y[4], y[5], y[6], y[7]);
    #pragma unroll
    for (int i = 0; i < 8; i += 2)
        *(__half2*)(out_16 + o8 + i) =
            __halves2half2(__float2half_rn(y[i]), __float2half_rn(y[i+1]));
}

// ---------------- all weights fp32 -> fp16 (one launch) --------------------
__global__ void wconv_all_kernel(const float* __restrict__ went,
                                 const float* __restrict__ w1,
                                 const float* __restrict__ w2) {
    int i = (blockIdx.x * blockDim.x + threadIdx.x) * 4;
    const int N0 = DOUT * DIN;
    const int N1 = N0 + DFF * DOUT;
    const int N2 = N1 + DOUT * DFF;
    if (i >= N2) return;
    const float* srcp;
    __half* dstp;
    int off;
    if (i < N0)      { srcp = went; dstp = g_went16; off = i; }
    else if (i < N1) { srcp = w1;   dstp = g_w116;   off = i - N0; }
    else             { srcp = w2;   dstp = g_w216;   off = i - N1; }
    float4 v = *(const float4*)(srcp + off);
    *(__half2*)(dstp + off)     = __halves2half2(__float2half_rn(v.x), __float2half_rn(v.y));
    *(__half2*)(dstp + off + 2) = __halves2half2(__float2half_rn(v.z), __float2half_rn(v.w));
}

// ---------------- fused edge softmax + hop 0 -------------------------------
__global__ void hop0s_kernel(const int* __restrict__ src) {
    int n = blockIdx.x;
    int t = threadIdx.x;
    int j = t >> 3, h = t & 7;
    __shared__ int   ssrc[DEG];
    __shared__ float se[DEG][NH];
    __shared__ float sm[NH], ss[NH];
    __shared__ float aw[DEG * NH];
    if (t < DEG) ssrc[t] = src[(size_t)n * DEG + t];
    __syncthreads();
    int s = ssrc[j];
    float e = g_eh[(size_t)s * NH + h] + g_et[(size_t)n * NH + h];
    e = (e > 0.f) ? e : SLOPE * e;
    se[j][h] = e;
    __syncthreads();
    if (t < NH) {
        float m = -1e30f;
        #pragma unroll
        for (int jj = 0; jj < DEG; jj++) m = fmaxf(m, se[jj][t]);
        float sum = 0.f;
        #pragma unroll
        for (int jj = 0; jj < DEG; jj++) sum += __expf(se[jj][t] - m);
        sm[t] = m; ss[t] = sum;
    }
    __syncthreads();
    float a = __expf(se[j][h] - sm[h]) / ss[h];
    aw[t] = a;
    g_a[(size_t)n * (DEG * NH) + t] = a;
    __syncthreads();

    int hh = t >> 4;
    const __half2* fin = (const __half2*)g_f016;
    float ax = 0.f, ay = 0.f;
    #pragma unroll
    for (int jj = 0; jj < DEG; jj++) {
        float2 f = __half22float2(fin[(size_t)ssrc[jj] * 128 + t]);
        float w = aw[jj * NH + hh];
        ax += w * f.x;
        ay += w * f.y;
    }
    float2 f0 = __half22float2(fin[(size_t)n * 128 + t]);
    float vx = (1.0f - ALPHA) * ax + ALPHA * f0.x;
    float vy = (1.0f - ALPHA) * ay + ALPHA * f0.y;
    ((__half2*)g_fa16)[(size_t)n * 128 + t] =
        __halves2half2(__float2half_rn(vx), __float2half_rn(vy));
}

// ---------------- vectorized hop smem staging ------------------------------
// block = 256 threads = 8 nodes; thread: nn = t>>5 node, tl = t&31 lane.
// Each lane owns 8 channels (one float4 of half2s) -> one LDG.128 per neighbor.
__device__ __forceinline__ void hop_stage(const int* __restrict__ src, int b,
                                          float (&aw)[8][128], int (&soff)[8][16]) {
    int t = threadIdx.x;
    float4 v = ((const float4*)g_a)[(size_t)b * 256 + t];
    *(float4*)&aw[t >> 5][(t & 31) * 4] = v;
    if (t < 128)
        soff[t >> 4][t & 15] = src[(size_t)b * 128 + t] * 32;  // float4 row offset
    __syncthreads();
}

// ---------------- hops 1..3, vectorized ------------------------------------
__global__ void __launch_bounds__(256)
hop16v_kernel(const int* __restrict__ src, int hop) {
    const float4* fin;
    float4* fout;
    if      (hop == 1) { fin = (const float4*)g_fa16; fout = (float4*)g_fb16; }
    else if (hop == 2) { fin = (const float4*)g_fb16; fout = (float4*)g_fa16; }
    else               { fin = (const float4*)g_fa16; fout = (float4*)g_fb16; }

    int b = blockIdx.x;
    int t = threadIdx.x;
    int nn = t >> 5, tl = t & 31;
    int n = b * 8 + nn;

    __shared__ float aw[8][128];
    __shared__ int   soff[8][16];
    hop_stage(src, b, aw, soff);

    int hh = tl >> 2;                      // head of this lane's 8 channels
    float w[16];
    int   off[16];
    #pragma unroll
    for (int j = 0; j < 16; j++) {
        w[j]   = aw[nn][j * 8 + hh];
        off[j] = soff[nn][j];
    }

    float acc[8];
    #pragma unroll
    for (int q = 0; q < 8; q++) acc[q] = 0.f;

    #pragma unroll
    for (int j = 0; j < 16; j++) {
        float4 v = fin[(size_t)off[j] + tl];
        const __half2* hp = (const __half2*)&v;
        #pragma unroll
        for (int q = 0; q < 4; q++) {
            float2 f = __half22float2(hp[q]);
            acc[q * 2]     += w[j] * f.x;
            acc[q * 2 + 1] += w[j] * f.y;
        }
    }

    float4 f0v = ((const float4*)g_f016)[(size_t)n * 32 + tl];
    const __half2* f0p = (const __half2*)&f0v;
    __half2 oh[4];
    #pragma unroll
    for (int q = 0; q < 4; q++) {
        float2 f = __half22float2(f0p[q]);
        float vx = (1.0f - ALPHA) * acc[q * 2]     + ALPHA * f.x;
        float vy = (1.0f - ALPHA) * acc[q * 2 + 1] + ALPHA * f.y;
        oh[q] = __floats2half2_rn(vx, vy);
    }
    fout[(size_t)n * 32 + tl] = *(float4*)oh;
}

// ---------------- final hop + residual + warp-local LN2 --------------------
__global__ void __launch_bounds__(256)
hoplastv_kernel(const int* __restrict__ src,
                const float* __restrict__ ln2_g,
                const float* __restrict__ ln2_b) {
    int b = blockIdx.x;
    int t = threadIdx.x;
    int nn = t >> 5, tl = t & 31;
    int n = b * 8 + nn;

    __shared__ float aw[8][128];
    __shared__ int   soff[8][16];
    hop_stage(src, b, aw, soff);

    int hh = tl >> 2;
    float w[16];
    int   off[16];
    #pragma unroll
    for (int j = 0; j < 16; j++) {
        w[j]   = aw[nn][j * 8 + hh];
        off[j] = soff[nn][j];
    }

    const float4* fin = (const float4*)g_fb16;
    float acc[8];
    #pragma unroll
    for (int q = 0; q < 8; q++) acc[q] = 0.f;

    #pragma unroll
    for (int j = 0; j < 16; j++) {
        float4 v = fin[(size_t)off[j] + tl];
        const __half2* hp = (const __half2*)&v;
        #pragma unroll
        for (int q = 0; q < 4; q++) {
            float2 f = __half22float2(hp[q]);
            acc[q * 2]     += w[j] * f.x;
            acc[q * 2 + 1] += w[j] * f.y;
        }
    }

    float4 f0v = ((const float4*)g_f016)[(size_t)n * 32 + tl];
    const __half2* f0p = (const __half2*)&f0v;
    float4 h0 = ((const float4*)g_h)[(size_t)n * 64 + tl * 2];
    float4 h1 = ((const float4*)g_h)[(size_t)n * 64 + tl * 2 + 1];
    const float* hs = (const float*)&h0;   // h0,h1 contiguous channels 0..7? no:
    // channels: h0 = ch[8tl..8tl+3], h1 = ch[8tl+4..8tl+7]
    float v[8];
    {
        float2 f;
        f = __half22float2(f0p[0]);
        v[0] = (1.0f - ALPHA) * acc[0] + ALPHA * f.x + h0.x;
        v[1] = (1.0f - ALPHA) * acc[1] + ALPHA * f.y + h0.y;
        f = __half22float2(f0p[1]);
        v[2] = (1.0f - ALPHA) * acc[2] + ALPHA * f.x + h0.z;
        v[3] = (1.0f - ALPHA) * acc[3] + ALPHA * f.y + h0.w;
        f = __half22float2(f0p[2]);
        v[4] = (1.0f - ALPHA) * acc[4] + ALPHA * f.x + h1.x;
        v[5] = (1.0f - ALPHA) * acc[5] + ALPHA * f.y + h1.y;
        f = __half22float2(f0p[3]);
        v[6] = (1.0f - ALPHA) * acc[6] + ALPHA * f.x + h1.z;
        v[7] = (1.0f - ALPHA) * acc[7] + ALPHA * f.y + h1.w;
    }
    (void)hs;
    ((float4*)g_rst)[(size_t)n * 64 + tl * 2]     = make_float4(v[0], v[1], v[2], v[3]);
    ((float4*)g_rst)[(size_t)n * 64 + tl * 2 + 1] = make_float4(v[4], v[5], v[6], v[7]);

    // warp-local LN2 (each warp = one node)
    float s = 0.f, sq = 0.f;
    #pragma unroll
    for (int q = 0; q < 8; q++) { s += v[q]; sq += v[q] * v[q]; }
    #pragma unroll
    for (int o = 16; o > 0; o >>= 1) {
        s  += __shfl_xor_sync(0xffffffffu, s, o);
        sq += __shfl_xor_sync(0xffffffffu, sq, o);
    }
    float mu  = s * (1.0f / 256.0f);
    float var = sq * (1.0f / 256.0f) - mu * mu;
    float rs  = rsqrtf(var + 1e-5f);

    float4 g0 = *(const float4*)(ln2_g + tl * 8);
    float4 g1 = *(const float4*)(ln2_g + tl * 8 + 4);
    float4 b0 = *(const float4*)(ln2_b + tl * 8);
    float4 b1 = *(const float4*)(ln2_b + tl * 8 + 4);
    float y[8];
    y[0] = (v[0] - mu) * rs * g0.x + b0.x;
    y[1] = (v[1] - mu) * rs * g0.y + b0.y;
    y[2] = (v[2] - mu) * rs * g0.z + b0.z;
    y[3] = (v[3] - mu) * rs * g0.w + b0.w;
    y[4] = (v[4] - mu) * rs * g1.x + b1.x;
    y[5] = (v[5] - mu) * rs * g1.y + b1.y;
    y[6] = (v[6] - mu) * rs * g1.z + b1.z;
    y[7] = (v[7] - mu) * rs * g1.w + b1.w;
    __half2 oh[4];
    #pragma unroll
    for (int q = 0; q < 4; q++)
        oh[q] = __floats2half2_rn(y[q * 2], y[q * 2 + 1]);
    ((float4*)g_x16)[(size_t)n * 32 + tl] = *(float4*)oh;
}

// ---------------------------------------------------------------------------
extern "C" void kernel_launch(void* const* d_in, const int* in_sizes, int n_in,
                              void* d_out, int out_size) {
    const float* ent_feat = (const float*)d_in[0];
    const float* W_ent    = (const float*)d_in[1];
    const float* attn_h   = (const float*)d_in[2];
    const float* attn_t   = (const float*)d_in[3];
    const float* ln1_g    = (const float*)d_in[4];
    const float* ln1_b    = (const float*)d_in[5];
    const float* ln2_g    = (const float*)d_in[6];
    const float* ln2_b    = (const float*)d_in[7];
    const float* W1       = (const float*)d_in[8];
    const float* b1       = (const float*)d_in[9];
    const float* W2       = (const float*)d_in[10];
    const float* b2       = (const float*)d_in[11];
    const int*   src      = (const int*)d_in[12];
    float*       out      = (float*)d_out;

    const int SMEM = 3 * 20480;
    cudaFuncSetAttribute(gemm_mma<0>, cudaFuncAttributeMaxDynamicSharedMemorySize, SMEM);
    cudaFuncSetAttribute(gemm_mma<1>, cudaFuncAttributeMaxDynamicSharedMemorySize, SMEM);
    cudaFuncSetAttribute(gemm_mma<2>, cudaFuncAttributeMaxDynamicSharedMemorySize, SMEM);

    float *p_h, *p_rst;
    __half *p_h16, *p_f016, *p_x16, *p_t16, *p_went16, *p_w116, *p_w216;
    cudaGetSymbolAddress((void**)&p_h,      g_h);
    cudaGetSymbolAddress((void**)&p_rst,    g_rst);
    cudaGetSymbolAddress((void**)&p_h16,    g_h16);
    cudaGetSymbolAddress((void**)&p_f016,   g_f016);
    cudaGetSymbolAddress((void**)&p_x16,    g_x16);
    cudaGetSymbolAddress((void**)&p_t16,    g_t16);
    cudaGetSymbolAddress((void**)&p_went16, g_went16);
    cudaGetSymbolAddress((void**)&p_w116,   g_w116);
    cudaGetSymbolAddress((void**)&p_w216,   g_w216);

    // 1. all weights -> fp16
    wconv_all_kernel<<<(589824 / 4 + 255) / 256, 256>>>(W_ent, W1, W2);

    // 2. h = LN1(ent_feat)  (fp32 + fp16)
    ln256w_kernel<<<(NN + 7) / 8, 256>>>(ent_feat, ln1_g, ln1_b, p_h, p_h16);

    // 3. feat0 = h @ W_ent^T -> fp16, fused eh/et
    {
        dim3 grid(DOUT / 128, (NN + 127) / 128);
        gemm_mma<0><<<grid, 256, SMEM>>>(p_h16, p_went16, nullptr, nullptr,
                                         nullptr, p_f016, attn_h, attn_t,
                                         NN, DOUT, DIN);
    }

    // 4. fused softmax + hop0
    hop0s_kernel<<<NN, 128>>>(src);

    // 5-7. hops 1..3 vectorized  [launch #6 = hop2 for ncu -s 5]
    for (int hop = 1; hop < HOPS - 1; hop++)
        hop16v_kernel<<<NN / 8, 256>>>(src, hop);

    // 8. final hop + residual + warp-local LN2
    hoplastv_kernel<<<NN / 8, 256>>>(src, ln2_g, ln2_b);

    // 9. t = relu(x @ W1^T + b1) -> fp16
    {
        dim3 grid(DFF / 128, (NN + 127) / 128);
        gemm_mma<1><<<grid, 256, SMEM>>>(p_x16, p_w116, b1, nullptr,
                                         nullptr, p_t16, nullptr, nullptr,
                                         NN, DFF, DOUT);
    }

    // 10. out = t @ W2^T + b2 + rst  (fp32)
    {
        dim3 grid(DOUT / 128, (NN + 127) / 128);
        gemm_mma<2><<<grid, 256, SMEM>>>(p_t16, p_w216, b2, p_rst,
                                         out, nullptr, nullptr, nullptr,
                                         NN, DOUT, DFF);
    }
}

// round 11
// speedup vs baseline: 4.5981x; 1.0439x over previous
#include <cuda_runtime.h>
#include <cuda_fp16.h>
#include <math.h>
#include <stdint.h>

// ---------------------------------------------------------------------------
// GDTEncoder: graph attention + PPR diffusion + FFN
// N=50000, DEG=16 (dst-contiguous), D_IN=D_OUT=256, H=8, HD=32, DFF=1024
// fp16 mma.sync GEMMs (3-stage cp.async), ehet fused into G1,
// softmax+hop0 fused AND vectorized, LDG.128 gathers for all hops,
// LN2 fused (warp-local) into final hop.
// ---------------------------------------------------------------------------

#define NN     50000
#define DEG    16
#define EDGES  (NN * DEG)
#define DIN    256
#define NH     8
#define HD     32
#define DOUT   256
#define DFF    1024
#define HOPS   5
#define ALPHA  0.15f
#define SLOPE  0.2f

// ---------------- scratch (static device globals; no allocation) -----------
__device__ __align__(256) float g_h[(size_t)NN * DIN];      // LN1 out (fp32 residual)
__device__ __align__(256) float g_eh[(size_t)NN * NH];
__device__ __align__(256) float g_et[(size_t)NN * NH];
__device__ __align__(256) float g_a[(size_t)EDGES * NH];    // softmaxed edge weights
__device__ __align__(256) float g_rst[(size_t)NN * DOUT];   // feat after hops + h (fp32)

__device__ __align__(256) __half g_h16[(size_t)NN * DIN];    // LN1 out fp16 (G1 A)
__device__ __align__(256) __half g_f016[(size_t)NN * DOUT];  // feat0 fp16
__device__ __align__(256) __half g_fa16[(size_t)NN * DOUT];  // hop ping
__device__ __align__(256) __half g_fb16[(size_t)NN * DOUT];  // hop pong
__device__ __align__(256) __half g_x16[(size_t)NN * DOUT];   // LN2 out fp16
__device__ __align__(256) __half g_t16[(size_t)NN * DFF];    // FFN hidden fp16
__device__ __align__(256) __half g_went16[DOUT * DIN];
__device__ __align__(256) __half g_w116[DFF * DOUT];
__device__ __align__(256) __half g_w216[DOUT * DFF];

// ---------------- mma / cp.async helpers -----------------------------------
__device__ __forceinline__ void ldmat4(uint32_t& r0, uint32_t& r1,
                                       uint32_t& r2, uint32_t& r3,
                                       uint32_t addr) {
    asm volatile("ldmatrix.sync.aligned.m8n8.x4.shared.b16 {%0,%1,%2,%3}, [%4];"
                 : "=r"(r0), "=r"(r1), "=r"(r2), "=r"(r3) : "r"(addr));
}

__device__ __forceinline__ void mma_fp(float c[4],
                                       uint32_t a0, uint32_t a1, uint32_t a2, uint32_t a3,
                                       uint32_t b0, uint32_t b1) {
    asm volatile(
        "mma.sync.aligned.m16n8k16.row.col.f32.f16.f16.f32 "
        "{%0,%1,%2,%3}, {%4,%5,%6,%7}, {%8,%9}, {%0,%1,%2,%3};"
        : "+f"(c[0]), "+f"(c[1]), "+f"(c[2]), "+f"(c[3])
        : "r"(a0), "r"(a1), "r"(a2), "r"(a3), "r"(b0), "r"(b1));
}

__device__ __forceinline__ void cp16(uint32_t dst, const void* src, int sz) {
    asm volatile("cp.async.cg.shared.global [%0], [%1], 16, %2;\n"
                 :: "r"(dst), "l"(src), "r"(sz));
}
__device__ __forceinline__ void cp_commit() {
    asm volatile("cp.async.commit_group;\n" ::);
}
template <int N>
__device__ __forceinline__ void cp_waitg() {
    asm volatile("cp.async.wait_group %0;\n" :: "n"(N));
}

// ---------------- GEMM: C[M,N] = A[M,K] * B[N,K]^T, fp16 mma ---------------
// MODE 0: plain -> fp16 Ch + fused eh/et.  MODE 1: relu(acc+bias) -> fp16 Ch.
// MODE 2: acc+bias+resid -> fp32 C.
template <int MODE>
__global__ void __launch_bounds__(256, 2)
gemm_mma(const __half* __restrict__ A, const __half* __restrict__ B,
         const float* __restrict__ bias, const float* __restrict__ resid,
         float* __restrict__ C, __half* __restrict__ Ch,
         const float* __restrict__ attn_h, const float* __restrict__ attn_t,
         int M, int N, int K) {
    constexpr int BM = 128, BN = 128, BK = 32;
    constexpr int LDS = 40;
    constexpr int MAT = BM * LDS * 2;       // 10240 B
    constexpr int STAGE = 2 * MAT;          // 20480 B
    constexpr int STAGES = 3;

    extern __shared__ __align__(16) char dynsmem[];
    const uint32_t smem0 = (uint32_t)__cvta_generic_to_shared(dynsmem);

    const int tid  = threadIdx.x;
    const int m0   = blockIdx.y * BM;
    const int n0   = blockIdx.x * BN;
    const int wid  = tid >> 5;
    const int lane = tid & 31;
    const int wm   = (wid >> 2) * 64;
    const int wn   = (wid & 3) * 32;
    const int lg   = lane >> 3;
    const int lr   = lane & 7;

    const int lrow = tid >> 1;
    const int lc0  = (tid & 1) * 2;
    const bool arow_ok = (m0 + lrow) < M;
    const int  a_sz = arow_ok ? 16 : 0;
    const __half* pA = A + (size_t)(m0 + lrow) * K + lc0 * 8;
    const __half* pB = B + (size_t)(n0 + lrow) * K + lc0 * 8;
    const uint32_t soff = (uint32_t)(lrow * 80 + lc0 * 16);

    const int KT = K / BK;

    auto load_stage = [&](int kt, int s) {
        uint32_t sb = smem0 + s * STAGE + soff;
        int ko = kt * BK;
        cp16(sb,            pA + ko,     a_sz);
        cp16(sb + 16,       pA + ko + 8, a_sz);
        cp16(sb + MAT,      pB + ko,     16);
        cp16(sb + MAT + 16, pB + ko + 8, 16);
    };

    float acc[4][4][4];
    #pragma unroll
    for (int i = 0; i < 4; i++)
        #pragma unroll
        for (int j = 0; j < 4; j++)
            #pragma unroll
            for (int q = 0; q < 4; q++) acc[i][j][q] = 0.f;

    #pragma unroll
    for (int s = 0; s < STAGES - 1; s++) {
        load_stage(s, s);
        cp_commit();
    }

    int cslot = 0;
    int lslot = STAGES - 1;
    for (int kt = 0; kt < KT; kt++) {
        cp_waitg<STAGES - 2>();
        __syncthreads();

        int nk = kt + STAGES - 1;
        if (nk < KT) load_stage(nk, lslot);
        cp_commit();

        const uint32_t baseA = smem0 + cslot * STAGE;
        const uint32_t baseB = baseA + MAT;

        #pragma unroll
        for (int ks = 0; ks < 2; ks++) {
            const int kb = ks * 16;
            uint32_t bh[4][2];
            #pragma unroll
            for (int p = 0; p < 2; p++) {
                int row = wn + p * 16 + lr + (lg & 2) * 4;
                int kc  = kb + (lg & 1) * 8;
                uint32_t off = (uint32_t)(row * LDS + kc) * 2;
                ldmat4(bh[2*p][0], bh[2*p][1], bh[2*p+1][0], bh[2*p+1][1], baseB + off);
            }
            #pragma unroll
            for (int mi = 0; mi < 4; mi++) {
                int row = wm + mi * 16 + lr + (lg & 1) * 8;
                int kc  = kb + (lg & 2) * 4;
                uint32_t off = (uint32_t)(row * LDS + kc) * 2;
                uint32_t a0, a1, a2, a3;
                ldmat4(a0, a1, a2, a3, baseA + off);
                #pragma unroll
                for (int nj = 0; nj < 4; nj++)
                    mma_fp(acc[mi][nj], a0, a1, a2, a3, bh[nj][0], bh[nj][1]);
            }
        }
        cslot = (cslot + 1 == STAGES) ? 0 : cslot + 1;
        lslot = (lslot + 1 == STAGES) ? 0 : lslot + 1;
    }

    const int gr  = lane >> 2;
    const int gc2 = (lane & 3) * 2;

    float avh[8], avt[8];
    int hh = 0;
    if (MODE == 0) {
        hh = (n0 + wn) >> 5;
        #pragma unroll
        for (int nj = 0; nj < 4; nj++)
            #pragma unroll
            for (int q = 0; q < 2; q++) {
                int col = nj * 8 + gc2 + q;
                avh[nj * 2 + q] = attn_h[hh * HD + col];
                avt[nj * 2 + q] = attn_t[hh * HD + col];
            }
    }

    #pragma unroll
    for (int mi = 0; mi < 4; mi++) {
        #pragma unroll
        for (int half = 0; half < 2; half++) {
            int gm = m0 + wm + mi * 16 + gr + half * 8;
            if (gm >= M) continue;
            if (MODE == 0) {
                float seh = 0.f, set = 0.f;
                #pragma unroll
                for (int nj = 0; nj < 4; nj++) {
                    float v0 = acc[mi][nj][half * 2 + 0];
                    float v1 = acc[mi][nj][half * 2 + 1];
                    int gn = n0 + wn + nj * 8 + gc2;
                    *(__half2*)(Ch + (size_t)gm * N + gn) =
                        __halves2half2(__float2half_rn(v0), __float2half_rn(v1));
                    seh += v0 * avh[nj * 2] + v1 * avh[nj * 2 + 1];
                    set += v0 * avt[nj * 2] + v1 * avt[nj * 2 + 1];
                }
                seh += __shfl_xor_sync(0xffffffffu, seh, 1);
                set += __shfl_xor_sync(0xffffffffu, set, 1);
                seh += __shfl_xor_sync(0xffffffffu, seh, 2);
                set += __shfl_xor_sync(0xffffffffu, set, 2);
                if ((lane & 3) == 0) {
                    g_eh[(size_t)gm * NH + hh] = seh;
                    g_et[(size_t)gm * NH + hh] = set;
                }
            } else {
                #pragma unroll
                for (int nj = 0; nj < 4; nj++) {
                    int gn = n0 + wn + nj * 8 + gc2;
                    float v0 = acc[mi][nj][half * 2 + 0];
                    float v1 = acc[mi][nj][half * 2 + 1];
                    if (MODE == 1) {
                        v0 = fmaxf(v0 + bias[gn], 0.f);
                        v1 = fmaxf(v1 + bias[gn + 1], 0.f);
                        *(__half2*)(Ch + (size_t)gm * N + gn) =
                            __halves2half2(__float2half_rn(v0), __float2half_rn(v1));
                    } else {
                        const float* rr = resid + (size_t)gm * N + gn;
                        v0 += bias[gn]     + rr[0];
                        v1 += bias[gn + 1] + rr[1];
                        *(float2*)(C + (size_t)gm * N + gn) = make_float2(v0, v1);
                    }
                }
            }
        }
    }
}

// ---------------- LayerNorm, warp per row (LN1) -----------------------------
__global__ void ln256w_kernel(const float* __restrict__ in,
                              const float* __restrict__ g,
                              const float* __restrict__ b,
                              float* __restrict__ out_f32,
                              __half* __restrict__ out_16) {
    int row  = blockIdx.x * 8 + (threadIdx.x >> 5);
    int lane = threadIdx.x & 31;
    if (row >= NN) return;
    const float* rp = in + (size_t)row * 256;
    float4 v0 = *(const float4*)(rp + lane * 8);
    float4 v1 = *(const float4*)(rp + lane * 8 + 4);
    float s  = v0.x + v0.y + v0.z + v0.w + v1.x + v1.y + v1.z + v1.w;
    float sq = v0.x*v0.x + v0.y*v0.y + v0.z*v0.z + v0.w*v0.w
             + v1.x*v1.x + v1.y*v1.y + v1.z*v1.z + v1.w*v1.w;
    #pragma unroll
    for (int o = 16; o > 0; o >>= 1) {
        s  += __shfl_xor_sync(0xffffffffu, s, o);
        sq += __shfl_xor_sync(0xffffffffu, sq, o);
    }
    float mu  = s * (1.0f / 256.0f);
    float var = sq * (1.0f / 256.0f) - mu * mu;
    float rs  = rsqrtf(var + 1e-5f);
    float4 g0 = *(const float4*)(g + lane * 8);
    float4 g1 = *(const float4*)(g + lane * 8 + 4);
    float4 b0 = *(const float4*)(b + lane * 8);
    float4 b1 = *(const float4*)(b + lane * 8 + 4);
    float y[8];
    y[0] = (v0.x - mu) * rs * g0.x + b0.x;
    y[1] = (v0.y - mu) * rs * g0.y + b0.y;
    y[2] = (v0.z - mu) * rs * g0.z + b0.z;
    y[3] = (v0.w - mu) * rs * g0.w + b0.w;
    y[4] = (v1.x - mu) * rs * g1.x + b1.x;
    y[5] = (v1.y - mu) * rs * g1.y + b1.y;
    y[6] = (v1.z - mu) * rs * g1.z + b1.z;
    y[7] = (v1.w - mu) * rs * g1.w + b1.w;
    size_t o8 = (size_t)row * 256 + lane * 8;
    *(float4*)(out_f32 + o8)     = make_float4(y[0], y[1], y[2], y[3]);
    *(float4*)(out_f32 + o8 + 4) = make_float4(y[4], y[5], y[6], y[7]);
    #pragma unroll
    for (int i = 0; i < 8; i += 2)
        *(__half2*)(out_16 + o8 + i) =
            __halves2half2(__float2half_rn(y[i]), __float2half_rn(y[i+1]));
}

// ---------------- all weights fp32 -> fp16 (one launch) --------------------
__global__ void wconv_all_kernel(const float* __restrict__ went,
                                 const float* __restrict__ w1,
                                 const float* __restrict__ w2) {
    int i = (blockIdx.x * blockDim.x + threadIdx.x) * 4;
    const int N0 = DOUT * DIN;
    const int N1 = N0 + DFF * DOUT;
    const int N2 = N1 + DOUT * DFF;
    if (i >= N2) return;
    const float* srcp;
    __half* dstp;
    int off;
    if (i < N0)      { srcp = went; dstp = g_went16; off = i; }
    else if (i < N1) { srcp = w1;   dstp = g_w116;   off = i - N0; }
    else             { srcp = w2;   dstp = g_w216;   off = i - N1; }
    float4 v = *(const float4*)(srcp + off);
    *(__half2*)(dstp + off)     = __halves2half2(__float2half_rn(v.x), __float2half_rn(v.y));
    *(__half2*)(dstp + off + 2) = __halves2half2(__float2half_rn(v.z), __float2half_rn(v.w));
}

// ---------------- fused softmax + hop0, vectorized (8 nodes/block) ---------
__global__ void __launch_bounds__(256)
hop0v_kernel(const int* __restrict__ src) {
    int b = blockIdx.x;
    int t = threadIdx.x;
    int nn = t >> 5, tl = t & 31;
    int n = b * 8 + nn;

    __shared__ int   sraw[8][16];
    __shared__ float se[8][128];     // (edge j, head h) scores, idx = j*8+h
    __shared__ float setv[8][8];     // et per node/head
    __shared__ float sms[8][8][2];   // max, sum per node/head
    __shared__ float aw[8][128];

    if (t < 128) sraw[t >> 4][t & 15] = src[(size_t)b * 128 + t];
    if (t < 64)  setv[t >> 3][t & 7] = g_et[(size_t)(b * 8 + (t >> 3)) * NH + (t & 7)];
    __syncthreads();

    // scores: 4 (j,h) pairs per thread
    #pragma unroll
    for (int k = 0; k < 4; k++) {
        int p = tl + 32 * k;          // 0..127
        int j = p >> 3, h = p & 7;
        float e = g_eh[(size_t)sraw[nn][j] * NH + h] + setv[nn][h];
        se[nn][p] = (e > 0.f) ? e : SLOPE * e;
    }
    __syncthreads();

    // per (node, head) max + sum
    if (t < 64) {
        int node = t >> 3, h = t & 7;
        float m = -1e30f;
        #pragma unroll
        for (int j = 0; j < DEG; j++) m = fmaxf(m, se[node][j * 8 + h]);
        float sum = 0.f;
        #pragma unroll
        for (int j = 0; j < DEG; j++) sum += __expf(se[node][j * 8 + h] - m);
        sms[node][h][0] = m;
        sms[node][h][1] = sum;
    }
    __syncthreads();

    // normalized weights -> smem + g_a
    #pragma unroll
    for (int k = 0; k < 4; k++) {
        int p = tl + 32 * k;
        int h = p & 7;
        float a = __expf(se[nn][p] - sms[nn][h][0]) / sms[nn][h][1];
        aw[nn][p] = a;
        g_a[(size_t)n * 128 + p] = a;
    }
    __syncthreads();

    // vectorized hop-0 gather: lane owns 8 channels, head = tl>>2
    int hh = tl >> 2;
    float w[16];
    int   off[16];
    #pragma unroll
    for (int j = 0; j < 16; j++) {
        w[j]   = aw[nn][j * 8 + hh];
        off[j] = sraw[nn][j] * 32;
    }

    const float4* fin = (const float4*)g_f016;
    float acc[8];
    #pragma unroll
    for (int q = 0; q < 8; q++) acc[q] = 0.f;
    #pragma unroll
    for (int j = 0; j < 16; j++) {
        float4 v = fin[(size_t)off[j] + tl];
        const __half2* hp = (const __half2*)&v;
        #pragma unroll
        for (int q = 0; q < 4; q++) {
            float2 f = __half22float2(hp[q]);
            acc[q * 2]     += w[j] * f.x;
            acc[q * 2 + 1] += w[j] * f.y;
        }
    }
    float4 f0v = fin[(size_t)n * 32 + tl];
    const __half2* f0p = (const __half2*)&f0v;
    __half2 oh[4];
    #pragma unroll
    for (int q = 0; q < 4; q++) {
        float2 f = __half22float2(f0p[q]);
        float vx = (1.0f - ALPHA) * acc[q * 2]     + ALPHA * f.x;
        float vy = (1.0f - ALPHA) * acc[q * 2 + 1] + ALPHA * f.y;
        oh[q] = __floats2half2_rn(vx, vy);
    }
    ((float4*)g_fa16)[(size_t)n * 32 + tl] = *(float4*)oh;
}

// ---------------- vectorized hop smem staging ------------------------------
__device__ __forceinline__ void hop_stage(const int* __restrict__ src, int b,
                                          float (&aw)[8][128], int (&soff)[8][16]) {
    int t = threadIdx.x;
    float4 v = ((const float4*)g_a)[(size_t)b * 256 + t];
    *(float4*)&aw[t >> 5][(t & 31) * 4] = v;
    if (t < 128)
        soff[t >> 4][t & 15] = src[(size_t)b * 128 + t] * 32;
    __syncthreads();
}

// ---------------- hops 1..3, vectorized ------------------------------------
__global__ void __launch_bounds__(256)
hop16v_kernel(const int* __restrict__ src, int hop) {
    const float4* fin;
    float4* fout;
    if      (hop == 1) { fin = (const float4*)g_fa16; fout = (float4*)g_fb16; }
    else if (hop == 2) { fin = (const float4*)g_fb16; fout = (float4*)g_fa16; }
    else               { fin = (const float4*)g_fa16; fout = (float4*)g_fb16; }

    int b = blockIdx.x;
    int t = threadIdx.x;
    int nn = t >> 5, tl = t & 31;
    int n = b * 8 + nn;

    __shared__ float aw[8][128];
    __shared__ int   soff[8][16];
    hop_stage(src, b, aw, soff);

    int hh = tl >> 2;
    float w[16];
    int   off[16];
    #pragma unroll
    for (int j = 0; j < 16; j++) {
        w[j]   = aw[nn][j * 8 + hh];
        off[j] = soff[nn][j];
    }

    float acc[8];
    #pragma unroll
    for (int q = 0; q < 8; q++) acc[q] = 0.f;

    #pragma unroll
    for (int j = 0; j < 16; j++) {
        float4 v = fin[(size_t)off[j] + tl];
        const __half2* hp = (const __half2*)&v;
        #pragma unroll
        for (int q = 0; q < 4; q++) {
            float2 f = __half22float2(hp[q]);
            acc[q * 2]     += w[j] * f.x;
            acc[q * 2 + 1] += w[j] * f.y;
        }
    }

    float4 f0v = ((const float4*)g_f016)[(size_t)n * 32 + tl];
    const __half2* f0p = (const __half2*)&f0v;
    __half2 oh[4];
    #pragma unroll
    for (int q = 0; q < 4; q++) {
        float2 f = __half22float2(f0p[q]);
        float vx = (1.0f - ALPHA) * acc[q * 2]     + ALPHA * f.x;
        float vy = (1.0f - ALPHA) * acc[q * 2 + 1] + ALPHA * f.y;
        oh[q] = __floats2half2_rn(vx, vy);
    }
    fout[(size_t)n * 32 + tl] = *(float4*)oh;
}

// ---------------- final hop + residual + warp-local LN2 --------------------
__global__ void __launch_bounds__(256)
hoplastv_kernel(const int* __restrict__ src,
                const float* __restrict__ ln2_g,
                const float* __restrict__ ln2_b) {
    int b = blockIdx.x;
    int t = threadIdx.x;
    int nn = t >> 5, tl = t & 31;
    int n = b * 8 + nn;

    __shared__ float aw[8][128];
    __shared__ int   soff[8][16];
    hop_stage(src, b, aw, soff);

    int hh = tl >> 2;
    float w[16];
    int   off[16];
    #pragma unroll
    for (int j = 0; j < 16; j++) {
        w[j]   = aw[nn][j * 8 + hh];
        off[j] = soff[nn][j];
    }

    const float4* fin = (const float4*)g_fb16;
    float acc[8];
    #pragma unroll
    for (int q = 0; q < 8; q++) acc[q] = 0.f;

    #pragma unroll
    for (int j = 0; j < 16; j++) {
        float4 v = fin[(size_t)off[j] + tl];
        const __half2* hp = (const __half2*)&v;
        #pragma unroll
        for (int q = 0; q < 4; q++) {
            float2 f = __half22float2(hp[q]);
            acc[q * 2]     += w[j] * f.x;
            acc[q * 2 + 1] += w[j] * f.y;
        }
    }

    float4 f0v = ((const float4*)g_f016)[(size_t)n * 32 + tl];
    const __half2* f0p = (const __half2*)&f0v;
    float4 h0 = ((const float4*)g_h)[(size_t)n * 64 + tl * 2];
    float4 h1 = ((const float4*)g_h)[(size_t)n * 64 + tl * 2 + 1];
    float v[8];
    {
        float2 f;
        f = __half22float2(f0p[0]);
        v[0] = (1.0f - ALPHA) * acc[0] + ALPHA * f.x + h0.x;
        v[1] = (1.0f - ALPHA) * acc[1] + ALPHA * f.y + h0.y;
        f = __half22float2(f0p[1]);
        v[2] = (1.0f - ALPHA) * acc[2] + ALPHA * f.x + h0.z;
        v[3] = (1.0f - ALPHA) * acc[3] + ALPHA * f.y + h0.w;
        f = __half22float2(f0p[2]);
        v[4] = (1.0f - ALPHA) * acc[4] + ALPHA * f.x + h1.x;
        v[5] = (1.0f - ALPHA) * acc[5] + ALPHA * f.y + h1.y;
        f = __half22float2(f0p[3]);
        v[6] = (1.0f - ALPHA) * acc[6] + ALPHA * f.x + h1.z;
        v[7] = (1.0f - ALPHA) * acc[7] + ALPHA * f.y + h1.w;
    }
    ((float4*)g_rst)[(size_t)n * 64 + tl * 2]     = make_float4(v[0], v[1], v[2], v[3]);
    ((float4*)g_rst)[(size_t)n * 64 + tl * 2 + 1] = make_float4(v[4], v[5], v[6], v[7]);

    float s = 0.f, sq = 0.f;
    #pragma unroll
    for (int q = 0; q < 8; q++) { s += v[q]; sq += v[q] * v[q]; }
    #pragma unroll
    for (int o = 16; o > 0; o >>= 1) {
        s  += __shfl_xor_sync(0xffffffffu, s, o);
        sq += __shfl_xor_sync(0xffffffffu, sq, o);
    }
    float mu  = s * (1.0f / 256.0f);
    float var = sq * (1.0f / 256.0f) - mu * mu;
    float rs  = rsqrtf(var + 1e-5f);

    float4 g0 = *(const float4*)(ln2_g + tl * 8);
    float4 g1 = *(const float4*)(ln2_g + tl * 8 + 4);
    float4 b0 = *(const float4*)(ln2_b + tl * 8);
    float4 b1 = *(const float4*)(ln2_b + tl * 8 + 4);
    float y[8];
    y[0] = (v[0] - mu) * rs * g0.x + b0.x;
    y[1] = (v[1] - mu) * rs * g0.y + b0.y;
    y[2] = (v[2] - mu) * rs * g0.z + b0.z;
    y[3] = (v[3] - mu) * rs * g0.w + b0.w;
    y[4] = (v[4] - mu) * rs * g1.x + b1.x;
    y[5] = (v[5] - mu) * rs * g1.y + b1.y;
    y[6] = (v[6] - mu) * rs * g1.z + b1.z;
    y[7] = (v[7] - mu) * rs * g1.w + b1.w;
    __half2 oh[4];
    #pragma unroll
    for (int q = 0; q < 4; q++)
        oh[q] = __floats2half2_rn(y[q * 2], y[q * 2 + 1]);
    ((float4*)g_x16)[(size_t)n * 32 + tl] = *(float4*)oh;
}

// ---------------------------------------------------------------------------
extern "C" void kernel_launch(void* const* d_in, const int* in_sizes, int n_in,
                              void* d_out, int out_size) {
    const float* ent_feat = (const float*)d_in[0];
    const float* W_ent    = (const float*)d_in[1];
    const float* attn_h   = (const float*)d_in[2];
    const float* attn_t   = (const float*)d_in[3];
    const float* ln1_g    = (const float*)d_in[4];
    const float* ln1_b    = (const float*)d_in[5];
    const float* ln2_g    = (const float*)d_in[6];
    const float* ln2_b    = (const float*)d_in[7];
    const float* W1       = (const float*)d_in[8];
    const float* b1       = (const float*)d_in[9];
    const float* W2       = (const float*)d_in[10];
    const float* b2       = (const float*)d_in[11];
    const int*   src      = (const int*)d_in[12];
    float*       out      = (float*)d_out;

    const int SMEM = 3 * 20480;
    cudaFuncSetAttribute(gemm_mma<0>, cudaFuncAttributeMaxDynamicSharedMemorySize, SMEM);
    cudaFuncSetAttribute(gemm_mma<1>, cudaFuncAttributeMaxDynamicSharedMemorySize, SMEM);
    cudaFuncSetAttribute(gemm_mma<2>, cudaFuncAttributeMaxDynamicSharedMemorySize, SMEM);

    float *p_h, *p_rst;
    __half *p_h16, *p_f016, *p_x16, *p_t16, *p_went16, *p_w116, *p_w216;
    cudaGetSymbolAddress((void**)&p_h,      g_h);
    cudaGetSymbolAddress((void**)&p_rst,    g_rst);
    cudaGetSymbolAddress((void**)&p_h16,    g_h16);
    cudaGetSymbolAddress((void**)&p_f016,   g_f016);
    cudaGetSymbolAddress((void**)&p_x16,    g_x16);
    cudaGetSymbolAddress((void**)&p_t16,    g_t16);
    cudaGetSymbolAddress((void**)&p_went16, g_went16);
    cudaGetSymbolAddress((void**)&p_w116,   g_w116);
    cudaGetSymbolAddress((void**)&p_w216,   g_w216);

    // 1. all weights -> fp16
    wconv_all_kernel<<<(589824 / 4 + 255) / 256, 256>>>(W_ent, W1, W2);

    // 2. h = LN1(ent_feat)  (fp32 + fp16)
    ln256w_kernel<<<(NN + 7) / 8, 256>>>(ent_feat, ln1_g, ln1_b, p_h, p_h16);

    // 3. feat0 = h @ W_ent^T -> fp16, fused eh/et
    {
        dim3 grid(DOUT / 128, (NN + 127) / 128);
        gemm_mma<0><<<grid, 256, SMEM>>>(p_h16, p_went16, nullptr, nullptr,
                                         nullptr, p_f016, attn_h, attn_t,
                                         NN, DOUT, DIN);
    }

    // 4. fused softmax + hop0 (vectorized)
    hop0v_kernel<<<NN / 8, 256>>>(src);

    // 5-7. hops 1..3 vectorized  [launch #6 = hop2 for ncu -s 5]
    for (int hop = 1; hop < HOPS - 1; hop++)
        hop16v_kernel<<<NN / 8, 256>>>(src, hop);

    // 8. final hop + residual + warp-local LN2
    hoplastv_kernel<<<NN / 8, 256>>>(src, ln2_g, ln2_b);

    // 9. t = relu(x @ W1^T + b1) -> fp16
    {
        dim3 grid(DFF / 128, (NN + 127) / 128);
        gemm_mma<1><<<grid, 256, SMEM>>>(p_x16, p_w116, b1, nullptr,
                                         nullptr, p_t16, nullptr, nullptr,
                                         NN, DFF, DOUT);
    }

    // 10. out = t @ W2^T + b2 + rst  (fp32)
    {
        dim3 grid(DOUT / 128, (NN + 127) / 128);
        gemm_mma<2><<<grid, 256, SMEM>>>(p_t16, p_w216, b2, p_rst,
                                         out, nullptr, nullptr, nullptr,
                                         NN, DOUT, DFF);
    }
}

// round 12
// speedup vs baseline: 4.7508x; 1.0332x over previous
#include <cuda_runtime.h>
#include <cuda_fp16.h>
#include <math.h>
#include <stdint.h>

// ---------------------------------------------------------------------------
// GDTEncoder: graph attention + PPR diffusion + FFN
// N=50000, DEG=16 (dst-contiguous), D_IN=D_OUT=256, H=8, HD=32, DFF=1024
// fp16 mma.sync GEMMs (3-stage cp.async), ehet fused into G1,
// warp-autonomous softmax+hop0, LDG.128 gathers for all hops,
// LN2 fused (warp-local) into final hop, fp16 residual (no fp32 h copy).
// ---------------------------------------------------------------------------

#define NN     50000
#define DEG    16
#define EDGES  (NN * DEG)
#define DIN    256
#define NH     8
#define HD     32
#define DOUT   256
#define DFF    1024
#define HOPS   5
#define ALPHA  0.15f
#define SLOPE  0.2f

// ---------------- scratch (static device globals; no allocation) -----------
__device__ __align__(256) float g_eh[(size_t)NN * NH];
__device__ __align__(256) float g_et[(size_t)NN * NH];
__device__ __align__(256) float g_a[(size_t)EDGES * NH];    // softmaxed edge weights
__device__ __align__(256) float g_rst[(size_t)NN * DOUT];   // feat after hops + h (fp32)

__device__ __align__(256) __half g_h16[(size_t)NN * DIN];    // LN1 out fp16
__device__ __align__(256) __half g_f016[(size_t)NN * DOUT];  // feat0 fp16
__device__ __align__(256) __half g_fa16[(size_t)NN * DOUT];  // hop ping
__device__ __align__(256) __half g_fb16[(size_t)NN * DOUT];  // hop pong
__device__ __align__(256) __half g_x16[(size_t)NN * DOUT];   // LN2 out fp16
__device__ __align__(256) __half g_t16[(size_t)NN * DFF];    // FFN hidden fp16
__device__ __align__(256) __half g_went16[DOUT * DIN];
__device__ __align__(256) __half g_w116[DFF * DOUT];
__device__ __align__(256) __half g_w216[DOUT * DFF];

// ---------------- mma / cp.async helpers -----------------------------------
__device__ __forceinline__ void ldmat4(uint32_t& r0, uint32_t& r1,
                                       uint32_t& r2, uint32_t& r3,
                                       uint32_t addr) {
    asm volatile("ldmatrix.sync.aligned.m8n8.x4.shared.b16 {%0,%1,%2,%3}, [%4];"
                 : "=r"(r0), "=r"(r1), "=r"(r2), "=r"(r3) : "r"(addr));
}

__device__ __forceinline__ void mma_fp(float c[4],
                                       uint32_t a0, uint32_t a1, uint32_t a2, uint32_t a3,
                                       uint32_t b0, uint32_t b1) {
    asm volatile(
        "mma.sync.aligned.m16n8k16.row.col.f32.f16.f16.f32 "
        "{%0,%1,%2,%3}, {%4,%5,%6,%7}, {%8,%9}, {%0,%1,%2,%3};"
        : "+f"(c[0]), "+f"(c[1]), "+f"(c[2]), "+f"(c[3])
        : "r"(a0), "r"(a1), "r"(a2), "r"(a3), "r"(b0), "r"(b1));
}

__device__ __forceinline__ void cp16(uint32_t dst, const void* src, int sz) {
    asm volatile("cp.async.cg.shared.global [%0], [%1], 16, %2;\n"
                 :: "r"(dst), "l"(src), "r"(sz));
}
__device__ __forceinline__ void cp_commit() {
    asm volatile("cp.async.commit_group;\n" ::);
}
template <int N>
__device__ __forceinline__ void cp_waitg() {
    asm volatile("cp.async.wait_group %0;\n" :: "n"(N));
}

// ---------------- GEMM: C[M,N] = A[M,K] * B[N,K]^T, fp16 mma ---------------
// MODE 0: plain -> fp16 Ch + fused eh/et.  MODE 1: relu(acc+bias) -> fp16 Ch.
// MODE 2: acc+bias+resid -> fp32 C.
template <int MODE>
__global__ void __launch_bounds__(256, 2)
gemm_mma(const __half* __restrict__ A, const __half* __restrict__ B,
         const float* __restrict__ bias, const float* __restrict__ resid,
         float* __restrict__ C, __half* __restrict__ Ch,
         const float* __restrict__ attn_h, const float* __restrict__ attn_t,
         int M, int N, int K) {
    constexpr int BM = 128, BN = 128, BK = 32;
    constexpr int LDS = 40;
    constexpr int MAT = BM * LDS * 2;       // 10240 B
    constexpr int STAGE = 2 * MAT;          // 20480 B
    constexpr int STAGES = 3;

    extern __shared__ __align__(16) char dynsmem[];
    const uint32_t smem0 = (uint32_t)__cvta_generic_to_shared(dynsmem);

    const int tid  = threadIdx.x;
    const int m0   = blockIdx.y * BM;
    const int n0   = blockIdx.x * BN;
    const int wid  = tid >> 5;
    const int lane = tid & 31;
    const int wm   = (wid >> 2) * 64;
    const int wn   = (wid & 3) * 32;
    const int lg   = lane >> 3;
    const int lr   = lane & 7;

    const int lrow = tid >> 1;
    const int lc0  = (tid & 1) * 2;
    const bool arow_ok = (m0 + lrow) < M;
    const int  a_sz = arow_ok ? 16 : 0;
    const __half* pA = A + (size_t)(m0 + lrow) * K + lc0 * 8;
    const __half* pB = B + (size_t)(n0 + lrow) * K + lc0 * 8;
    const uint32_t soff = (uint32_t)(lrow * 80 + lc0 * 16);

    const int KT = K / BK;

    auto load_stage = [&](int kt, int s) {
        uint32_t sb = smem0 + s * STAGE + soff;
        int ko = kt * BK;
        cp16(sb,            pA + ko,     a_sz);
        cp16(sb + 16,       pA + ko + 8, a_sz);
        cp16(sb + MAT,      pB + ko,     16);
        cp16(sb + MAT + 16, pB + ko + 8, 16);
    };

    float acc[4][4][4];
    #pragma unroll
    for (int i = 0; i < 4; i++)
        #pragma unroll
        for (int j = 0; j < 4; j++)
            #pragma unroll
            for (int q = 0; q < 4; q++) acc[i][j][q] = 0.f;

    #pragma unroll
    for (int s = 0; s < STAGES - 1; s++) {
        load_stage(s, s);
        cp_commit();
    }

    int cslot = 0;
    int lslot = STAGES - 1;
    for (int kt = 0; kt < KT; kt++) {
        cp_waitg<STAGES - 2>();
        __syncthreads();

        int nk = kt + STAGES - 1;
        if (nk < KT) load_stage(nk, lslot);
        cp_commit();

        const uint32_t baseA = smem0 + cslot * STAGE;
        const uint32_t baseB = baseA + MAT;

        #pragma unroll
        for (int ks = 0; ks < 2; ks++) {
            const int kb = ks * 16;
            uint32_t bh[4][2];
            #pragma unroll
            for (int p = 0; p < 2; p++) {
                int row = wn + p * 16 + lr + (lg & 2) * 4;
                int kc  = kb + (lg & 1) * 8;
                uint32_t off = (uint32_t)(row * LDS + kc) * 2;
                ldmat4(bh[2*p][0], bh[2*p][1], bh[2*p+1][0], bh[2*p+1][1], baseB + off);
            }
            #pragma unroll
            for (int mi = 0; mi < 4; mi++) {
                int row = wm + mi * 16 + lr + (lg & 1) * 8;
                int kc  = kb + (lg & 2) * 4;
                uint32_t off = (uint32_t)(row * LDS + kc) * 2;
                uint32_t a0, a1, a2, a3;
                ldmat4(a0, a1, a2, a3, baseA + off);
                #pragma unroll
                for (int nj = 0; nj < 4; nj++)
                    mma_fp(acc[mi][nj], a0, a1, a2, a3, bh[nj][0], bh[nj][1]);
            }
        }
        cslot = (cslot + 1 == STAGES) ? 0 : cslot + 1;
        lslot = (lslot + 1 == STAGES) ? 0 : lslot + 1;
    }

    const int gr  = lane >> 2;
    const int gc2 = (lane & 3) * 2;

    float avh[8], avt[8];
    int hh = 0;
    if (MODE == 0) {
        hh = (n0 + wn) >> 5;
        #pragma unroll
        for (int nj = 0; nj < 4; nj++)
            #pragma unroll
            for (int q = 0; q < 2; q++) {
                int col = nj * 8 + gc2 + q;
                avh[nj * 2 + q] = attn_h[hh * HD + col];
                avt[nj * 2 + q] = attn_t[hh * HD + col];
            }
    }

    #pragma unroll
    for (int mi = 0; mi < 4; mi++) {
        #pragma unroll
        for (int half = 0; half < 2; half++) {
            int gm = m0 + wm + mi * 16 + gr + half * 8;
            if (gm >= M) continue;
            if (MODE == 0) {
                float seh = 0.f, set = 0.f;
                #pragma unroll
                for (int nj = 0; nj < 4; nj++) {
                    float v0 = acc[mi][nj][half * 2 + 0];
                    float v1 = acc[mi][nj][half * 2 + 1];
                    int gn = n0 + wn + nj * 8 + gc2;
                    *(__half2*)(Ch + (size_t)gm * N + gn) =
                        __halves2half2(__float2half_rn(v0), __float2half_rn(v1));
                    seh += v0 * avh[nj * 2] + v1 * avh[nj * 2 + 1];
                    set += v0 * avt[nj * 2] + v1 * avt[nj * 2 + 1];
                }
                seh += __shfl_xor_sync(0xffffffffu, seh, 1);
                set += __shfl_xor_sync(0xffffffffu, set, 1);
                seh += __shfl_xor_sync(0xffffffffu, seh, 2);
                set += __shfl_xor_sync(0xffffffffu, set, 2);
                if ((lane & 3) == 0) {
                    g_eh[(size_t)gm * NH + hh] = seh;
                    g_et[(size_t)gm * NH + hh] = set;
                }
            } else {
                #pragma unroll
                for (int nj = 0; nj < 4; nj++) {
                    int gn = n0 + wn + nj * 8 + gc2;
                    float v0 = acc[mi][nj][half * 2 + 0];
                    float v1 = acc[mi][nj][half * 2 + 1];
                    if (MODE == 1) {
                        v0 = fmaxf(v0 + bias[gn], 0.f);
                        v1 = fmaxf(v1 + bias[gn + 1], 0.f);
                        *(__half2*)(Ch + (size_t)gm * N + gn) =
                            __halves2half2(__float2half_rn(v0), __float2half_rn(v1));
                    } else {
                        const float* rr = resid + (size_t)gm * N + gn;
                        v0 += bias[gn]     + rr[0];
                        v1 += bias[gn + 1] + rr[1];
                        *(float2*)(C + (size_t)gm * N + gn) = make_float2(v0, v1);
                    }
                }
            }
        }
    }
}

// ---------------- LayerNorm, warp per row (LN1) -> fp16 only ----------------
__global__ void ln256w_kernel(const float* __restrict__ in,
                              const float* __restrict__ g,
                              const float* __restrict__ b,
                              __half* __restrict__ out_16) {
    int row  = blockIdx.x * 8 + (threadIdx.x >> 5);
    int lane = threadIdx.x & 31;
    if (row >= NN) return;
    const float* rp = in + (size_t)row * 256;
    float4 v0 = *(const float4*)(rp + lane * 8);
    float4 v1 = *(const float4*)(rp + lane * 8 + 4);
    float s  = v0.x + v0.y + v0.z + v0.w + v1.x + v1.y + v1.z + v1.w;
    float sq = v0.x*v0.x + v0.y*v0.y + v0.z*v0.z + v0.w*v0.w
             + v1.x*v1.x + v1.y*v1.y + v1.z*v1.z + v1.w*v1.w;
    #pragma unroll
    for (int o = 16; o > 0; o >>= 1) {
        s  += __shfl_xor_sync(0xffffffffu, s, o);
        sq += __shfl_xor_sync(0xffffffffu, sq, o);
    }
    float mu  = s * (1.0f / 256.0f);
    float var = sq * (1.0f / 256.0f) - mu * mu;
    float rs  = rsqrtf(var + 1e-5f);
    float4 g0 = *(const float4*)(g + lane * 8);
    float4 g1 = *(const float4*)(g + lane * 8 + 4);
    float4 b0 = *(const float4*)(b + lane * 8);
    float4 b1 = *(const float4*)(b + lane * 8 + 4);
    float y[8];
    y[0] = (v0.x - mu) * rs * g0.x + b0.x;
    y[1] = (v0.y - mu) * rs * g0.y + b0.y;
    y[2] = (v0.z - mu) * rs * g0.z + b0.z;
    y[3] = (v0.w - mu) * rs * g0.w + b0.w;
    y[4] = (v1.x - mu) * rs * g1.x + b1.x;
    y[5] = (v1.y - mu) * rs * g1.y + b1.y;
    y[6] = (v1.z - mu) * rs * g1.z + b1.z;
    y[7] = (v1.w - mu) * rs * g1.w + b1.w;
    size_t o8 = (size_t)row * 256 + lane * 8;
    __half2 oh[4];
    #pragma unroll
    for (int i = 0; i < 4; i++)
        oh[i] = __floats2half2_rn(y[i * 2], y[i * 2 + 1]);
    *(float4*)(out_16 + o8) = *(float4*)oh;
}

// ---------------- all weights fp32 -> fp16 (one launch) --------------------
__global__ void wconv_all_kernel(const float* __restrict__ went,
                                 const float* __restrict__ w1,
                                 const float* __restrict__ w2) {
    int i = (blockIdx.x * blockDim.x + threadIdx.x) * 4;
    const int N0 = DOUT * DIN;
    const int N1 = N0 + DFF * DOUT;
    const int N2 = N1 + DOUT * DFF;
    if (i >= N2) return;
    const float* srcp;
    __half* dstp;
    int off;
    if (i < N0)      { srcp = went; dstp = g_went16; off = i; }
    else if (i < N1) { srcp = w1;   dstp = g_w116;   off = i - N0; }
    else             { srcp = w2;   dstp = g_w216;   off = i - N1; }
    float4 v = *(const float4*)(srcp + off);
    *(__half2*)(dstp + off)     = __halves2half2(__float2half_rn(v.x), __float2half_rn(v.y));
    *(__half2*)(dstp + off + 2) = __halves2half2(__float2half_rn(v.z), __float2half_rn(v.w));
}

// ---------------- fused softmax + hop0, warp-autonomous (8 nodes/block) ----
__global__ void __launch_bounds__(256)
hop0v_kernel(const int* __restrict__ src) {
    int b = blockIdx.x;
    int t = threadIdx.x;
    int nn = t >> 5, tl = t & 31;
    int n = b * 8 + nn;

    __shared__ int   sraw[8][16];
    __shared__ float aw[8][128];

    if (tl < 16) sraw[nn][tl] = src[(size_t)n * 16 + tl];
    __syncwarp();

    // warp-local softmax: lane = g*8 + h handles edges j = g*4 + k
    int gg = tl >> 3, h = tl & 7;
    float etv = g_et[(size_t)n * NH + h];
    float e[4], ex[4];
    #pragma unroll
    for (int k = 0; k < 4; k++) {
        int j = gg * 4 + k;
        float v = g_eh[(size_t)sraw[nn][j] * NH + h] + etv;
        e[k] = (v > 0.f) ? v : SLOPE * v;
    }
    float m = fmaxf(fmaxf(e[0], e[1]), fmaxf(e[2], e[3]));
    m = fmaxf(m, __shfl_xor_sync(0xffffffffu, m, 8));
    m = fmaxf(m, __shfl_xor_sync(0xffffffffu, m, 16));
    float s = 0.f;
    #pragma unroll
    for (int k = 0; k < 4; k++) { ex[k] = __expf(e[k] - m); s += ex[k]; }
    s += __shfl_xor_sync(0xffffffffu, s, 8);
    s += __shfl_xor_sync(0xffffffffu, s, 16);
    float rinv = 1.0f / s;
    #pragma unroll
    for (int k = 0; k < 4; k++) {
        int j = gg * 4 + k;
        float a = ex[k] * rinv;
        aw[nn][j * 8 + h] = a;
        g_a[(size_t)n * 128 + j * 8 + h] = a;
    }
    __syncwarp();

    // vectorized hop-0 gather: lane owns 8 channels, head = tl>>2
    int hh = tl >> 2;
    float w[16];
    int   off[16];
    #pragma unroll
    for (int j = 0; j < 16; j++) {
        w[j]   = aw[nn][j * 8 + hh];
        off[j] = sraw[nn][j] * 32;
    }

    const float4* fin = (const float4*)g_f016;
    float acc[8];
    #pragma unroll
    for (int q = 0; q < 8; q++) acc[q] = 0.f;
    #pragma unroll
    for (int j = 0; j < 16; j++) {
        float4 v = fin[(size_t)off[j] + tl];
        const __half2* hp = (const __half2*)&v;
        #pragma unroll
        for (int q = 0; q < 4; q++) {
            float2 f = __half22float2(hp[q]);
            acc[q * 2]     += w[j] * f.x;
            acc[q * 2 + 1] += w[j] * f.y;
        }
    }
    float4 f0v = fin[(size_t)n * 32 + tl];
    const __half2* f0p = (const __half2*)&f0v;
    __half2 oh[4];
    #pragma unroll
    for (int q = 0; q < 4; q++) {
        float2 f = __half22float2(f0p[q]);
        float vx = (1.0f - ALPHA) * acc[q * 2]     + ALPHA * f.x;
        float vy = (1.0f - ALPHA) * acc[q * 2 + 1] + ALPHA * f.y;
        oh[q] = __floats2half2_rn(vx, vy);
    }
    ((float4*)g_fa16)[(size_t)n * 32 + tl] = *(float4*)oh;
}

// ---------------- vectorized hop smem staging ------------------------------
__device__ __forceinline__ void hop_stage(const int* __restrict__ src, int b,
                                          float (&aw)[8][128], int (&soff)[8][16]) {
    int t = threadIdx.x;
    float4 v = ((const float4*)g_a)[(size_t)b * 256 + t];
    *(float4*)&aw[t >> 5][(t & 31) * 4] = v;
    if (t < 128)
        soff[t >> 4][t & 15] = src[(size_t)b * 128 + t] * 32;
    __syncthreads();
}

// ---------------- hops 1..3, vectorized ------------------------------------
__global__ void __launch_bounds__(256)
hop16v_kernel(const int* __restrict__ src, int hop) {
    const float4* fin;
    float4* fout;
    if      (hop == 1) { fin = (const float4*)g_fa16; fout = (float4*)g_fb16; }
    else if (hop == 2) { fin = (const float4*)g_fb16; fout = (float4*)g_fa16; }
    else               { fin = (const float4*)g_fa16; fout = (float4*)g_fb16; }

    int b = blockIdx.x;
    int t = threadIdx.x;
    int nn = t >> 5, tl = t & 31;
    int n = b * 8 + nn;

    __shared__ float aw[8][128];
    __shared__ int   soff[8][16];
    hop_stage(src, b, aw, soff);

    int hh = tl >> 2;
    float w[16];
    int   off[16];
    #pragma unroll
    for (int j = 0; j < 16; j++) {
        w[j]   = aw[nn][j * 8 + hh];
        off[j] = soff[nn][j];
    }

    float acc[8];
    #pragma unroll
    for (int q = 0; q < 8; q++) acc[q] = 0.f;

    #pragma unroll
    for (int j = 0; j < 16; j++) {
        float4 v = fin[(size_t)off[j] + tl];
        const __half2* hp = (const __half2*)&v;
        #pragma unroll
        for (int q = 0; q < 4; q++) {
            float2 f = __half22float2(hp[q]);
            acc[q * 2]     += w[j] * f.x;
            acc[q * 2 + 1] += w[j] * f.y;
        }
    }

    float4 f0v = ((const float4*)g_f016)[(size_t)n * 32 + tl];
    const __half2* f0p = (const __half2*)&f0v;
    __half2 oh[4];
    #pragma unroll
    for (int q = 0; q < 4; q++) {
        float2 f = __half22float2(f0p[q]);
        float vx = (1.0f - ALPHA) * acc[q * 2]     + ALPHA * f.x;
        float vy = (1.0f - ALPHA) * acc[q * 2 + 1] + ALPHA * f.y;
        oh[q] = __floats2half2_rn(vx, vy);
    }
    fout[(size_t)n * 32 + tl] = *(float4*)oh;
}

// ---------------- final hop + fp16 residual + warp-local LN2 ---------------
__global__ void __launch_bounds__(256)
hoplastv_kernel(const int* __restrict__ src,
                const float* __restrict__ ln2_g,
                const float* __restrict__ ln2_b) {
    int b = blockIdx.x;
    int t = threadIdx.x;
    int nn = t >> 5, tl = t & 31;
    int n = b * 8 + nn;

    __shared__ float aw[8][128];
    __shared__ int   soff[8][16];
    hop_stage(src, b, aw, soff);

    int hh = tl >> 2;
    float w[16];
    int   off[16];
    #pragma unroll
    for (int j = 0; j < 16; j++) {
        w[j]   = aw[nn][j * 8 + hh];
        off[j] = soff[nn][j];
    }

    const float4* fin = (const float4*)g_fb16;
    float acc[8];
    #pragma unroll
    for (int q = 0; q < 8; q++) acc[q] = 0.f;

    #pragma unroll
    for (int j = 0; j < 16; j++) {
        float4 v = fin[(size_t)off[j] + tl];
        const __half2* hp = (const __half2*)&v;
        #pragma unroll
        for (int q = 0; q < 4; q++) {
            float2 f = __half22float2(hp[q]);
            acc[q * 2]     += w[j] * f.x;
            acc[q * 2 + 1] += w[j] * f.y;
        }
    }

    float4 f0v = ((const float4*)g_f016)[(size_t)n * 32 + tl];
    const __half2* f0p = (const __half2*)&f0v;
    float4 hv = ((const float4*)g_h16)[(size_t)n * 32 + tl];
    const __half2* hp2 = (const __half2*)&hv;
    float v[8];
    #pragma unroll
    for (int q = 0; q < 4; q++) {
        float2 f = __half22float2(f0p[q]);
        float2 hr = __half22float2(hp2[q]);
        v[q * 2]     = (1.0f - ALPHA) * acc[q * 2]     + ALPHA * f.x + hr.x;
        v[q * 2 + 1] = (1.0f - ALPHA) * acc[q * 2 + 1] + ALPHA * f.y + hr.y;
    }
    ((float4*)g_rst)[(size_t)n * 64 + tl * 2]     = make_float4(v[0], v[1], v[2], v[3]);
    ((float4*)g_rst)[(size_t)n * 64 + tl * 2 + 1] = make_float4(v[4], v[5], v[6], v[7]);

    float s = 0.f, sq = 0.f;
    #pragma unroll
    for (int q = 0; q < 8; q++) { s += v[q]; sq += v[q] * v[q]; }
    #pragma unroll
    for (int o = 16; o > 0; o >>= 1) {
        s  += __shfl_xor_sync(0xffffffffu, s, o);
        sq += __shfl_xor_sync(0xffffffffu, sq, o);
    }
    float mu  = s * (1.0f / 256.0f);
    float var = sq * (1.0f / 256.0f) - mu * mu;
    float rs  = rsqrtf(var + 1e-5f);

    float4 g0 = *(const float4*)(ln2_g + tl * 8);
    float4 g1 = *(const float4*)(ln2_g + tl * 8 + 4);
    float4 b0 = *(const float4*)(ln2_b + tl * 8);
    float4 b1 = *(const float4*)(ln2_b + tl * 8 + 4);
    float y[8];
    y[0] = (v[0] - mu) * rs * g0.x + b0.x;
    y[1] = (v[1] - mu) * rs * g0.y + b0.y;
    y[2] = (v[2] - mu) * rs * g0.z + b0.z;
    y[3] = (v[3] - mu) * rs * g0.w + b0.w;
    y[4] = (v[4] - mu) * rs * g1.x + b1.x;
    y[5] = (v[5] - mu) * rs * g1.y + b1.y;
    y[6] = (v[6] - mu) * rs * g1.z + b1.z;
    y[7] = (v[7] - mu) * rs * g1.w + b1.w;
    __half2 oh[4];
    #pragma unroll
    for (int q = 0; q < 4; q++)
        oh[q] = __floats2half2_rn(y[q * 2], y[q * 2 + 1]);
    ((float4*)g_x16)[(size_t)n * 32 + tl] = *(float4*)oh;
}

// ---------------------------------------------------------------------------
extern "C" void kernel_launch(void* const* d_in, const int* in_sizes, int n_in,
                              void* d_out, int out_size) {
    const float* ent_feat = (const float*)d_in[0];
    const float* W_ent    = (const float*)d_in[1];
    const float* attn_h   = (const float*)d_in[2];
    const float* attn_t   = (const float*)d_in[3];
    const float* ln1_g    = (const float*)d_in[4];
    const float* ln1_b    = (const float*)d_in[5];
    const float* ln2_g    = (const float*)d_in[6];
    const float* ln2_b    = (const float*)d_in[7];
    const float* W1       = (const float*)d_in[8];
    const float* b1       = (const float*)d_in[9];
    const float* W2       = (const float*)d_in[10];
    const float* b2       = (const float*)d_in[11];
    const int*   src      = (const int*)d_in[12];
    float*       out      = (float*)d_out;

    const int SMEM = 3 * 20480;
    cudaFuncSetAttribute(gemm_mma<0>, cudaFuncAttributeMaxDynamicSharedMemorySize, SMEM);
    cudaFuncSetAttribute(gemm_mma<1>, cudaFuncAttributeMaxDynamicSharedMemorySize, SMEM);
    cudaFuncSetAttribute(gemm_mma<2>, cudaFuncAttributeMaxDynamicSharedMemorySize, SMEM);

    float* p_rst;
    __half *p_h16, *p_f016, *p_x16, *p_t16, *p_went16, *p_w116, *p_w216;
    cudaGetSymbolAddress((void**)&p_rst,    g_rst);
    cudaGetSymbolAddress((void**)&p_h16,    g_h16);
    cudaGetSymbolAddress((void**)&p_f016,   g_f016);
    cudaGetSymbolAddress((void**)&p_x16,    g_x16);
    cudaGetSymbolAddress((void**)&p_t16,    g_t16);
    cudaGetSymbolAddress((void**)&p_went16, g_went16);
    cudaGetSymbolAddress((void**)&p_w116,   g_w116);
    cudaGetSymbolAddress((void**)&p_w216,   g_w216);

    // 1. all weights -> fp16
    wconv_all_kernel<<<(589824 / 4 + 255) / 256, 256>>>(W_ent, W1, W2);

    // 2. h = LN1(ent_feat) -> fp16
    ln256w_kernel<<<(NN + 7) / 8, 256>>>(ent_feat, ln1_g, ln1_b, p_h16);

    // 3. feat0 = h @ W_ent^T -> fp16, fused eh/et
    {
        dim3 grid(DOUT / 128, (NN + 127) / 128);
        gemm_mma<0><<<grid, 256, SMEM>>>(p_h16, p_went16, nullptr, nullptr,
                                         nullptr, p_f016, attn_h, attn_t,
                                         NN, DOUT, DIN);
    }

    // 4. fused softmax + hop0 (warp-autonomous)
    hop0v_kernel<<<NN / 8, 256>>>(src);

    // 5-7. hops 1..3 vectorized
    for (int hop = 1; hop < HOPS - 1; hop++)
        hop16v_kernel<<<NN / 8, 256>>>(src, hop);

    // 8. final hop + fp16 residual + warp-local LN2
    hoplastv_kernel<<<NN / 8, 256>>>(src, ln2_g, ln2_b);

    // 9. t = relu(x @ W1^T + b1) -> fp16
    {
        dim3 grid(DFF / 128, (NN + 127) / 128);
        gemm_mma<1><<<grid, 256, SMEM>>>(p_x16, p_w116, b1, nullptr,
                                         nullptr, p_t16, nullptr, nullptr,
                                         NN, DFF, DOUT);
    }

    // 10. out = t @ W2^T + b2 + rst  (fp32)
    {
        dim3 grid(DOUT / 128, (NN + 127) / 128);
        gemm_mma<2><<<grid, 256, SMEM>>>(p_t16, p_w216, b2, p_rst,
                                         out, nullptr, nullptr, nullptr,
                                         NN, DOUT, DFF);
    }
}